// round 9
// baseline (speedup 1.0000x reference)
#include <cuda_runtime.h>
#include <math.h>

#define BB 8
#define NN 1024
#define MM 1024
#define D  512
#define HH 8
#define DS 64
#define ROWS (BB*NN)          // 8192
#define NEGV (-1e38f)
#define SCALE 0.04419417382415922f   // 1/sqrt(512)

typedef unsigned long long ull;

// packed f32x2 helpers (sm_100+)
__device__ __forceinline__ ull pk2(float lo, float hi) {
    ull r;
    asm("mov.b64 %0, {%1, %2};" : "=l"(r) : "f"(lo), "f"(hi));
    return r;
}
__device__ __forceinline__ float2 upk2(ull v) {
    float2 f;
    asm("mov.b64 {%0, %1}, %2;" : "=f"(f.x), "=f"(f.y) : "l"(v));
    return f;
}
#define FMA2(d, a, b) asm("fma.rn.f32x2 %0, %1, %2, %0;" : "+l"(d) : "l"(a), "l"(b))
#define MUL2(d, a)    asm("mul.rn.f32x2 %0, %0, %1;"    : "+l"(d) : "l"(a))

// Scratch (device globals; no allocation allowed)
__device__ float S_q  [ROWS*D];
__device__ float S_k  [ROWS*D];
__device__ float S_v  [ROWS*D];
__device__ float S_att[ROWS*D];
__device__ float S_t1 [ROWS*D];
__device__ float S_t2 [ROWS*D];

// ---------------------------------------------------------------------------
// SGEMM: C[ROWS,512] = A[ROWS,512] @ B[512,512]
// FLAGS: bit0 = +bias, bit1 = relu, bit2 = zero A rows where amask[row]!=0
// 128x64 tile, k-chunk 16, 256 threads, 4x8 microtile, FFMA2 inner,
// double-buffered smem, 3 CTAs/SM.
// ---------------------------------------------------------------------------
template<int FLAGS>
__global__ void __launch_bounds__(256, 3) sgemm_k(
    const float* __restrict__ A, const float* __restrict__ Bmat,
    const float* __restrict__ bias, const int* __restrict__ amask,
    float* __restrict__ C)
{
    __shared__ float As[2][16][132];   // [k][row] transposed
    __shared__ float Bs[2][16][68];    // [k][col]
    const int t  = threadIdx.x;
    const int tx = t & 7, ty = t >> 3;            // tx: 8 col-groups, ty: 32 row-groups
    const int row0 = blockIdx.y * 128, col0 = blockIdx.x * 64;
    const int ar = t >> 1, ak = (t & 1) * 8;      // A: 2 threads/row, 8 k each
    const int bk = t >> 4, bn = (t & 15) * 4;     // B: 16 k-rows, 16 threads/row

    const bool am = (FLAGS & 4) && (amask[row0 + ar] != 0);
    const float* Aptr = A + (size_t)(row0 + ar) * D + ak;
    const float* Bptr = Bmat + (size_t)bk * D + col0 + bn;

    float4 av0 = *(const float4*)Aptr;
    float4 av1 = *(const float4*)(Aptr + 4);
    float4 bv  = *(const float4*)Bptr;
    if (am) { av0 = make_float4(0,0,0,0); av1 = make_float4(0,0,0,0); }
    As[0][ak+0][ar] = av0.x; As[0][ak+1][ar] = av0.y;
    As[0][ak+2][ar] = av0.z; As[0][ak+3][ar] = av0.w;
    As[0][ak+4][ar] = av1.x; As[0][ak+5][ar] = av1.y;
    As[0][ak+6][ar] = av1.z; As[0][ak+7][ar] = av1.w;
    *(float4*)&Bs[0][bk][bn] = bv;
    __syncthreads();

    ull acc2[4][4] = {};   // 4 rows x (2 cols-pairs per 32-block x 2 blocks)

    #pragma unroll 1
    for (int c = 0; c < 32; c++) {
        int cur = c & 1;
        if (c < 31) {
            av0 = *(const float4*)(Aptr + (c + 1) * 16);
            av1 = *(const float4*)(Aptr + (c + 1) * 16 + 4);
            bv  = *(const float4*)(Bptr + (size_t)(c + 1) * 16 * D);
            if (am) { av0 = make_float4(0,0,0,0); av1 = make_float4(0,0,0,0); }
        }
        #pragma unroll
        for (int kk = 0; kk < 16; kk++) {
            float4 a  = *(const float4*)&As[cur][kk][ty * 4];
            float4 b0 = *(const float4*)&Bs[cur][kk][tx * 4];
            float4 b1 = *(const float4*)&Bs[cur][kk][32 + tx * 4];
            ull bp0 = pk2(b0.x, b0.y), bp1 = pk2(b0.z, b0.w);
            ull bp2 = pk2(b1.x, b1.y), bp3 = pk2(b1.z, b1.w);
            float ra[4] = {a.x, a.y, a.z, a.w};
            #pragma unroll
            for (int i = 0; i < 4; i++) {
                ull ap = pk2(ra[i], ra[i]);
                FMA2(acc2[i][0], ap, bp0);
                FMA2(acc2[i][1], ap, bp1);
                FMA2(acc2[i][2], ap, bp2);
                FMA2(acc2[i][3], ap, bp3);
            }
        }
        if (c < 31) {
            int nxt = cur ^ 1;
            As[nxt][ak+0][ar] = av0.x; As[nxt][ak+1][ar] = av0.y;
            As[nxt][ak+2][ar] = av0.z; As[nxt][ak+3][ar] = av0.w;
            As[nxt][ak+4][ar] = av1.x; As[nxt][ak+5][ar] = av1.y;
            As[nxt][ak+6][ar] = av1.z; As[nxt][ak+7][ar] = av1.w;
            *(float4*)&Bs[nxt][bk][bn] = bv;
            __syncthreads();
        }
    }

    #pragma unroll
    for (int i = 0; i < 4; i++) {
        int row = row0 + ty * 4 + i;
        #pragma unroll
        for (int cb = 0; cb < 2; cb++) {
            int col = col0 + cb * 32 + tx * 4;
            float2 v0 = upk2(acc2[i][cb * 2 + 0]);
            float2 v1 = upk2(acc2[i][cb * 2 + 1]);
            float vv[4] = {v0.x, v0.y, v1.x, v1.y};
            #pragma unroll
            for (int j = 0; j < 4; j++) {
                if (FLAGS & 1) vv[j] += bias[col + j];
                if (FLAGS & 2) vv[j] = fmaxf(vv[j], 0.f);
            }
            *(float4*)&C[(size_t)row * D + col] =
                make_float4(vv[0], vv[1], vv[2], vv[3]);
        }
    }
}

// ---------------------------------------------------------------------------
// Flash attention: one CTA = (b,h, 64-query tile). Online softmax over M=1024.
// 16x16 threads, 4q x 4k per thread, FFMA2, register softmax, 3 CTAs/SM.
// ---------------------------------------------------------------------------
__global__ void __launch_bounds__(256, 3) attn_k(
    const float* __restrict__ q, const float* __restrict__ k,
    const float* __restrict__ v,
    const int* __restrict__ xmask,
    const int* __restrict__ ymask,
    float* __restrict__ att)
{
    extern __shared__ float sm[];
    float* Qs = sm;              // [d=64][q=68]  pre-scaled
    float* Ks = Qs + 64 * 68;    // [d=64][k=68]
    float* Vs = Ks + 64 * 68;    // [m=64][d=68]
    float* Ss = Vs + 64 * 68;    // [k=64][q=68]  (exp'd P)

    const int bh = blockIdx.y;
    const int b  = bh >> 3, h = bh & 7;
    const int n0 = blockIdx.x * 64;
    const int t  = threadIdx.x;
    const int tx = t & 15, ty = t >> 4;

    const float* qbase = q + ((size_t)b * NN + n0) * D + h * DS;
    const float* kbase = k + (size_t)b * MM * D + h * DS;
    const float* vbase = v + (size_t)b * MM * D + h * DS;
    const int* ymb = ymask + b * MM;
    const int* xmb = xmask + b * NN;

    // Load Q tile (64x64) transposed into [d][q], scaled
    {
        int r = t >> 2;
        #pragma unroll
        for (int dd = 0; dd < 4; dd++) {
            int d4 = (t & 3) * 4 + dd * 16;
            float4 qa = *(const float4*)&qbase[(size_t)r * D + d4];
            Qs[(d4+0)*68 + r] = qa.x * SCALE; Qs[(d4+1)*68 + r] = qa.y * SCALE;
            Qs[(d4+2)*68 + r] = qa.z * SCALE; Qs[(d4+3)*68 + r] = qa.w * SCALE;
        }
    }

    float mi[4] = {-3.0e38f, -3.0e38f, -3.0e38f, -3.0e38f};
    float li[4] = {0.f, 0.f, 0.f, 0.f};
    ull acc2[4][2] = {};

    for (int m0 = 0; m0 < MM; m0 += 64) {
        __syncthreads();
        {
            int r = t >> 2;
            #pragma unroll
            for (int dd = 0; dd < 4; dd++) {
                int d4 = (t & 3) * 4 + dd * 16;
                float4 kv = *(const float4*)&kbase[(size_t)(m0 + r) * D + d4];
                Ks[(d4+0)*68 + r] = kv.x; Ks[(d4+1)*68 + r] = kv.y;
                Ks[(d4+2)*68 + r] = kv.z; Ks[(d4+3)*68 + r] = kv.w;
                float4 vv = *(const float4*)&vbase[(size_t)(m0 + r) * D + d4];
                *(float4*)&Vs[r * 68 + d4] = vv;
            }
        }
        __syncthreads();

        // S = (Q*SCALE).K^T : 4q x 4k per thread, FFMA2
        ull s2[4][2] = {};
        #pragma unroll 8
        for (int d = 0; d < 64; d++) {
            float4 qa = *(const float4*)&Qs[d * 68 + ty * 4];
            float4 kq = *(const float4*)&Ks[d * 68 + tx * 4];
            ull kp0 = pk2(kq.x, kq.y), kp1 = pk2(kq.z, kq.w);
            float qq[4] = {qa.x, qa.y, qa.z, qa.w};
            #pragma unroll
            for (int i = 0; i < 4; i++) {
                ull ap = pk2(qq[i], qq[i]);
                FMA2(s2[i][0], ap, kp0);
                FMA2(s2[i][1], ap, kp1);
            }
        }

        // unpack + key-mask
        float s[4][4];
        int km0 = ymb[m0 + tx * 4 + 0], km1 = ymb[m0 + tx * 4 + 1];
        int km2 = ymb[m0 + tx * 4 + 2], km3 = ymb[m0 + tx * 4 + 3];
        #pragma unroll
        for (int i = 0; i < 4; i++) {
            float2 v0 = upk2(s2[i][0]);
            float2 v1 = upk2(s2[i][1]);
            s[i][0] = km0 ? NEGV : v0.x;
            s[i][1] = km1 ? NEGV : v0.y;
            s[i][2] = km2 ? NEGV : v1.x;
            s[i][3] = km3 ? NEGV : v1.y;
        }

        // online softmax in registers (reduce across 16 tx lanes)
        #pragma unroll
        for (int i = 0; i < 4; i++) {
            float mx = fmaxf(fmaxf(s[i][0], s[i][1]), fmaxf(s[i][2], s[i][3]));
            mx = fmaxf(mx, __shfl_xor_sync(0xffffffffu, mx, 1));
            mx = fmaxf(mx, __shfl_xor_sync(0xffffffffu, mx, 2));
            mx = fmaxf(mx, __shfl_xor_sync(0xffffffffu, mx, 4));
            mx = fmaxf(mx, __shfl_xor_sync(0xffffffffu, mx, 8));
            float mnew = fmaxf(mi[i], mx);
            float corr = __expf(mi[i] - mnew);
            float p0 = __expf(s[i][0] - mnew);
            float p1 = __expf(s[i][1] - mnew);
            float p2 = __expf(s[i][2] - mnew);
            float p3 = __expf(s[i][3] - mnew);
            int r = ty * 4 + i;
            Ss[(tx*4+0)*68 + r] = p0;
            Ss[(tx*4+1)*68 + r] = p1;
            Ss[(tx*4+2)*68 + r] = p2;
            Ss[(tx*4+3)*68 + r] = p3;
            float sum = (p0 + p1) + (p2 + p3);
            sum += __shfl_xor_sync(0xffffffffu, sum, 1);
            sum += __shfl_xor_sync(0xffffffffu, sum, 2);
            sum += __shfl_xor_sync(0xffffffffu, sum, 4);
            sum += __shfl_xor_sync(0xffffffffu, sum, 8);
            li[i] = li[i] * corr + sum;
            mi[i] = mnew;
            ull cp = pk2(corr, corr);
            MUL2(acc2[i][0], cp);
            MUL2(acc2[i][1], cp);
        }
        __syncthreads();

        // acc += P.V : 4q x 4d per thread, FFMA2
        #pragma unroll 8
        for (int m = 0; m < 64; m++) {
            float4 pa = *(const float4*)&Ss[m * 68 + ty * 4];
            float4 vv = *(const float4*)&Vs[m * 68 + tx * 4];
            ull vp0 = pk2(vv.x, vv.y), vp1 = pk2(vv.z, vv.w);
            float pp[4] = {pa.x, pa.y, pa.z, pa.w};
            #pragma unroll
            for (int i = 0; i < 4; i++) {
                ull ap = pk2(pp[i], pp[i]);
                FMA2(acc2[i][0], ap, vp0);
                FMA2(acc2[i][1], ap, vp1);
            }
        }
    }

    // Writeout: att = acc / li, query-masked rows -> 0
    float* obase = att + ((size_t)b * NN + n0) * D + h * DS;
    #pragma unroll
    for (int i = 0; i < 4; i++) {
        int r = ty * 4 + i;
        float inv = 1.f / li[i];
        bool qm = xmb[n0 + r] != 0;
        float2 a0 = upk2(acc2[i][0]);
        float2 a1 = upk2(acc2[i][1]);
        float4 o;
        o.x = qm ? 0.f : a0.x * inv;
        o.y = qm ? 0.f : a0.y * inv;
        o.z = qm ? 0.f : a1.x * inv;
        o.w = qm ? 0.f : a1.y * inv;
        *(float4*)&obase[(size_t)r * D + tx * 4] = o;
    }
}

// ---------------------------------------------------------------------------
// out = LN(a' + b) * g + be
// mode bit0: zero OUTPUT rows where mask; bit1: zero `a` INPUT rows where mask
// ---------------------------------------------------------------------------
__global__ void __launch_bounds__(128) add_ln_k(
    const float* __restrict__ a, const float* __restrict__ bsrc,
    const float* __restrict__ g, const float* __restrict__ be,
    const int* __restrict__ xmask, int mode,
    float* __restrict__ out)
{
    int row = blockIdx.x;
    int t = threadIdx.x;
    const float* ar = a + (size_t)row * D;
    const float* br = bsrc + (size_t)row * D;
    bool rowmask = xmask[row] != 0;
    bool maska = (mode & 2) && rowmask;

    float vals[4];
    float s = 0.f;
    #pragma unroll
    for (int i = 0; i < 4; i++) {
        float av = maska ? 0.f : ar[t + i * 128];
        vals[i] = av + br[t + i * 128];
        s += vals[i];
    }
    __shared__ float red[4];
    #pragma unroll
    for (int o = 16; o; o >>= 1) s += __shfl_xor_sync(0xffffffffu, s, o);
    if ((t & 31) == 0) red[t >> 5] = s;
    __syncthreads();
    float mu = (red[0] + red[1] + red[2] + red[3]) * (1.f / 512.f);

    float s2 = 0.f;
    #pragma unroll
    for (int i = 0; i < 4; i++) { float d = vals[i] - mu; s2 += d * d; }
    __syncthreads();
    #pragma unroll
    for (int o = 16; o; o >>= 1) s2 += __shfl_xor_sync(0xffffffffu, s2, o);
    if ((t & 31) == 0) red[t >> 5] = s2;
    __syncthreads();
    float inv = rsqrtf((red[0] + red[1] + red[2] + red[3]) * (1.f / 512.f) + 1e-5f);

    bool maskout = (mode & 1) && rowmask;
    #pragma unroll
    for (int i = 0; i < 4; i++) {
        int c = t + i * 128;
        out[(size_t)row * D + c] = maskout ? 0.f : (vals[i] - mu) * inv * g[c] + be[c];
    }
}

// ---------------------------------------------------------------------------
extern "C" void kernel_launch(void* const* d_in, const int* in_sizes, int n_in,
                              void* d_out, int out_size)
{
    const float* x  = (const float*)d_in[0];
    const float* y  = (const float*)d_in[1];
    const int* xm = (const int*)d_in[2];
    const int* ym = (const int*)d_in[3];
    const float* Wq = (const float*)d_in[4];
    const float* Wk = (const float*)d_in[5];
    const float* Wv = (const float*)d_in[6];
    const float* Wo = (const float*)d_in[7];
    const float* W1 = (const float*)d_in[8];
    const float* b1 = (const float*)d_in[9];
    const float* W2 = (const float*)d_in[10];
    const float* b2 = (const float*)d_in[11];
    const float* g1 = (const float*)d_in[12];
    const float* be1= (const float*)d_in[13];
    const float* g2 = (const float*)d_in[14];
    const float* be2= (const float*)d_in[15];
    float* out = (float*)d_out;

    float *q, *k, *v, *att, *t1, *t2;
    cudaGetSymbolAddress((void**)&q,   S_q);
    cudaGetSymbolAddress((void**)&k,   S_k);
    cudaGetSymbolAddress((void**)&v,   S_v);
    cudaGetSymbolAddress((void**)&att, S_att);
    cudaGetSymbolAddress((void**)&t1,  S_t1);
    cudaGetSymbolAddress((void**)&t2,  S_t2);

    const int smem_attn = (4 * 64 * 68) * sizeof(float); // 69632
    cudaFuncSetAttribute(attn_k, cudaFuncAttributeMaxDynamicSharedMemorySize, smem_attn);

    dim3 gg(8, 64);   // 64-col tiles x 128-row tiles
    sgemm_k<4><<<gg, 256>>>(x, Wq, nullptr, xm, q);
    sgemm_k<4><<<gg, 256>>>(y, Wk, nullptr, ym, k);
    sgemm_k<4><<<gg, 256>>>(y, Wv, nullptr, ym, v);

    dim3 ga(16, 64);  // 16 q-tiles (64 each) x (B*H)
    attn_k<<<ga, 256, smem_attn>>>(q, k, v, xm, ym, att);

    sgemm_k<0><<<gg, 256>>>(att, Wo, nullptr, nullptr, t1);   // t1 = att@Wo
    add_ln_k<<<ROWS, 128>>>(x, t1, g1, be1, xm, 2, t2);        // t2 = LN1(x_masked + t1)
    sgemm_k<3><<<gg, 256>>>(t2, W1, b1, nullptr, q);           // q = relu(t2@W1+b1)
    sgemm_k<1><<<gg, 256>>>(q, W2, b2, nullptr, k);            // k = ff
    add_ln_k<<<ROWS, 128>>>(t2, k, g2, be2, xm, 1, out);       // out = LN2(t2+ff), masked
}

// round 11
// speedup vs baseline: 1.4297x; 1.4297x over previous
#include <cuda_runtime.h>
#include <cuda_bf16.h>
#include <math.h>
#include <stdint.h>

#define BB 8
#define NN 1024
#define MM 1024
#define D  512
#define HH 8
#define DS 64
#define ROWS (BB*NN)          // 8192
#define NEGV (-1e38f)
#define SCALE 0.04419417382415922f   // 1/sqrt(512)

typedef unsigned long long ull;

// ---------------- packed f32x2 helpers ----------------
__device__ __forceinline__ ull pk2(float lo, float hi) {
    ull r;
    asm("mov.b64 %0, {%1, %2};" : "=l"(r) : "f"(lo), "f"(hi));
    return r;
}
__device__ __forceinline__ float2 upk2(ull v) {
    float2 f;
    asm("mov.b64 {%0, %1}, %2;" : "=f"(f.x), "=f"(f.y) : "l"(v));
    return f;
}
#define FMA2(d, a, b) asm("fma.rn.f32x2 %0, %1, %2, %0;" : "+l"(d) : "l"(a), "l"(b))
#define MUL2(d, a)    asm("mul.rn.f32x2 %0, %0, %1;"    : "+l"(d) : "l"(a))

// bf16x2 MMA: D(16x8 f32) += A(16x16) * B(16x8), row.col
#define MMA(d, a0,a1,a2,a3, b0,b1) \
    asm volatile("mma.sync.aligned.m16n8k16.row.col.f32.bf16.bf16.f32 " \
        "{%0,%1,%2,%3}, {%4,%5,%6,%7}, {%8,%9}, {%0,%1,%2,%3};" \
        : "+f"(d[0]),"+f"(d[1]),"+f"(d[2]),"+f"(d[3]) \
        : "r"(a0),"r"(a1),"r"(a2),"r"(a3),"r"(b0),"r"(b1))

// ---------------- scratch (device globals) ----------------
__device__ float S_q  [ROWS*D];
__device__ float S_k  [ROWS*D];
__device__ float S_v  [ROWS*D];
__device__ float S_att[ROWS*D];
__device__ float S_t1 [ROWS*D];
__device__ float S_t2 [ROWS*D];
__device__ __nv_bfloat16 S_WH[6][D*D];   // weights transposed [n][k] hi
__device__ __nv_bfloat16 S_WL[6][D*D];   // weights transposed [n][k] lo
__device__ __nv_bfloat16 S_AH[ROWS*D];   // activation hi (per-GEMM reuse)
__device__ __nv_bfloat16 S_AL[ROWS*D];   // activation lo

// ---------------------------------------------------------------------------
// Weight prep: Wt_hi[n][k] = bf16(W[k][n]); Wt_lo = bf16(residual)
// ---------------------------------------------------------------------------
__global__ void __launch_bounds__(256) wsplit_k(
    const float* __restrict__ W,
    __nv_bfloat16* __restrict__ WhiT, __nv_bfloat16* __restrict__ WloT)
{
    int idx = blockIdx.x * 256 + threadIdx.x;   // 262144
    int n = idx & 511, kk = idx >> 9;
    float w = W[(size_t)kk * D + n];
    __nv_bfloat16 h = __float2bfloat16_rn(w);
    __nv_bfloat16 l = __float2bfloat16_rn(w - __bfloat162float(h));
    WhiT[(size_t)n * D + kk] = h;
    WloT[(size_t)n * D + kk] = l;
}

// ---------------------------------------------------------------------------
// Activation split: AH/AL[row][k] bf16 from f32 A, optional row-mask zero.
// ---------------------------------------------------------------------------
__global__ void __launch_bounds__(256) asplit_k(
    const float* __restrict__ A, const int* __restrict__ mask, int use_mask,
    __nv_bfloat16* __restrict__ AHg, __nv_bfloat16* __restrict__ ALg)
{
    int i4 = blockIdx.x * 256 + threadIdx.x;   // ROWS*D/4 = 1048576
    int row = i4 >> 7;
    float4 f = ((const float4*)A)[i4];
    if (use_mask && mask[row]) f = make_float4(0.f, 0.f, 0.f, 0.f);
    __nv_bfloat162 h0 = __floats2bfloat162_rn(f.x, f.y);
    __nv_bfloat162 h1 = __floats2bfloat162_rn(f.z, f.w);
    float2 hf0 = __bfloat1622float2(h0);
    float2 hf1 = __bfloat1622float2(h1);
    __nv_bfloat162 l0 = __floats2bfloat162_rn(f.x - hf0.x, f.y - hf0.y);
    __nv_bfloat162 l1 = __floats2bfloat162_rn(f.z - hf1.x, f.w - hf1.y);
    uint2 hh, ll;
    hh.x = *(uint32_t*)&h0; hh.y = *(uint32_t*)&h1;
    ll.x = *(uint32_t*)&l0; ll.y = *(uint32_t*)&l1;
    *(uint2*)(AHg + (size_t)i4 * 4) = hh;
    *(uint2*)(ALg + (size_t)i4 * 4) = ll;
}

// ---------------------------------------------------------------------------
// bf16 tensor-core GEMM: C[8192,512] = A @ Wt^T, split precision
// (Ah.Bh + Ah.Bl + Al.Bh, fp32 accum). Tile 128x128, k-chunk 32,
// 8 warps in 2x4, warp tile 64x32 (4 m16 x 4 n8 MMA tiles).
// FLAGS: bit0 +bias, bit1 relu.
// ---------------------------------------------------------------------------
template<int FLAGS>
__global__ void __launch_bounds__(256) hgemm_k(
    const __nv_bfloat16* __restrict__ AHg, const __nv_bfloat16* __restrict__ ALg,
    const __nv_bfloat16* __restrict__ BHg, const __nv_bfloat16* __restrict__ BLg,
    const float* __restrict__ bias, float* __restrict__ C)
{
    __shared__ __nv_bfloat16 AH[128][40], AL[128][40], BH[128][40], BL[128][40];
    const int t = threadIdx.x, lane = t & 31, wid = t >> 5;
    const int wm = wid >> 2, wn = wid & 3;        // 2 x 4 warp grid
    const int g = lane >> 2, tg = lane & 3;       // mma fragment coords
    const int row0 = blockIdx.y * 128, col0 = blockIdx.x * 128;
    const int lr = t >> 1, lc = (t & 1) * 16;     // smem fill: 2 thr/row

    const __nv_bfloat16* AHp = AHg + (size_t)(row0 + lr) * D + lc;
    const __nv_bfloat16* ALp = ALg + (size_t)(row0 + lr) * D + lc;
    const __nv_bfloat16* BHp = BHg + (size_t)(col0 + lr) * D + lc;
    const __nv_bfloat16* BLp = BLg + (size_t)(col0 + lr) * D + lc;

    float acc[4][4][4] = {};   // [mt][nt][frag]

    #pragma unroll 1
    for (int kc = 0; kc < 16; kc++) {
        const int ko = kc * 32;
        #pragma unroll
        for (int j = 0; j < 2; j++) {
            *(uint4*)&AH[lr][lc + j*8] = *(const uint4*)(AHp + ko + j*8);
            *(uint4*)&AL[lr][lc + j*8] = *(const uint4*)(ALp + ko + j*8);
            *(uint4*)&BH[lr][lc + j*8] = *(const uint4*)(BHp + ko + j*8);
            *(uint4*)&BL[lr][lc + j*8] = *(const uint4*)(BLp + ko + j*8);
        }
        __syncthreads();

        #pragma unroll
        for (int ks = 0; ks < 32; ks += 16) {
            uint32_t bh0[4], bh1[4], bl0[4], bl1[4];
            #pragma unroll
            for (int nt = 0; nt < 4; nt++) {
                int nr = wn * 32 + nt * 8 + g;
                bh0[nt] = *(const uint32_t*)&BH[nr][ks + tg*2];
                bh1[nt] = *(const uint32_t*)&BH[nr][ks + tg*2 + 8];
                bl0[nt] = *(const uint32_t*)&BL[nr][ks + tg*2];
                bl1[nt] = *(const uint32_t*)&BL[nr][ks + tg*2 + 8];
            }
            #pragma unroll
            for (int mt = 0; mt < 4; mt++) {
                int mr = wm * 64 + mt * 16 + g;
                uint32_t ah0 = *(const uint32_t*)&AH[mr][ks + tg*2];
                uint32_t ah1 = *(const uint32_t*)&AH[mr + 8][ks + tg*2];
                uint32_t ah2 = *(const uint32_t*)&AH[mr][ks + tg*2 + 8];
                uint32_t ah3 = *(const uint32_t*)&AH[mr + 8][ks + tg*2 + 8];
                uint32_t al0 = *(const uint32_t*)&AL[mr][ks + tg*2];
                uint32_t al1 = *(const uint32_t*)&AL[mr + 8][ks + tg*2];
                uint32_t al2 = *(const uint32_t*)&AL[mr][ks + tg*2 + 8];
                uint32_t al3 = *(const uint32_t*)&AL[mr + 8][ks + tg*2 + 8];
                #pragma unroll
                for (int nt = 0; nt < 4; nt++) {
                    MMA(acc[mt][nt], ah0, ah1, ah2, ah3, bh0[nt], bh1[nt]);
                    MMA(acc[mt][nt], ah0, ah1, ah2, ah3, bl0[nt], bl1[nt]);
                    MMA(acc[mt][nt], al0, al1, al2, al3, bh0[nt], bh1[nt]);
                }
            }
        }
        __syncthreads();
    }

    // epilogue: fragment -> global, bias/relu
    #pragma unroll
    for (int mt = 0; mt < 4; mt++) {
        int row = row0 + wm * 64 + mt * 16 + g;
        #pragma unroll
        for (int nt = 0; nt < 4; nt++) {
            int col = col0 + wn * 32 + nt * 8 + tg * 2;
            float2 v0 = make_float2(acc[mt][nt][0], acc[mt][nt][1]);
            float2 v1 = make_float2(acc[mt][nt][2], acc[mt][nt][3]);
            if (FLAGS & 1) {
                float bb0 = bias[col], bb1 = bias[col + 1];
                v0.x += bb0; v0.y += bb1; v1.x += bb0; v1.y += bb1;
            }
            if (FLAGS & 2) {
                v0.x = fmaxf(v0.x, 0.f); v0.y = fmaxf(v0.y, 0.f);
                v1.x = fmaxf(v1.x, 0.f); v1.y = fmaxf(v1.y, 0.f);
            }
            *(float2*)&C[(size_t)row * D + col] = v0;
            *(float2*)&C[(size_t)(row + 8) * D + col] = v1;
        }
    }
}

// ---------------------------------------------------------------------------
// Flash attention (round-5 best): one CTA = (b,h, 128-query tile), FFMA2,
// register online-softmax, 64-key chunks.
// ---------------------------------------------------------------------------
#define QT 128
__global__ void __launch_bounds__(256) attn_k(
    const float* __restrict__ q, const float* __restrict__ k,
    const float* __restrict__ v,
    const int* __restrict__ xmask,
    const int* __restrict__ ymask,
    float* __restrict__ att)
{
    extern __shared__ float sm[];
    float* Qs = sm;               // [d=64][q=132]  pre-scaled
    float* Ks = Qs + 64 * 132;    // [d=64][k=68]
    float* Vs = Ks + 64 * 68;     // [m=64][d=68]
    float* Ss = Vs + 64 * 68;     // [k=64][q=132]  (exp'd P)

    const int bh = blockIdx.y;
    const int b  = bh >> 3, h = bh & 7;
    const int n0 = blockIdx.x * QT;
    const int t  = threadIdx.x;
    const int tx = t & 15, ty = t >> 4;

    const float* qbase = q + ((size_t)b * NN + n0) * D + h * DS;
    const float* kbase = k + (size_t)b * MM * D + h * DS;
    const float* vbase = v + (size_t)b * MM * D + h * DS;
    const int* ymb = ymask + b * MM;
    const int* xmb = xmask + b * NN;

    {
        int r = t >> 1;
        #pragma unroll
        for (int dd = 0; dd < 8; dd++) {
            int d4 = (t & 1) * 4 + dd * 8;
            float4 qa = *(const float4*)&qbase[(size_t)r * D + d4];
            Qs[(d4+0)*132 + r] = qa.x * SCALE; Qs[(d4+1)*132 + r] = qa.y * SCALE;
            Qs[(d4+2)*132 + r] = qa.z * SCALE; Qs[(d4+3)*132 + r] = qa.w * SCALE;
        }
    }

    float mi[8], li[8];
    #pragma unroll
    for (int i = 0; i < 8; i++) { mi[i] = -3.0e38f; li[i] = 0.f; }
    ull acc2[8][2] = {};

    for (int m0 = 0; m0 < MM; m0 += 64) {
        __syncthreads();
        {
            int r = t >> 2;
            #pragma unroll
            for (int dd = 0; dd < 4; dd++) {
                int d4 = (t & 3) * 4 + dd * 16;
                float4 kv = *(const float4*)&kbase[(size_t)(m0 + r) * D + d4];
                Ks[(d4+0)*68 + r] = kv.x; Ks[(d4+1)*68 + r] = kv.y;
                Ks[(d4+2)*68 + r] = kv.z; Ks[(d4+3)*68 + r] = kv.w;
                float4 vv = *(const float4*)&vbase[(size_t)(m0 + r) * D + d4];
                *(float4*)&Vs[r * 68 + d4] = vv;
            }
        }
        __syncthreads();

        ull s2[8][2] = {};
        #pragma unroll 4
        for (int d = 0; d < 64; d++) {
            float4 q0 = *(const float4*)&Qs[d * 132 + ty * 8];
            float4 q1 = *(const float4*)&Qs[d * 132 + ty * 8 + 4];
            float4 kq = *(const float4*)&Ks[d * 68 + tx * 4];
            ull kp0 = pk2(kq.x, kq.y), kp1 = pk2(kq.z, kq.w);
            float qa[8] = {q0.x,q0.y,q0.z,q0.w,q1.x,q1.y,q1.z,q1.w};
            #pragma unroll
            for (int i = 0; i < 8; i++) {
                ull ap = pk2(qa[i], qa[i]);
                FMA2(s2[i][0], ap, kp0);
                FMA2(s2[i][1], ap, kp1);
            }
        }

        float s[8][4];
        int km0 = ymb[m0 + tx * 4 + 0], km1 = ymb[m0 + tx * 4 + 1];
        int km2 = ymb[m0 + tx * 4 + 2], km3 = ymb[m0 + tx * 4 + 3];
        #pragma unroll
        for (int i = 0; i < 8; i++) {
            float2 v0 = upk2(s2[i][0]);
            float2 v1 = upk2(s2[i][1]);
            s[i][0] = km0 ? NEGV : v0.x;
            s[i][1] = km1 ? NEGV : v0.y;
            s[i][2] = km2 ? NEGV : v1.x;
            s[i][3] = km3 ? NEGV : v1.y;
        }

        #pragma unroll
        for (int i = 0; i < 8; i++) {
            float mx = fmaxf(fmaxf(s[i][0], s[i][1]), fmaxf(s[i][2], s[i][3]));
            mx = fmaxf(mx, __shfl_xor_sync(0xffffffffu, mx, 1));
            mx = fmaxf(mx, __shfl_xor_sync(0xffffffffu, mx, 2));
            mx = fmaxf(mx, __shfl_xor_sync(0xffffffffu, mx, 4));
            mx = fmaxf(mx, __shfl_xor_sync(0xffffffffu, mx, 8));
            float mnew = fmaxf(mi[i], mx);
            float corr = __expf(mi[i] - mnew);
            float p0 = __expf(s[i][0] - mnew);
            float p1 = __expf(s[i][1] - mnew);
            float p2 = __expf(s[i][2] - mnew);
            float p3 = __expf(s[i][3] - mnew);
            int r = ty * 8 + i;
            Ss[(tx*4+0)*132 + r] = p0;
            Ss[(tx*4+1)*132 + r] = p1;
            Ss[(tx*4+2)*132 + r] = p2;
            Ss[(tx*4+3)*132 + r] = p3;
            float sum = (p0 + p1) + (p2 + p3);
            sum += __shfl_xor_sync(0xffffffffu, sum, 1);
            sum += __shfl_xor_sync(0xffffffffu, sum, 2);
            sum += __shfl_xor_sync(0xffffffffu, sum, 4);
            sum += __shfl_xor_sync(0xffffffffu, sum, 8);
            li[i] = li[i] * corr + sum;
            mi[i] = mnew;
            ull cp = pk2(corr, corr);
            MUL2(acc2[i][0], cp);
            MUL2(acc2[i][1], cp);
        }
        __syncthreads();

        #pragma unroll 4
        for (int m = 0; m < 64; m++) {
            float4 p0 = *(const float4*)&Ss[m * 132 + ty * 8];
            float4 p1 = *(const float4*)&Ss[m * 132 + ty * 8 + 4];
            float4 vv = *(const float4*)&Vs[m * 68 + tx * 4];
            ull vp0 = pk2(vv.x, vv.y), vp1 = pk2(vv.z, vv.w);
            float pa[8] = {p0.x,p0.y,p0.z,p0.w,p1.x,p1.y,p1.z,p1.w};
            #pragma unroll
            for (int i = 0; i < 8; i++) {
                ull ap = pk2(pa[i], pa[i]);
                FMA2(acc2[i][0], ap, vp0);
                FMA2(acc2[i][1], ap, vp1);
            }
        }
    }

    float* obase = att + ((size_t)b * NN + n0) * D + h * DS;
    #pragma unroll
    for (int i = 0; i < 8; i++) {
        int r = ty * 8 + i;
        float inv = 1.f / li[i];
        bool qm = xmb[n0 + r] != 0;
        float2 a0 = upk2(acc2[i][0]);
        float2 a1 = upk2(acc2[i][1]);
        float4 o;
        o.x = qm ? 0.f : a0.x * inv;
        o.y = qm ? 0.f : a0.y * inv;
        o.z = qm ? 0.f : a1.x * inv;
        o.w = qm ? 0.f : a1.y * inv;
        *(float4*)&obase[(size_t)r * D + tx * 4] = o;
    }
}

// ---------------------------------------------------------------------------
// out = LN(a' + b) * g + be
// mode bit0: zero OUTPUT rows where mask; bit1: zero `a` INPUT rows where mask
// ---------------------------------------------------------------------------
__global__ void __launch_bounds__(128) add_ln_k(
    const float* __restrict__ a, const float* __restrict__ bsrc,
    const float* __restrict__ g, const float* __restrict__ be,
    const int* __restrict__ xmask, int mode,
    float* __restrict__ out)
{
    int row = blockIdx.x;
    int t = threadIdx.x;
    const float* ar = a + (size_t)row * D;
    const float* br = bsrc + (size_t)row * D;
    bool rowmask = xmask[row] != 0;
    bool maska = (mode & 2) && rowmask;

    float vals[4];
    float s = 0.f;
    #pragma unroll
    for (int i = 0; i < 4; i++) {
        float av = maska ? 0.f : ar[t + i * 128];
        vals[i] = av + br[t + i * 128];
        s += vals[i];
    }
    __shared__ float red[4];
    #pragma unroll
    for (int o = 16; o; o >>= 1) s += __shfl_xor_sync(0xffffffffu, s, o);
    if ((t & 31) == 0) red[t >> 5] = s;
    __syncthreads();
    float mu = (red[0] + red[1] + red[2] + red[3]) * (1.f / 512.f);

    float s2 = 0.f;
    #pragma unroll
    for (int i = 0; i < 4; i++) { float d = vals[i] - mu; s2 += d * d; }
    __syncthreads();
    #pragma unroll
    for (int o = 16; o; o >>= 1) s2 += __shfl_xor_sync(0xffffffffu, s2, o);
    if ((t & 31) == 0) red[t >> 5] = s2;
    __syncthreads();
    float inv = rsqrtf((red[0] + red[1] + red[2] + red[3]) * (1.f / 512.f) + 1e-5f);

    bool maskout = (mode & 1) && rowmask;
    #pragma unroll
    for (int i = 0; i < 4; i++) {
        int c = t + i * 128;
        out[(size_t)row * D + c] = maskout ? 0.f : (vals[i] - mu) * inv * g[c] + be[c];
    }
}

// ---------------------------------------------------------------------------
extern "C" void kernel_launch(void* const* d_in, const int* in_sizes, int n_in,
                              void* d_out, int out_size)
{
    const float* x  = (const float*)d_in[0];
    const float* y  = (const float*)d_in[1];
    const int* xm = (const int*)d_in[2];
    const int* ym = (const int*)d_in[3];
    const float* W[6] = { (const float*)d_in[4], (const float*)d_in[5],
                          (const float*)d_in[6], (const float*)d_in[7],
                          (const float*)d_in[8], (const float*)d_in[10] };
    const float* b1 = (const float*)d_in[9];
    const float* b2 = (const float*)d_in[11];
    const float* g1 = (const float*)d_in[12];
    const float* be1= (const float*)d_in[13];
    const float* g2 = (const float*)d_in[14];
    const float* be2= (const float*)d_in[15];
    float* out = (float*)d_out;

    float *q, *k, *v, *att, *t1, *t2;
    cudaGetSymbolAddress((void**)&q,   S_q);
    cudaGetSymbolAddress((void**)&k,   S_k);
    cudaGetSymbolAddress((void**)&v,   S_v);
    cudaGetSymbolAddress((void**)&att, S_att);
    cudaGetSymbolAddress((void**)&t1,  S_t1);
    cudaGetSymbolAddress((void**)&t2,  S_t2);
    __nv_bfloat16 *wh, *wl, *ah, *al;
    cudaGetSymbolAddress((void**)&wh, S_WH);
    cudaGetSymbolAddress((void**)&wl, S_WL);
    cudaGetSymbolAddress((void**)&ah, S_AH);
    cudaGetSymbolAddress((void**)&al, S_AL);

    const int smem_attn = (64*132 + 64*68 + 64*68 + 64*132) * sizeof(float); // 102400
    cudaFuncSetAttribute(attn_k, cudaFuncAttributeMaxDynamicSharedMemorySize, smem_attn);

    // one-time weight prep (Wq,Wk,Wv,Wo,W1,W2): transpose + bf16 split
    for (int i = 0; i < 6; i++)
        wsplit_k<<<1024, 256>>>(W[i], wh + (size_t)i * D * D, wl + (size_t)i * D * D);

    dim3 gg(4, 64);   // 128x128 tiles

    // q = x @ Wq (masked rows of x zeroed)
    asplit_k<<<4096, 256>>>(x, xm, 1, ah, al);
    hgemm_k<0><<<gg, 256>>>(ah, al, wh + 0*(size_t)D*D, wl + 0*(size_t)D*D, nullptr, q);
    // k = y @ Wk, v = y @ Wv (same split of masked y)
    asplit_k<<<4096, 256>>>(y, ym, 1, ah, al);
    hgemm_k<0><<<gg, 256>>>(ah, al, wh + 1*(size_t)D*D, wl + 1*(size_t)D*D, nullptr, k);
    hgemm_k<0><<<gg, 256>>>(ah, al, wh + 2*(size_t)D*D, wl + 2*(size_t)D*D, nullptr, v);

    dim3 ga(8, 64);   // 8 q-tiles (128 each) x (B*H)
    attn_k<<<ga, 256, smem_attn>>>(q, k, v, xm, ym, att);

    // t1 = att @ Wo
    asplit_k<<<4096, 256>>>(att, nullptr, 0, ah, al);
    hgemm_k<0><<<gg, 256>>>(ah, al, wh + 3*(size_t)D*D, wl + 3*(size_t)D*D, nullptr, t1);
    add_ln_k<<<ROWS, 128>>>(x, t1, g1, be1, xm, 2, t2);     // t2 = LN1(x_masked + t1)
    // q = relu(t2 @ W1 + b1)
    asplit_k<<<4096, 256>>>(t2, nullptr, 0, ah, al);
    hgemm_k<3><<<gg, 256>>>(ah, al, wh + 4*(size_t)D*D, wl + 4*(size_t)D*D, b1, q);
    // k = q @ W2 + b2
    asplit_k<<<4096, 256>>>(q, nullptr, 0, ah, al);
    hgemm_k<1><<<gg, 256>>>(ah, al, wh + 5*(size_t)D*D, wl + 5*(size_t)D*D, b2, k);
    add_ln_k<<<ROWS, 128>>>(t2, k, g2, be2, xm, 1, out);    // out = LN2(t2+ff), masked
}

// round 12
// speedup vs baseline: 2.0476x; 1.4321x over previous
#include <cuda_runtime.h>
#include <cuda_bf16.h>
#include <math.h>
#include <stdint.h>

#define BB 8
#define NN 1024
#define MM 1024
#define D  512
#define HH 8
#define DS 64
#define ROWS (BB*NN)          // 8192
#define NEGV (-1e38f)
#define SCALE 0.04419417382415922f   // 1/sqrt(512)

typedef unsigned int u32;
typedef __nv_bfloat16 bf16;

// pack two f32 -> bf16x2 {lo, hi}
__device__ __forceinline__ u32 pkbf(float lo, float hi) {
    u32 r;
    asm("cvt.rn.bf16x2.f32 %0, %1, %2;" : "=r"(r) : "f"(hi), "f"(lo));
    return r;
}
__device__ __forceinline__ float2 upbf(u32 p) {
    __nv_bfloat162 b2 = *reinterpret_cast<__nv_bfloat162*>(&p);
    return __bfloat1622float2(b2);
}

// bf16x2 MMA: D(16x8 f32) += A(16x16) * B(16x8), row.col
#define MMA(d, a0,a1,a2,a3, b0,b1) \
    asm volatile("mma.sync.aligned.m16n8k16.row.col.f32.bf16.bf16.f32 " \
        "{%0,%1,%2,%3}, {%4,%5,%6,%7}, {%8,%9}, {%0,%1,%2,%3};" \
        : "+f"(d[0]),"+f"(d[1]),"+f"(d[2]),"+f"(d[3]) \
        : "r"(a0),"r"(a1),"r"(a2),"r"(a3),"r"(b0),"r"(b1))

// ---------------- scratch (device globals) ----------------
__device__ float S_t1 [ROWS*D];
__device__ float S_t2 [ROWS*D];
__device__ float S_ff [ROWS*D];
__device__ bf16 S_WH[6*D*D], S_WL[6*D*D];         // weights [n][k] split
__device__ bf16 S_XH[ROWS*D], S_XL[ROWS*D];
__device__ bf16 S_YH[ROWS*D], S_YL[ROWS*D];
__device__ bf16 S_QH[ROWS*D], S_QL[ROWS*D];
__device__ bf16 S_KH[ROWS*D], S_KL[ROWS*D];
__device__ bf16 S_VTH[ROWS*D], S_VTL[ROWS*D];     // [b*h][d][key]
__device__ bf16 S_ATH[ROWS*D], S_ATL[ROWS*D];
__device__ bf16 S_T2H[ROWS*D], S_T2L[ROWS*D];
__device__ bf16 S_RH[ROWS*D],  S_RL[ROWS*D];

// ---------------------------------------------------------------------------
// Fused weight prep: all 6 weights, transpose + bf16 split; Wq gets SCALE.
// ---------------------------------------------------------------------------
__global__ void __launch_bounds__(256) wsplit_all(
    const float* __restrict__ W0, const float* __restrict__ W1,
    const float* __restrict__ W2, const float* __restrict__ W3,
    const float* __restrict__ W4, const float* __restrict__ W5,
    bf16* __restrict__ WH, bf16* __restrict__ WL)
{
    int gi = blockIdx.x;
    int wi = gi >> 10;
    const float* W = (wi == 0) ? W0 : (wi == 1) ? W1 : (wi == 2) ? W2
                   : (wi == 3) ? W3 : (wi == 4) ? W4 : W5;
    float sc = (wi == 0) ? SCALE : 1.f;
    int idx = (gi & 1023) * 256 + threadIdx.x;
    int n = idx & 511, kk = idx >> 9;
    float w = W[(size_t)kk * D + n] * sc;
    bf16 h = __float2bfloat16_rn(w);
    bf16 l = __float2bfloat16_rn(w - __bfloat162float(h));
    WH[(size_t)wi * D * D + (size_t)n * D + kk] = h;
    WL[(size_t)wi * D * D + (size_t)n * D + kk] = l;
}

// ---------------------------------------------------------------------------
// Activation split (x, y only): bf16 hi/lo with row-mask zero.
// ---------------------------------------------------------------------------
__global__ void __launch_bounds__(256) asplit_k(
    const float* __restrict__ A, const int* __restrict__ mask,
    bf16* __restrict__ AHg, bf16* __restrict__ ALg)
{
    int i4 = blockIdx.x * 256 + threadIdx.x;   // ROWS*D/4
    int row = i4 >> 7;
    float4 f = ((const float4*)A)[i4];
    if (mask[row]) f = make_float4(0.f, 0.f, 0.f, 0.f);
    u32 h0 = pkbf(f.x, f.y), h1 = pkbf(f.z, f.w);
    float2 a = upbf(h0), b = upbf(h1);
    u32 l0 = pkbf(f.x - a.x, f.y - a.y), l1 = pkbf(f.z - b.x, f.w - b.y);
    uint2 hh = make_uint2(h0, h1), ll = make_uint2(l0, l1);
    *(uint2*)(AHg + (size_t)i4 * 4) = hh;
    *(uint2*)(ALg + (size_t)i4 * 4) = ll;
}

// ---------------------------------------------------------------------------
// bf16 tensor-core GEMM, split precision (Ah.Bh + Ah.Bl + Al.Bh).
// Tile 128x128, k-chunk 32, 8 warps 2x4, warp tile 64x32.
// FLAGS: bit0 +bias, bit1 relu, bit3(8) split bf16 out, bit4(16) vT split out.
// ---------------------------------------------------------------------------
__device__ __forceinline__ size_t vtidx(int row, int col) {
    return (((size_t)(row >> 10) * 8 + (col >> 6)) * 64 + (col & 63)) * 1024
           + (row & 1023);
}

template<int FLAGS>
__global__ void __launch_bounds__(256) hgemm_k(
    const bf16* __restrict__ AHg, const bf16* __restrict__ ALg,
    const bf16* __restrict__ BHg, const bf16* __restrict__ BLg,
    const float* __restrict__ bias, float* __restrict__ C,
    bf16* __restrict__ CH, bf16* __restrict__ CL)
{
    __shared__ bf16 AH[128][40], AL[128][40], BH[128][40], BL[128][40];
    const int t = threadIdx.x, lane = t & 31, wid = t >> 5;
    const int wm = wid >> 2, wn = wid & 3;
    const int g = lane >> 2, tg = lane & 3;
    const int row0 = blockIdx.y * 128, col0 = blockIdx.x * 128;
    const int lr = t >> 1, lc = (t & 1) * 16;

    const bf16* AHp = AHg + (size_t)(row0 + lr) * D + lc;
    const bf16* ALp = ALg + (size_t)(row0 + lr) * D + lc;
    const bf16* BHp = BHg + (size_t)(col0 + lr) * D + lc;
    const bf16* BLp = BLg + (size_t)(col0 + lr) * D + lc;

    float acc[4][4][4] = {};

    #pragma unroll 1
    for (int kc = 0; kc < 16; kc++) {
        const int ko = kc * 32;
        #pragma unroll
        for (int j = 0; j < 2; j++) {
            *(uint4*)&AH[lr][lc + j*8] = *(const uint4*)(AHp + ko + j*8);
            *(uint4*)&AL[lr][lc + j*8] = *(const uint4*)(ALp + ko + j*8);
            *(uint4*)&BH[lr][lc + j*8] = *(const uint4*)(BHp + ko + j*8);
            *(uint4*)&BL[lr][lc + j*8] = *(const uint4*)(BLp + ko + j*8);
        }
        __syncthreads();

        #pragma unroll
        for (int ks = 0; ks < 32; ks += 16) {
            u32 bh0[4], bh1[4], bl0[4], bl1[4];
            #pragma unroll
            for (int nt = 0; nt < 4; nt++) {
                int nr = wn * 32 + nt * 8 + g;
                bh0[nt] = *(const u32*)&BH[nr][ks + tg*2];
                bh1[nt] = *(const u32*)&BH[nr][ks + tg*2 + 8];
                bl0[nt] = *(const u32*)&BL[nr][ks + tg*2];
                bl1[nt] = *(const u32*)&BL[nr][ks + tg*2 + 8];
            }
            #pragma unroll
            for (int mt = 0; mt < 4; mt++) {
                int mr = wm * 64 + mt * 16 + g;
                u32 ah0 = *(const u32*)&AH[mr][ks + tg*2];
                u32 ah1 = *(const u32*)&AH[mr + 8][ks + tg*2];
                u32 ah2 = *(const u32*)&AH[mr][ks + tg*2 + 8];
                u32 ah3 = *(const u32*)&AH[mr + 8][ks + tg*2 + 8];
                u32 al0 = *(const u32*)&AL[mr][ks + tg*2];
                u32 al1 = *(const u32*)&AL[mr + 8][ks + tg*2];
                u32 al2 = *(const u32*)&AL[mr][ks + tg*2 + 8];
                u32 al3 = *(const u32*)&AL[mr + 8][ks + tg*2 + 8];
                #pragma unroll
                for (int nt = 0; nt < 4; nt++) {
                    MMA(acc[mt][nt], ah0, ah1, ah2, ah3, bh0[nt], bh1[nt]);
                    MMA(acc[mt][nt], ah0, ah1, ah2, ah3, bl0[nt], bl1[nt]);
                    MMA(acc[mt][nt], al0, al1, al2, al3, bh0[nt], bh1[nt]);
                }
            }
        }
        __syncthreads();
    }

    #pragma unroll
    for (int mt = 0; mt < 4; mt++) {
        int row = row0 + wm * 64 + mt * 16 + g;
        #pragma unroll
        for (int nt = 0; nt < 4; nt++) {
            int col = col0 + wn * 32 + nt * 8 + tg * 2;
            float2 v0 = make_float2(acc[mt][nt][0], acc[mt][nt][1]);
            float2 v1 = make_float2(acc[mt][nt][2], acc[mt][nt][3]);
            if (FLAGS & 1) {
                float bb0 = bias[col], bb1 = bias[col + 1];
                v0.x += bb0; v0.y += bb1; v1.x += bb0; v1.y += bb1;
            }
            if (FLAGS & 2) {
                v0.x = fmaxf(v0.x, 0.f); v0.y = fmaxf(v0.y, 0.f);
                v1.x = fmaxf(v1.x, 0.f); v1.y = fmaxf(v1.y, 0.f);
            }
            if (FLAGS & 16) {
                // transposed split output: vt[(b*8+h)*64 + d][key]
                bf16 h00 = __float2bfloat16_rn(v0.x);
                bf16 h01 = __float2bfloat16_rn(v0.y);
                bf16 h10 = __float2bfloat16_rn(v1.x);
                bf16 h11 = __float2bfloat16_rn(v1.y);
                CH[vtidx(row, col)]       = h00;
                CH[vtidx(row, col + 1)]   = h01;
                CH[vtidx(row + 8, col)]   = h10;
                CH[vtidx(row + 8, col+1)] = h11;
                CL[vtidx(row, col)]       = __float2bfloat16_rn(v0.x - __bfloat162float(h00));
                CL[vtidx(row, col + 1)]   = __float2bfloat16_rn(v0.y - __bfloat162float(h01));
                CL[vtidx(row + 8, col)]   = __float2bfloat16_rn(v1.x - __bfloat162float(h10));
                CL[vtidx(row + 8, col+1)] = __float2bfloat16_rn(v1.y - __bfloat162float(h11));
            } else if (FLAGS & 8) {
                u32 h0 = pkbf(v0.x, v0.y);
                float2 f0 = upbf(h0);
                u32 l0 = pkbf(v0.x - f0.x, v0.y - f0.y);
                u32 h1 = pkbf(v1.x, v1.y);
                float2 f1 = upbf(h1);
                u32 l1 = pkbf(v1.x - f1.x, v1.y - f1.y);
                *(u32*)&CH[(size_t)row * D + col] = h0;
                *(u32*)&CL[(size_t)row * D + col] = l0;
                *(u32*)&CH[(size_t)(row + 8) * D + col] = h1;
                *(u32*)&CL[(size_t)(row + 8) * D + col] = l1;
            } else {
                *(float2*)&C[(size_t)row * D + col] = v0;
                *(float2*)&C[(size_t)(row + 8) * D + col] = v1;
            }
        }
    }
}

// ---------------------------------------------------------------------------
// Tensor-core flash attention. CTA = (b,h,128q), 8 warps x 16q, key chunks 128.
// S and PV via m16n8k16 with split operands; P repacked in registers.
// Outputs split bf16 att (atth/attl).
// ---------------------------------------------------------------------------
#define AQS 72
#define AVS 136
__global__ void __launch_bounds__(256) attn_mma(
    const bf16* __restrict__ qh, const bf16* __restrict__ ql,
    const bf16* __restrict__ kh, const bf16* __restrict__ kl,
    const bf16* __restrict__ vth, const bf16* __restrict__ vtl,
    const int* __restrict__ xmask, const int* __restrict__ ymask,
    bf16* __restrict__ atth, bf16* __restrict__ attl)
{
    extern __shared__ char smraw[];
    bf16* Qh = (bf16*)smraw;              // [128][72]
    bf16* Ql = Qh + 128 * AQS;
    bf16* Kh = Ql + 128 * AQS;            // [128][72]
    bf16* Kl = Kh + 128 * AQS;
    bf16* Vh = Kl + 128 * AQS;            // [64][136]  (Vt: [d][key])
    bf16* Vl = Vh + 64 * AVS;
    float* sbias = (float*)(Vl + 64 * AVS);  // [128]

    const int bh = blockIdx.y, b = bh >> 3, h = bh & 7;
    const int n0 = blockIdx.x * 128;
    const int t = threadIdx.x, lane = t & 31, w = t >> 5;
    const int g = lane >> 2, tg = lane & 3;

    // Q fill (once)
    {
        int r = t >> 1, c0 = (t & 1) * 32;
        const bf16* sh = qh + (size_t)(b * NN + n0 + r) * D + h * DS + c0;
        const bf16* sl = ql + (size_t)(b * NN + n0 + r) * D + h * DS + c0;
        #pragma unroll
        for (int j = 0; j < 4; j++) {
            *(uint4*)&Qh[r * AQS + c0 + j * 8] = *(const uint4*)(sh + j * 8);
            *(uint4*)&Ql[r * AQS + c0 + j * 8] = *(const uint4*)(sl + j * 8);
        }
    }
    const int* ymb = ymask + b * MM;

    float mi0 = -3.0e38f, mi1 = -3.0e38f, li0 = 0.f, li1 = 0.f;
    float acco[8][4] = {};

    #pragma unroll 1
    for (int m0 = 0; m0 < MM; m0 += 128) {
        __syncthreads();
        {
            int r = t >> 1, c0 = (t & 1) * 32;
            const bf16* skh = kh + (size_t)(b * MM + m0 + r) * D + h * DS + c0;
            const bf16* skl = kl + (size_t)(b * MM + m0 + r) * D + h * DS + c0;
            #pragma unroll
            for (int j = 0; j < 4; j++) {
                *(uint4*)&Kh[r * AQS + c0 + j * 8] = *(const uint4*)(skh + j * 8);
                *(uint4*)&Kl[r * AQS + c0 + j * 8] = *(const uint4*)(skl + j * 8);
            }
            int d = t >> 2, vc = (t & 3) * 32;
            const bf16* svh = vth + ((size_t)bh * 64 + d) * MM + m0 + vc;
            const bf16* svl = vtl + ((size_t)bh * 64 + d) * MM + m0 + vc;
            #pragma unroll
            for (int j = 0; j < 4; j++) {
                *(uint4*)&Vh[d * AVS + vc + j * 8] = *(const uint4*)(svh + j * 8);
                *(uint4*)&Vl[d * AVS + vc + j * 8] = *(const uint4*)(svl + j * 8);
            }
            if (t < 128) sbias[t] = ymb[m0 + t] ? NEGV : 0.f;
        }
        __syncthreads();

        // ---- S = Q.K^T ----
        float accs[16][4];
        #pragma unroll
        for (int nt = 0; nt < 16; nt++)
            { accs[nt][0]=0.f; accs[nt][1]=0.f; accs[nt][2]=0.f; accs[nt][3]=0.f; }

        const int qr = w * 16 + g;
        #pragma unroll
        for (int ks = 0; ks < 4; ks++) {
            int kc = ks * 16 + tg * 2;
            u32 ah0 = *(const u32*)&Qh[qr * AQS + kc];
            u32 ah1 = *(const u32*)&Qh[(qr + 8) * AQS + kc];
            u32 ah2 = *(const u32*)&Qh[qr * AQS + kc + 8];
            u32 ah3 = *(const u32*)&Qh[(qr + 8) * AQS + kc + 8];
            u32 al0 = *(const u32*)&Ql[qr * AQS + kc];
            u32 al1 = *(const u32*)&Ql[(qr + 8) * AQS + kc];
            u32 al2 = *(const u32*)&Ql[qr * AQS + kc + 8];
            u32 al3 = *(const u32*)&Ql[(qr + 8) * AQS + kc + 8];
            #pragma unroll
            for (int nt = 0; nt < 16; nt++) {
                int kr = nt * 8 + g;
                u32 b0 = *(const u32*)&Kh[kr * AQS + kc];
                u32 b1 = *(const u32*)&Kh[kr * AQS + kc + 8];
                u32 c0 = *(const u32*)&Kl[kr * AQS + kc];
                u32 c1 = *(const u32*)&Kl[kr * AQS + kc + 8];
                MMA(accs[nt], ah0, ah1, ah2, ah3, b0, b1);
                MMA(accs[nt], ah0, ah1, ah2, ah3, c0, c1);
                MMA(accs[nt], al0, al1, al2, al3, b0, b1);
            }
        }

        // ---- key-mask bias + online softmax ----
        float mx0 = -3.0e38f, mx1 = -3.0e38f;
        #pragma unroll
        for (int nt = 0; nt < 16; nt++) {
            float2 sb = *(float2*)&sbias[nt * 8 + tg * 2];
            accs[nt][0] += sb.x; accs[nt][1] += sb.y;
            accs[nt][2] += sb.x; accs[nt][3] += sb.y;
            mx0 = fmaxf(mx0, fmaxf(accs[nt][0], accs[nt][1]));
            mx1 = fmaxf(mx1, fmaxf(accs[nt][2], accs[nt][3]));
        }
        mx0 = fmaxf(mx0, __shfl_xor_sync(0xffffffffu, mx0, 1));
        mx0 = fmaxf(mx0, __shfl_xor_sync(0xffffffffu, mx0, 2));
        mx1 = fmaxf(mx1, __shfl_xor_sync(0xffffffffu, mx1, 1));
        mx1 = fmaxf(mx1, __shfl_xor_sync(0xffffffffu, mx1, 2));
        float mn0 = fmaxf(mi0, mx0), mn1 = fmaxf(mi1, mx1);
        float cr0 = __expf(mi0 - mn0), cr1 = __expf(mi1 - mn1);
        float sum0 = 0.f, sum1 = 0.f;
        #pragma unroll
        for (int nt = 0; nt < 16; nt++) {
            accs[nt][0] = __expf(accs[nt][0] - mn0); sum0 += accs[nt][0];
            accs[nt][1] = __expf(accs[nt][1] - mn0); sum0 += accs[nt][1];
            accs[nt][2] = __expf(accs[nt][2] - mn1); sum1 += accs[nt][2];
            accs[nt][3] = __expf(accs[nt][3] - mn1); sum1 += accs[nt][3];
        }
        sum0 += __shfl_xor_sync(0xffffffffu, sum0, 1);
        sum0 += __shfl_xor_sync(0xffffffffu, sum0, 2);
        sum1 += __shfl_xor_sync(0xffffffffu, sum1, 1);
        sum1 += __shfl_xor_sync(0xffffffffu, sum1, 2);
        li0 = li0 * cr0 + sum0; mi0 = mn0;
        li1 = li1 * cr1 + sum1; mi1 = mn1;
        #pragma unroll
        for (int nt = 0; nt < 8; nt++) {
            acco[nt][0] *= cr0; acco[nt][1] *= cr0;
            acco[nt][2] *= cr1; acco[nt][3] *= cr1;
        }

        // ---- PV: P repacked in registers (split hi/lo) ----
        #pragma unroll
        for (int ks = 0; ks < 8; ks++) {
            int n0t = ks * 2, n1t = ks * 2 + 1;
            u32 ph0 = pkbf(accs[n0t][0], accs[n0t][1]);
            u32 ph1 = pkbf(accs[n0t][2], accs[n0t][3]);
            u32 ph2 = pkbf(accs[n1t][0], accs[n1t][1]);
            u32 ph3 = pkbf(accs[n1t][2], accs[n1t][3]);
            float2 f0 = upbf(ph0), f1 = upbf(ph1), f2 = upbf(ph2), f3 = upbf(ph3);
            u32 pl0 = pkbf(accs[n0t][0] - f0.x, accs[n0t][1] - f0.y);
            u32 pl1 = pkbf(accs[n0t][2] - f1.x, accs[n0t][3] - f1.y);
            u32 pl2 = pkbf(accs[n1t][0] - f2.x, accs[n1t][1] - f2.y);
            u32 pl3 = pkbf(accs[n1t][2] - f3.x, accs[n1t][3] - f3.y);
            int kc = ks * 16 + tg * 2;
            #pragma unroll
            for (int nt = 0; nt < 8; nt++) {
                int dr = nt * 8 + g;
                u32 b0 = *(const u32*)&Vh[dr * AVS + kc];
                u32 b1 = *(const u32*)&Vh[dr * AVS + kc + 8];
                u32 c0 = *(const u32*)&Vl[dr * AVS + kc];
                u32 c1 = *(const u32*)&Vl[dr * AVS + kc + 8];
                MMA(acco[nt], ph0, ph1, ph2, ph3, b0, b1);
                MMA(acco[nt], ph0, ph1, ph2, ph3, c0, c1);
                MMA(acco[nt], pl0, pl1, pl2, pl3, b0, b1);
            }
        }
    }

    // ---- writeout: split bf16 att, query-masked rows -> 0 ----
    const int* xmb = xmask + b * NN;
    int qr0 = n0 + w * 16 + g, qr1 = qr0 + 8;
    bool qm0 = xmb[qr0] != 0, qm1 = xmb[qr1] != 0;
    float inv0 = qm0 ? 0.f : 1.f / li0;
    float inv1 = qm1 ? 0.f : 1.f / li1;
    #pragma unroll
    for (int nt = 0; nt < 8; nt++) {
        int col = h * DS + nt * 8 + tg * 2;
        float o00 = acco[nt][0] * inv0, o01 = acco[nt][1] * inv0;
        float o10 = acco[nt][2] * inv1, o11 = acco[nt][3] * inv1;
        u32 h0 = pkbf(o00, o01);
        float2 f0 = upbf(h0);
        u32 l0 = pkbf(o00 - f0.x, o01 - f0.y);
        u32 h1 = pkbf(o10, o11);
        float2 f1 = upbf(h1);
        u32 l1 = pkbf(o10 - f1.x, o11 - f1.y);
        *(u32*)&atth[((size_t)b * NN + qr0) * D + col] = h0;
        *(u32*)&attl[((size_t)b * NN + qr0) * D + col] = l0;
        *(u32*)&atth[((size_t)b * NN + qr1) * D + col] = h1;
        *(u32*)&attl[((size_t)b * NN + qr1) * D + col] = l1;
    }
}
#define ATTN_SMEM (4*128*AQS*2 + 2*64*AVS*2 + 128*4)   // 109056

// ---------------------------------------------------------------------------
// out = LN(a' + b) * g + be; mode bit0: mask output rows; bit1: mask `a` rows;
// bit2: also write split bf16 (OH/OL).
// ---------------------------------------------------------------------------
__global__ void __launch_bounds__(128) add_ln_k(
    const float* __restrict__ a, const float* __restrict__ bsrc,
    const float* __restrict__ g, const float* __restrict__ be,
    const int* __restrict__ xmask, int mode,
    float* __restrict__ out, bf16* __restrict__ OH, bf16* __restrict__ OL)
{
    int row = blockIdx.x;
    int t = threadIdx.x;
    const float* ar = a + (size_t)row * D;
    const float* br = bsrc + (size_t)row * D;
    bool rowmask = xmask[row] != 0;
    bool maska = (mode & 2) && rowmask;

    float vals[4];
    float s = 0.f;
    #pragma unroll
    for (int i = 0; i < 4; i++) {
        float av = maska ? 0.f : ar[t + i * 128];
        vals[i] = av + br[t + i * 128];
        s += vals[i];
    }
    __shared__ float red[4];
    #pragma unroll
    for (int o = 16; o; o >>= 1) s += __shfl_xor_sync(0xffffffffu, s, o);
    if ((t & 31) == 0) red[t >> 5] = s;
    __syncthreads();
    float mu = (red[0] + red[1] + red[2] + red[3]) * (1.f / 512.f);

    float s2 = 0.f;
    #pragma unroll
    for (int i = 0; i < 4; i++) { float d = vals[i] - mu; s2 += d * d; }
    __syncthreads();
    #pragma unroll
    for (int o = 16; o; o >>= 1) s2 += __shfl_xor_sync(0xffffffffu, s2, o);
    if ((t & 31) == 0) red[t >> 5] = s2;
    __syncthreads();
    float inv = rsqrtf((red[0] + red[1] + red[2] + red[3]) * (1.f / 512.f) + 1e-5f);

    bool maskout = (mode & 1) && rowmask;
    #pragma unroll
    for (int i = 0; i < 4; i++) {
        int c = t + i * 128;
        float v = maskout ? 0.f : (vals[i] - mu) * inv * g[c] + be[c];
        out[(size_t)row * D + c] = v;
        if (mode & 4) {
            bf16 hb = __float2bfloat16_rn(v);
            OH[(size_t)row * D + c] = hb;
            OL[(size_t)row * D + c] = __float2bfloat16_rn(v - __bfloat162float(hb));
        }
    }
}

// ---------------------------------------------------------------------------
extern "C" void kernel_launch(void* const* d_in, const int* in_sizes, int n_in,
                              void* d_out, int out_size)
{
    const float* x  = (const float*)d_in[0];
    const float* y  = (const float*)d_in[1];
    const int* xm = (const int*)d_in[2];
    const int* ym = (const int*)d_in[3];
    const float* Wq = (const float*)d_in[4];
    const float* Wk = (const float*)d_in[5];
    const float* Wv = (const float*)d_in[6];
    const float* Wo = (const float*)d_in[7];
    const float* W1 = (const float*)d_in[8];
    const float* b1 = (const float*)d_in[9];
    const float* W2 = (const float*)d_in[10];
    const float* b2 = (const float*)d_in[11];
    const float* g1 = (const float*)d_in[12];
    const float* be1= (const float*)d_in[13];
    const float* g2 = (const float*)d_in[14];
    const float* be2= (const float*)d_in[15];
    float* out = (float*)d_out;

    float *t1, *t2, *ff;
    cudaGetSymbolAddress((void**)&t1, S_t1);
    cudaGetSymbolAddress((void**)&t2, S_t2);
    cudaGetSymbolAddress((void**)&ff, S_ff);
    bf16 *wh, *wl, *xh, *xl, *yh, *yl, *qh, *ql, *kh, *kl, *vth, *vtl;
    bf16 *ath, *atl, *t2h, *t2l, *rh, *rl;
    cudaGetSymbolAddress((void**)&wh,  S_WH);
    cudaGetSymbolAddress((void**)&wl,  S_WL);
    cudaGetSymbolAddress((void**)&xh,  S_XH);
    cudaGetSymbolAddress((void**)&xl,  S_XL);
    cudaGetSymbolAddress((void**)&yh,  S_YH);
    cudaGetSymbolAddress((void**)&yl,  S_YL);
    cudaGetSymbolAddress((void**)&qh,  S_QH);
    cudaGetSymbolAddress((void**)&ql,  S_QL);
    cudaGetSymbolAddress((void**)&kh,  S_KH);
    cudaGetSymbolAddress((void**)&kl,  S_KL);
    cudaGetSymbolAddress((void**)&vth, S_VTH);
    cudaGetSymbolAddress((void**)&vtl, S_VTL);
    cudaGetSymbolAddress((void**)&ath, S_ATH);
    cudaGetSymbolAddress((void**)&atl, S_ATL);
    cudaGetSymbolAddress((void**)&t2h, S_T2H);
    cudaGetSymbolAddress((void**)&t2l, S_T2L);
    cudaGetSymbolAddress((void**)&rh,  S_RH);
    cudaGetSymbolAddress((void**)&rl,  S_RL);

    cudaFuncSetAttribute(attn_mma, cudaFuncAttributeMaxDynamicSharedMemorySize,
                         ATTN_SMEM);

    // weight prep (one launch; SCALE folded into Wq)
    wsplit_all<<<6144, 256>>>(Wq, Wk, Wv, Wo, W1, W2, wh, wl);

    // input splits (masked)
    asplit_k<<<4096, 256>>>(x, xm, xh, xl);
    asplit_k<<<4096, 256>>>(y, ym, yh, yl);

    dim3 gg(4, 64);
    // q (scaled by SCALE via Wq), k: split out; v: transposed split out
    hgemm_k<8> <<<gg, 256>>>(xh, xl, wh + 0*(size_t)D*D, wl + 0*(size_t)D*D, nullptr, nullptr, qh, ql);
    hgemm_k<8> <<<gg, 256>>>(yh, yl, wh + 1*(size_t)D*D, wl + 1*(size_t)D*D, nullptr, nullptr, kh, kl);
    hgemm_k<16><<<gg, 256>>>(yh, yl, wh + 2*(size_t)D*D, wl + 2*(size_t)D*D, nullptr, nullptr, vth, vtl);

    dim3 ga(8, 64);
    attn_mma<<<ga, 256, ATTN_SMEM>>>(qh, ql, kh, kl, vth, vtl, xm, ym, ath, atl);

    hgemm_k<0><<<gg, 256>>>(ath, atl, wh + 3*(size_t)D*D, wl + 3*(size_t)D*D, nullptr, t1, nullptr, nullptr);
    add_ln_k<<<ROWS, 128>>>(x, t1, g1, be1, xm, 2 | 4, t2, t2h, t2l);
    hgemm_k<11><<<gg, 256>>>(t2h, t2l, wh + 4*(size_t)D*D, wl + 4*(size_t)D*D, b1, nullptr, rh, rl);
    hgemm_k<1><<<gg, 256>>>(rh, rl, wh + 5*(size_t)D*D, wl + 5*(size_t)D*D, b2, ff, nullptr, nullptr);
    add_ln_k<<<ROWS, 128>>>(t2, ff, g2, be2, xm, 1, out, nullptr, nullptr);
}

// round 13
// speedup vs baseline: 2.1536x; 1.0518x over previous
#include <cuda_runtime.h>
#include <cuda_bf16.h>
#include <math.h>
#include <stdint.h>

#define BB 8
#define NN 1024
#define MM 1024
#define D  512
#define HH 8
#define DS 64
#define ROWS (BB*NN)          // 8192
#define NEGV (-1e38f)
#define SCALE 0.04419417382415922f   // 1/sqrt(512)

typedef unsigned int u32;
typedef __nv_bfloat16 bf16;

// pack two f32 -> bf16x2 {lo, hi}
__device__ __forceinline__ u32 pkbf(float lo, float hi) {
    u32 r;
    asm("cvt.rn.bf16x2.f32 %0, %1, %2;" : "=r"(r) : "f"(hi), "f"(lo));
    return r;
}
__device__ __forceinline__ float2 upbf(u32 p) {
    __nv_bfloat162 b2 = *reinterpret_cast<__nv_bfloat162*>(&p);
    return __bfloat1622float2(b2);
}
__device__ __forceinline__ u32 smem_u32(const void* p) {
    u32 a;
    asm("{ .reg .u64 t; cvta.to.shared.u64 t, %1; cvt.u32.u64 %0, t; }" : "=r"(a) : "l"(p));
    return a;
}
__device__ __forceinline__ void cpa16(u32 s, const void* g) {
    asm volatile("cp.async.cg.shared.global [%0], [%1], 16;" :: "r"(s), "l"(g));
}
#define CPA_COMMIT() asm volatile("cp.async.commit_group;")
#define CPA_WAIT1()  asm volatile("cp.async.wait_group 1;")

// bf16x2 MMA: D(16x8 f32) += A(16x16) * B(16x8), row.col
#define MMA(d, a0,a1,a2,a3, b0,b1) \
    asm volatile("mma.sync.aligned.m16n8k16.row.col.f32.bf16.bf16.f32 " \
        "{%0,%1,%2,%3}, {%4,%5,%6,%7}, {%8,%9}, {%0,%1,%2,%3};" \
        : "+f"(d[0]),"+f"(d[1]),"+f"(d[2]),"+f"(d[3]) \
        : "r"(a0),"r"(a1),"r"(a2),"r"(a3),"r"(b0),"r"(b1))

// ---------------- scratch (device globals) ----------------
__device__ float S_t1 [ROWS*D];
__device__ float S_t2 [ROWS*D];
__device__ float S_ff [ROWS*D];
__device__ bf16 S_WH[6*D*D], S_WL[6*D*D];         // weights [n][k] split
__device__ bf16 S_XH[ROWS*D], S_XL[ROWS*D];
__device__ bf16 S_YH[ROWS*D], S_YL[ROWS*D];
__device__ bf16 S_QH[ROWS*D], S_QL[ROWS*D];
__device__ bf16 S_KH[ROWS*D], S_KL[ROWS*D];
__device__ bf16 S_VTH[ROWS*D], S_VTL[ROWS*D];     // [b*h][d][key]
__device__ bf16 S_ATH[ROWS*D], S_ATL[ROWS*D];
__device__ bf16 S_T2H[ROWS*D], S_T2L[ROWS*D];
__device__ bf16 S_RH[ROWS*D],  S_RL[ROWS*D];

// ---------------------------------------------------------------------------
// Fused weight prep: all 6 weights, transpose + bf16 split; Wq gets SCALE.
// ---------------------------------------------------------------------------
__global__ void __launch_bounds__(256) wsplit_all(
    const float* __restrict__ W0, const float* __restrict__ W1,
    const float* __restrict__ W2, const float* __restrict__ W3,
    const float* __restrict__ W4, const float* __restrict__ W5,
    bf16* __restrict__ WH, bf16* __restrict__ WL)
{
    int gi = blockIdx.x;
    int wi = gi >> 10;
    const float* W = (wi == 0) ? W0 : (wi == 1) ? W1 : (wi == 2) ? W2
                   : (wi == 3) ? W3 : (wi == 4) ? W4 : W5;
    float sc = (wi == 0) ? SCALE : 1.f;
    int idx = (gi & 1023) * 256 + threadIdx.x;
    int n = idx & 511, kk = idx >> 9;
    float w = W[(size_t)kk * D + n] * sc;
    bf16 h = __float2bfloat16_rn(w);
    bf16 l = __float2bfloat16_rn(w - __bfloat162float(h));
    WH[(size_t)wi * D * D + (size_t)n * D + kk] = h;
    WL[(size_t)wi * D * D + (size_t)n * D + kk] = l;
}

// ---------------------------------------------------------------------------
// Activation split (x, y only): bf16 hi/lo with row-mask zero.
// ---------------------------------------------------------------------------
__global__ void __launch_bounds__(256) asplit_k(
    const float* __restrict__ A, const int* __restrict__ mask,
    bf16* __restrict__ AHg, bf16* __restrict__ ALg)
{
    int i4 = blockIdx.x * 256 + threadIdx.x;   // ROWS*D/4
    int row = i4 >> 7;
    float4 f = ((const float4*)A)[i4];
    if (mask[row]) f = make_float4(0.f, 0.f, 0.f, 0.f);
    u32 h0 = pkbf(f.x, f.y), h1 = pkbf(f.z, f.w);
    float2 a = upbf(h0), b = upbf(h1);
    u32 l0 = pkbf(f.x - a.x, f.y - a.y), l1 = pkbf(f.z - b.x, f.w - b.y);
    uint2 hh = make_uint2(h0, h1), ll = make_uint2(l0, l1);
    *(uint2*)(AHg + (size_t)i4 * 4) = hh;
    *(uint2*)(ALg + (size_t)i4 * 4) = ll;
}

// ---------------------------------------------------------------------------
// bf16 tensor-core GEMM, split precision (Ah.Bh + Ah.Bl + Al.Bh).
// Tile 128x128, k-chunk 32, 8 warps 2x4, warp tile 64x32.
// 3-stage cp.async pipeline, one __syncthreads per chunk.
// FLAGS: bit0 +bias, bit1 relu, bit3(8) split bf16 out, bit4(16) vT split out.
// ---------------------------------------------------------------------------
#define HG_LD   40                  // smem row stride (elems)
#define HG_ARR  (128 * HG_LD)       // one array (elems)
#define HG_STG  (4 * HG_ARR)        // one stage: AH,AL,BH,BL (elems)
#define HG_SMEM (3 * HG_STG * 2)    // bytes = 122880

__device__ __forceinline__ size_t vtidx(int row, int col) {
    return (((size_t)(row >> 10) * 8 + (col >> 6)) * 64 + (col & 63)) * 1024
           + (row & 1023);
}

template<int FLAGS>
__global__ void __launch_bounds__(256) hgemm_k(
    const bf16* __restrict__ AHg, const bf16* __restrict__ ALg,
    const bf16* __restrict__ BHg, const bf16* __restrict__ BLg,
    const float* __restrict__ bias, float* __restrict__ C,
    bf16* __restrict__ CH, bf16* __restrict__ CL)
{
    extern __shared__ bf16 hs[];
    const u32 sbase = smem_u32(hs);
    const int t = threadIdx.x, lane = t & 31, wid = t >> 5;
    const int wm = wid >> 2, wn = wid & 3;
    const int g = lane >> 2, tg = lane & 3;
    const int row0 = blockIdx.y * 128, col0 = blockIdx.x * 128;
    const int lr = t >> 1, lc = (t & 1) * 16;

    const bf16* AHp = AHg + (size_t)(row0 + lr) * D + lc;
    const bf16* ALp = ALg + (size_t)(row0 + lr) * D + lc;
    const bf16* BHp = BHg + (size_t)(col0 + lr) * D + lc;
    const bf16* BLp = BLg + (size_t)(col0 + lr) * D + lc;
    const u32 soff = (u32)(lr * HG_LD + lc) * 2;   // byte offset within array

    auto issue = [&](int c) {
        u32 st = sbase + (u32)(c % 3) * (HG_STG * 2);
        const int ko = c * 32;
        cpa16(st + 0*HG_ARR*2 + soff,      AHp + ko);
        cpa16(st + 0*HG_ARR*2 + soff + 16, AHp + ko + 8);
        cpa16(st + 1*HG_ARR*2 + soff,      ALp + ko);
        cpa16(st + 1*HG_ARR*2 + soff + 16, ALp + ko + 8);
        cpa16(st + 2*HG_ARR*2 + soff,      BHp + ko);
        cpa16(st + 2*HG_ARR*2 + soff + 16, BHp + ko + 8);
        cpa16(st + 3*HG_ARR*2 + soff,      BLp + ko);
        cpa16(st + 3*HG_ARR*2 + soff + 16, BLp + ko + 8);
    };

    issue(0); CPA_COMMIT();
    issue(1); CPA_COMMIT();

    float acc[4][4][4] = {};

    #pragma unroll 1
    for (int c = 0; c < 16; c++) {
        CPA_WAIT1();
        __syncthreads();
        const bf16* AH = hs + (c % 3) * HG_STG;
        const bf16* AL = AH + HG_ARR;
        const bf16* BH = AL + HG_ARR;
        const bf16* BL = BH + HG_ARR;

        #pragma unroll
        for (int ks = 0; ks < 32; ks += 16) {
            u32 bh0[4], bh1[4], bl0[4], bl1[4];
            #pragma unroll
            for (int nt = 0; nt < 4; nt++) {
                int nr = wn * 32 + nt * 8 + g;
                bh0[nt] = *(const u32*)&BH[nr * HG_LD + ks + tg*2];
                bh1[nt] = *(const u32*)&BH[nr * HG_LD + ks + tg*2 + 8];
                bl0[nt] = *(const u32*)&BL[nr * HG_LD + ks + tg*2];
                bl1[nt] = *(const u32*)&BL[nr * HG_LD + ks + tg*2 + 8];
            }
            #pragma unroll
            for (int mt = 0; mt < 4; mt++) {
                int mr = wm * 64 + mt * 16 + g;
                u32 ah0 = *(const u32*)&AH[mr * HG_LD + ks + tg*2];
                u32 ah1 = *(const u32*)&AH[(mr + 8) * HG_LD + ks + tg*2];
                u32 ah2 = *(const u32*)&AH[mr * HG_LD + ks + tg*2 + 8];
                u32 ah3 = *(const u32*)&AH[(mr + 8) * HG_LD + ks + tg*2 + 8];
                u32 al0 = *(const u32*)&AL[mr * HG_LD + ks + tg*2];
                u32 al1 = *(const u32*)&AL[(mr + 8) * HG_LD + ks + tg*2];
                u32 al2 = *(const u32*)&AL[mr * HG_LD + ks + tg*2 + 8];
                u32 al3 = *(const u32*)&AL[(mr + 8) * HG_LD + ks + tg*2 + 8];
                // interleaved: dependent MMAs 4 apart
                #pragma unroll
                for (int nt = 0; nt < 4; nt++)
                    MMA(acc[mt][nt], ah0, ah1, ah2, ah3, bh0[nt], bh1[nt]);
                #pragma unroll
                for (int nt = 0; nt < 4; nt++)
                    MMA(acc[mt][nt], ah0, ah1, ah2, ah3, bl0[nt], bl1[nt]);
                #pragma unroll
                for (int nt = 0; nt < 4; nt++)
                    MMA(acc[mt][nt], al0, al1, al2, al3, bh0[nt], bh1[nt]);
            }
        }
        if (c + 2 < 16) issue(c + 2);
        CPA_COMMIT();
    }

    #pragma unroll
    for (int mt = 0; mt < 4; mt++) {
        int row = row0 + wm * 64 + mt * 16 + g;
        #pragma unroll
        for (int nt = 0; nt < 4; nt++) {
            int col = col0 + wn * 32 + nt * 8 + tg * 2;
            float2 v0 = make_float2(acc[mt][nt][0], acc[mt][nt][1]);
            float2 v1 = make_float2(acc[mt][nt][2], acc[mt][nt][3]);
            if (FLAGS & 1) {
                float bb0 = bias[col], bb1 = bias[col + 1];
                v0.x += bb0; v0.y += bb1; v1.x += bb0; v1.y += bb1;
            }
            if (FLAGS & 2) {
                v0.x = fmaxf(v0.x, 0.f); v0.y = fmaxf(v0.y, 0.f);
                v1.x = fmaxf(v1.x, 0.f); v1.y = fmaxf(v1.y, 0.f);
            }
            if (FLAGS & 16) {
                bf16 h00 = __float2bfloat16_rn(v0.x);
                bf16 h01 = __float2bfloat16_rn(v0.y);
                bf16 h10 = __float2bfloat16_rn(v1.x);
                bf16 h11 = __float2bfloat16_rn(v1.y);
                CH[vtidx(row, col)]       = h00;
                CH[vtidx(row, col + 1)]   = h01;
                CH[vtidx(row + 8, col)]   = h10;
                CH[vtidx(row + 8, col+1)] = h11;
                CL[vtidx(row, col)]       = __float2bfloat16_rn(v0.x - __bfloat162float(h00));
                CL[vtidx(row, col + 1)]   = __float2bfloat16_rn(v0.y - __bfloat162float(h01));
                CL[vtidx(row + 8, col)]   = __float2bfloat16_rn(v1.x - __bfloat162float(h10));
                CL[vtidx(row + 8, col+1)] = __float2bfloat16_rn(v1.y - __bfloat162float(h11));
            } else if (FLAGS & 8) {
                u32 h0 = pkbf(v0.x, v0.y);
                float2 f0 = upbf(h0);
                u32 l0 = pkbf(v0.x - f0.x, v0.y - f0.y);
                u32 h1 = pkbf(v1.x, v1.y);
                float2 f1 = upbf(h1);
                u32 l1 = pkbf(v1.x - f1.x, v1.y - f1.y);
                *(u32*)&CH[(size_t)row * D + col] = h0;
                *(u32*)&CL[(size_t)row * D + col] = l0;
                *(u32*)&CH[(size_t)(row + 8) * D + col] = h1;
                *(u32*)&CL[(size_t)(row + 8) * D + col] = l1;
            } else {
                *(float2*)&C[(size_t)row * D + col] = v0;
                *(float2*)&C[(size_t)(row + 8) * D + col] = v1;
            }
        }
    }
}

// ---------------------------------------------------------------------------
// Tensor-core flash attention. CTA = (b,h,128q), 8 warps x 16q, key chunks 128.
// S and PV via m16n8k16 with split operands; P repacked in registers.
// ---------------------------------------------------------------------------
#define AQS 72
#define AVS 136
__global__ void __launch_bounds__(256) attn_mma(
    const bf16* __restrict__ qh, const bf16* __restrict__ ql,
    const bf16* __restrict__ kh, const bf16* __restrict__ kl,
    const bf16* __restrict__ vth, const bf16* __restrict__ vtl,
    const int* __restrict__ xmask, const int* __restrict__ ymask,
    bf16* __restrict__ atth, bf16* __restrict__ attl)
{
    extern __shared__ char smraw[];
    bf16* Qh = (bf16*)smraw;              // [128][72]
    bf16* Ql = Qh + 128 * AQS;
    bf16* Kh = Ql + 128 * AQS;            // [128][72]
    bf16* Kl = Kh + 128 * AQS;
    bf16* Vh = Kl + 128 * AQS;            // [64][136]  (Vt: [d][key])
    bf16* Vl = Vh + 64 * AVS;
    float* sbias = (float*)(Vl + 64 * AVS);  // [128]

    const int bh = blockIdx.y, b = bh >> 3, h = bh & 7;
    const int n0 = blockIdx.x * 128;
    const int t = threadIdx.x, lane = t & 31, w = t >> 5;
    const int g = lane >> 2, tg = lane & 3;

    {
        int r = t >> 1, c0 = (t & 1) * 32;
        const bf16* sh = qh + (size_t)(b * NN + n0 + r) * D + h * DS + c0;
        const bf16* sl = ql + (size_t)(b * NN + n0 + r) * D + h * DS + c0;
        #pragma unroll
        for (int j = 0; j < 4; j++) {
            *(uint4*)&Qh[r * AQS + c0 + j * 8] = *(const uint4*)(sh + j * 8);
            *(uint4*)&Ql[r * AQS + c0 + j * 8] = *(const uint4*)(sl + j * 8);
        }
    }
    const int* ymb = ymask + b * MM;

    float mi0 = -3.0e38f, mi1 = -3.0e38f, li0 = 0.f, li1 = 0.f;
    float acco[8][4] = {};

    #pragma unroll 1
    for (int m0 = 0; m0 < MM; m0 += 128) {
        __syncthreads();
        {
            int r = t >> 1, c0 = (t & 1) * 32;
            const bf16* skh = kh + (size_t)(b * MM + m0 + r) * D + h * DS + c0;
            const bf16* skl = kl + (size_t)(b * MM + m0 + r) * D + h * DS + c0;
            #pragma unroll
            for (int j = 0; j < 4; j++) {
                *(uint4*)&Kh[r * AQS + c0 + j * 8] = *(const uint4*)(skh + j * 8);
                *(uint4*)&Kl[r * AQS + c0 + j * 8] = *(const uint4*)(skl + j * 8);
            }
            int d = t >> 2, vc = (t & 3) * 32;
            const bf16* svh = vth + ((size_t)bh * 64 + d) * MM + m0 + vc;
            const bf16* svl = vtl + ((size_t)bh * 64 + d) * MM + m0 + vc;
            #pragma unroll
            for (int j = 0; j < 4; j++) {
                *(uint4*)&Vh[d * AVS + vc + j * 8] = *(const uint4*)(svh + j * 8);
                *(uint4*)&Vl[d * AVS + vc + j * 8] = *(const uint4*)(svl + j * 8);
            }
            if (t < 128) sbias[t] = ymb[m0 + t] ? NEGV : 0.f;
        }
        __syncthreads();

        float accs[16][4];
        #pragma unroll
        for (int nt = 0; nt < 16; nt++)
            { accs[nt][0]=0.f; accs[nt][1]=0.f; accs[nt][2]=0.f; accs[nt][3]=0.f; }

        const int qr = w * 16 + g;
        #pragma unroll
        for (int ks = 0; ks < 4; ks++) {
            int kc = ks * 16 + tg * 2;
            u32 ah0 = *(const u32*)&Qh[qr * AQS + kc];
            u32 ah1 = *(const u32*)&Qh[(qr + 8) * AQS + kc];
            u32 ah2 = *(const u32*)&Qh[qr * AQS + kc + 8];
            u32 ah3 = *(const u32*)&Qh[(qr + 8) * AQS + kc + 8];
            u32 al0 = *(const u32*)&Ql[qr * AQS + kc];
            u32 al1 = *(const u32*)&Ql[(qr + 8) * AQS + kc];
            u32 al2 = *(const u32*)&Ql[qr * AQS + kc + 8];
            u32 al3 = *(const u32*)&Ql[(qr + 8) * AQS + kc + 8];
            #pragma unroll
            for (int nt = 0; nt < 16; nt++) {
                int kr = nt * 8 + g;
                u32 b0 = *(const u32*)&Kh[kr * AQS + kc];
                u32 b1 = *(const u32*)&Kh[kr * AQS + kc + 8];
                u32 c0 = *(const u32*)&Kl[kr * AQS + kc];
                u32 c1 = *(const u32*)&Kl[kr * AQS + kc + 8];
                MMA(accs[nt], ah0, ah1, ah2, ah3, b0, b1);
                MMA(accs[nt], ah0, ah1, ah2, ah3, c0, c1);
                MMA(accs[nt], al0, al1, al2, al3, b0, b1);
            }
        }

        float mx0 = -3.0e38f, mx1 = -3.0e38f;
        #pragma unroll
        for (int nt = 0; nt < 16; nt++) {
            float2 sb = *(float2*)&sbias[nt * 8 + tg * 2];
            accs[nt][0] += sb.x; accs[nt][1] += sb.y;
            accs[nt][2] += sb.x; accs[nt][3] += sb.y;
            mx0 = fmaxf(mx0, fmaxf(accs[nt][0], accs[nt][1]));
            mx1 = fmaxf(mx1, fmaxf(accs[nt][2], accs[nt][3]));
        }
        mx0 = fmaxf(mx0, __shfl_xor_sync(0xffffffffu, mx0, 1));
        mx0 = fmaxf(mx0, __shfl_xor_sync(0xffffffffu, mx0, 2));
        mx1 = fmaxf(mx1, __shfl_xor_sync(0xffffffffu, mx1, 1));
        mx1 = fmaxf(mx1, __shfl_xor_sync(0xffffffffu, mx1, 2));
        float mn0 = fmaxf(mi0, mx0), mn1 = fmaxf(mi1, mx1);
        float cr0 = __expf(mi0 - mn0), cr1 = __expf(mi1 - mn1);
        float sum0 = 0.f, sum1 = 0.f;
        #pragma unroll
        for (int nt = 0; nt < 16; nt++) {
            accs[nt][0] = __expf(accs[nt][0] - mn0); sum0 += accs[nt][0];
            accs[nt][1] = __expf(accs[nt][1] - mn0); sum0 += accs[nt][1];
            accs[nt][2] = __expf(accs[nt][2] - mn1); sum1 += accs[nt][2];
            accs[nt][3] = __expf(accs[nt][3] - mn1); sum1 += accs[nt][3];
        }
        sum0 += __shfl_xor_sync(0xffffffffu, sum0, 1);
        sum0 += __shfl_xor_sync(0xffffffffu, sum0, 2);
        sum1 += __shfl_xor_sync(0xffffffffu, sum1, 1);
        sum1 += __shfl_xor_sync(0xffffffffu, sum1, 2);
        li0 = li0 * cr0 + sum0; mi0 = mn0;
        li1 = li1 * cr1 + sum1; mi1 = mn1;
        #pragma unroll
        for (int nt = 0; nt < 8; nt++) {
            acco[nt][0] *= cr0; acco[nt][1] *= cr0;
            acco[nt][2] *= cr1; acco[nt][3] *= cr1;
        }

        #pragma unroll
        for (int ks = 0; ks < 8; ks++) {
            int n0t = ks * 2, n1t = ks * 2 + 1;
            u32 ph0 = pkbf(accs[n0t][0], accs[n0t][1]);
            u32 ph1 = pkbf(accs[n0t][2], accs[n0t][3]);
            u32 ph2 = pkbf(accs[n1t][0], accs[n1t][1]);
            u32 ph3 = pkbf(accs[n1t][2], accs[n1t][3]);
            float2 f0 = upbf(ph0), f1 = upbf(ph1), f2 = upbf(ph2), f3 = upbf(ph3);
            u32 pl0 = pkbf(accs[n0t][0] - f0.x, accs[n0t][1] - f0.y);
            u32 pl1 = pkbf(accs[n0t][2] - f1.x, accs[n0t][3] - f1.y);
            u32 pl2 = pkbf(accs[n1t][0] - f2.x, accs[n1t][1] - f2.y);
            u32 pl3 = pkbf(accs[n1t][2] - f3.x, accs[n1t][3] - f3.y);
            int kc = ks * 16 + tg * 2;
            #pragma unroll
            for (int nt = 0; nt < 8; nt++) {
                int dr = nt * 8 + g;
                u32 b0 = *(const u32*)&Vh[dr * AVS + kc];
                u32 b1 = *(const u32*)&Vh[dr * AVS + kc + 8];
                u32 c0 = *(const u32*)&Vl[dr * AVS + kc];
                u32 c1 = *(const u32*)&Vl[dr * AVS + kc + 8];
                MMA(acco[nt], ph0, ph1, ph2, ph3, b0, b1);
                MMA(acco[nt], ph0, ph1, ph2, ph3, c0, c1);
                MMA(acco[nt], pl0, pl1, pl2, pl3, b0, b1);
            }
        }
    }

    const int* xmb = xmask + b * NN;
    int qr0 = n0 + w * 16 + g, qr1 = qr0 + 8;
    bool qm0 = xmb[qr0] != 0, qm1 = xmb[qr1] != 0;
    float inv0 = qm0 ? 0.f : 1.f / li0;
    float inv1 = qm1 ? 0.f : 1.f / li1;
    #pragma unroll
    for (int nt = 0; nt < 8; nt++) {
        int col = h * DS + nt * 8 + tg * 2;
        float o00 = acco[nt][0] * inv0, o01 = acco[nt][1] * inv0;
        float o10 = acco[nt][2] * inv1, o11 = acco[nt][3] * inv1;
        u32 h0 = pkbf(o00, o01);
        float2 f0 = upbf(h0);
        u32 l0 = pkbf(o00 - f0.x, o01 - f0.y);
        u32 h1 = pkbf(o10, o11);
        float2 f1 = upbf(h1);
        u32 l1 = pkbf(o10 - f1.x, o11 - f1.y);
        *(u32*)&atth[((size_t)b * NN + qr0) * D + col] = h0;
        *(u32*)&attl[((size_t)b * NN + qr0) * D + col] = l0;
        *(u32*)&atth[((size_t)b * NN + qr1) * D + col] = h1;
        *(u32*)&attl[((size_t)b * NN + qr1) * D + col] = l1;
    }
}
#define ATTN_SMEM (4*128*AQS*2 + 2*64*AVS*2 + 128*4)   // 109056

// ---------------------------------------------------------------------------
// out = LN(a' + b) * g + be; mode bit0: mask output rows; bit1: mask `a` rows;
// bit2: also write split bf16 (OH/OL).
// ---------------------------------------------------------------------------
__global__ void __launch_bounds__(128) add_ln_k(
    const float* __restrict__ a, const float* __restrict__ bsrc,
    const float* __restrict__ g, const float* __restrict__ be,
    const int* __restrict__ xmask, int mode,
    float* __restrict__ out, bf16* __restrict__ OH, bf16* __restrict__ OL)
{
    int row = blockIdx.x;
    int t = threadIdx.x;
    const float* ar = a + (size_t)row * D;
    const float* br = bsrc + (size_t)row * D;
    bool rowmask = xmask[row] != 0;
    bool maska = (mode & 2) && rowmask;

    float vals[4];
    float s = 0.f;
    #pragma unroll
    for (int i = 0; i < 4; i++) {
        float av = maska ? 0.f : ar[t + i * 128];
        vals[i] = av + br[t + i * 128];
        s += vals[i];
    }
    __shared__ float red[4];
    #pragma unroll
    for (int o = 16; o; o >>= 1) s += __shfl_xor_sync(0xffffffffu, s, o);
    if ((t & 31) == 0) red[t >> 5] = s;
    __syncthreads();
    float mu = (red[0] + red[1] + red[2] + red[3]) * (1.f / 512.f);

    float s2 = 0.f;
    #pragma unroll
    for (int i = 0; i < 4; i++) { float d = vals[i] - mu; s2 += d * d; }
    __syncthreads();
    #pragma unroll
    for (int o = 16; o; o >>= 1) s2 += __shfl_xor_sync(0xffffffffu, s2, o);
    if ((t & 31) == 0) red[t >> 5] = s2;
    __syncthreads();
    float inv = rsqrtf((red[0] + red[1] + red[2] + red[3]) * (1.f / 512.f) + 1e-5f);

    bool maskout = (mode & 1) && rowmask;
    #pragma unroll
    for (int i = 0; i < 4; i++) {
        int c = t + i * 128;
        float v = maskout ? 0.f : (vals[i] - mu) * inv * g[c] + be[c];
        out[(size_t)row * D + c] = v;
        if (mode & 4) {
            bf16 hb = __float2bfloat16_rn(v);
            OH[(size_t)row * D + c] = hb;
            OL[(size_t)row * D + c] = __float2bfloat16_rn(v - __bfloat162float(hb));
        }
    }
}

// ---------------------------------------------------------------------------
extern "C" void kernel_launch(void* const* d_in, const int* in_sizes, int n_in,
                              void* d_out, int out_size)
{
    const float* x  = (const float*)d_in[0];
    const float* y  = (const float*)d_in[1];
    const int* xm = (const int*)d_in[2];
    const int* ym = (const int*)d_in[3];
    const float* Wq = (const float*)d_in[4];
    const float* Wk = (const float*)d_in[5];
    const float* Wv = (const float*)d_in[6];
    const float* Wo = (const float*)d_in[7];
    const float* W1 = (const float*)d_in[8];
    const float* b1 = (const float*)d_in[9];
    const float* W2 = (const float*)d_in[10];
    const float* b2 = (const float*)d_in[11];
    const float* g1 = (const float*)d_in[12];
    const float* be1= (const float*)d_in[13];
    const float* g2 = (const float*)d_in[14];
    const float* be2= (const float*)d_in[15];
    float* out = (float*)d_out;

    float *t1, *t2, *ff;
    cudaGetSymbolAddress((void**)&t1, S_t1);
    cudaGetSymbolAddress((void**)&t2, S_t2);
    cudaGetSymbolAddress((void**)&ff, S_ff);
    bf16 *wh, *wl, *xh, *xl, *yh, *yl, *qh, *ql, *kh, *kl, *vth, *vtl;
    bf16 *ath, *atl, *t2h, *t2l, *rh, *rl;
    cudaGetSymbolAddress((void**)&wh,  S_WH);
    cudaGetSymbolAddress((void**)&wl,  S_WL);
    cudaGetSymbolAddress((void**)&xh,  S_XH);
    cudaGetSymbolAddress((void**)&xl,  S_XL);
    cudaGetSymbolAddress((void**)&yh,  S_YH);
    cudaGetSymbolAddress((void**)&yl,  S_YL);
    cudaGetSymbolAddress((void**)&qh,  S_QH);
    cudaGetSymbolAddress((void**)&ql,  S_QL);
    cudaGetSymbolAddress((void**)&kh,  S_KH);
    cudaGetSymbolAddress((void**)&kl,  S_KL);
    cudaGetSymbolAddress((void**)&vth, S_VTH);
    cudaGetSymbolAddress((void**)&vtl, S_VTL);
    cudaGetSymbolAddress((void**)&ath, S_ATH);
    cudaGetSymbolAddress((void**)&atl, S_ATL);
    cudaGetSymbolAddress((void**)&t2h, S_T2H);
    cudaGetSymbolAddress((void**)&t2l, S_T2L);
    cudaGetSymbolAddress((void**)&rh,  S_RH);
    cudaGetSymbolAddress((void**)&rl,  S_RL);

    cudaFuncSetAttribute(attn_mma, cudaFuncAttributeMaxDynamicSharedMemorySize,
                         ATTN_SMEM);
    cudaFuncSetAttribute(hgemm_k<0>,  cudaFuncAttributeMaxDynamicSharedMemorySize, HG_SMEM);
    cudaFuncSetAttribute(hgemm_k<1>,  cudaFuncAttributeMaxDynamicSharedMemorySize, HG_SMEM);
    cudaFuncSetAttribute(hgemm_k<8>,  cudaFuncAttributeMaxDynamicSharedMemorySize, HG_SMEM);
    cudaFuncSetAttribute(hgemm_k<11>, cudaFuncAttributeMaxDynamicSharedMemorySize, HG_SMEM);
    cudaFuncSetAttribute(hgemm_k<16>, cudaFuncAttributeMaxDynamicSharedMemorySize, HG_SMEM);

    wsplit_all<<<6144, 256>>>(Wq, Wk, Wv, Wo, W1, W2, wh, wl);
    asplit_k<<<4096, 256>>>(x, xm, xh, xl);
    asplit_k<<<4096, 256>>>(y, ym, yh, yl);

    dim3 gg(4, 64);
    hgemm_k<8> <<<gg, 256, HG_SMEM>>>(xh, xl, wh + 0*(size_t)D*D, wl + 0*(size_t)D*D, nullptr, nullptr, qh, ql);
    hgemm_k<8> <<<gg, 256, HG_SMEM>>>(yh, yl, wh + 1*(size_t)D*D, wl + 1*(size_t)D*D, nullptr, nullptr, kh, kl);
    hgemm_k<16><<<gg, 256, HG_SMEM>>>(yh, yl, wh + 2*(size_t)D*D, wl + 2*(size_t)D*D, nullptr, nullptr, vth, vtl);

    dim3 ga(8, 64);
    attn_mma<<<ga, 256, ATTN_SMEM>>>(qh, ql, kh, kl, vth, vtl, xm, ym, ath, atl);

    hgemm_k<0><<<gg, 256, HG_SMEM>>>(ath, atl, wh + 3*(size_t)D*D, wl + 3*(size_t)D*D, nullptr, t1, nullptr, nullptr);
    add_ln_k<<<ROWS, 128>>>(x, t1, g1, be1, xm, 2 | 4, t2, t2h, t2l);
    hgemm_k<11><<<gg, 256, HG_SMEM>>>(t2h, t2l, wh + 4*(size_t)D*D, wl + 4*(size_t)D*D, b1, nullptr, rh, rl);
    hgemm_k<1><<<gg, 256, HG_SMEM>>>(rh, rl, wh + 5*(size_t)D*D, wl + 5*(size_t)D*D, b2, ff, nullptr, nullptr);
    add_ln_k<<<ROWS, 128>>>(t2, ff, g2, be2, xm, 1, out, nullptr, nullptr);
}

// round 14
// speedup vs baseline: 2.1895x; 1.0167x over previous
#include <cuda_runtime.h>
#include <cuda_bf16.h>
#include <math.h>
#include <stdint.h>

#define BB 8
#define NN 1024
#define MM 1024
#define D  512
#define HH 8
#define DS 64
#define ROWS (BB*NN)          // 8192
#define NEGV (-1e38f)
#define SCALE 0.04419417382415922f   // 1/sqrt(512)

typedef unsigned int u32;
typedef __nv_bfloat16 bf16;

// pack two f32 -> bf16x2 {lo, hi}
__device__ __forceinline__ u32 pkbf(float lo, float hi) {
    u32 r;
    asm("cvt.rn.bf16x2.f32 %0, %1, %2;" : "=r"(r) : "f"(hi), "f"(lo));
    return r;
}
__device__ __forceinline__ float2 upbf(u32 p) {
    __nv_bfloat162 b2 = *reinterpret_cast<__nv_bfloat162*>(&p);
    return __bfloat1622float2(b2);
}
__device__ __forceinline__ u32 smem_u32(const void* p) {
    u32 a;
    asm("{ .reg .u64 t; cvta.to.shared.u64 t, %1; cvt.u32.u64 %0, t; }" : "=r"(a) : "l"(p));
    return a;
}
__device__ __forceinline__ void cpa16(u32 s, const void* g) {
    asm volatile("cp.async.cg.shared.global [%0], [%1], 16;" :: "r"(s), "l"(g));
}
#define CPA_COMMIT() asm volatile("cp.async.commit_group;")
#define CPA_WAIT1()  asm volatile("cp.async.wait_group 1;")

// bf16x2 MMA: D(16x8 f32) += A(16x16) * B(16x8), row.col
#define MMA(d, a0,a1,a2,a3, b0,b1) \
    asm volatile("mma.sync.aligned.m16n8k16.row.col.f32.bf16.bf16.f32 " \
        "{%0,%1,%2,%3}, {%4,%5,%6,%7}, {%8,%9}, {%0,%1,%2,%3};" \
        : "+f"(d[0]),"+f"(d[1]),"+f"(d[2]),"+f"(d[3]) \
        : "r"(a0),"r"(a1),"r"(a2),"r"(a3),"r"(b0),"r"(b1))

// ---------------- scratch (device globals) ----------------
__device__ float S_t1 [ROWS*D];
__device__ float S_t2 [ROWS*D];
__device__ float S_ff [ROWS*D];
__device__ bf16 S_WH[6*D*D], S_WL[6*D*D];         // weights [n][k] split
__device__ bf16 S_XH[ROWS*D], S_XL[ROWS*D];
__device__ bf16 S_YH[ROWS*D], S_YL[ROWS*D];
__device__ bf16 S_QH[ROWS*D], S_QL[ROWS*D];
__device__ bf16 S_KH[ROWS*D], S_KL[ROWS*D];
__device__ bf16 S_VTH[ROWS*D], S_VTL[ROWS*D];     // [b*h][d][key]
__device__ bf16 S_ATH[ROWS*D], S_ATL[ROWS*D];
__device__ bf16 S_T2H[ROWS*D], S_T2L[ROWS*D];
__device__ bf16 S_RH[ROWS*D],  S_RL[ROWS*D];

// ---------------------------------------------------------------------------
// Fused weight prep: all 6 weights, transpose + bf16 split; Wq gets SCALE.
// ---------------------------------------------------------------------------
__global__ void __launch_bounds__(256) wsplit_all(
    const float* __restrict__ W0, const float* __restrict__ W1,
    const float* __restrict__ W2, const float* __restrict__ W3,
    const float* __restrict__ W4, const float* __restrict__ W5,
    bf16* __restrict__ WH, bf16* __restrict__ WL)
{
    int gi = blockIdx.x;
    int wi = gi >> 10;
    const float* W = (wi == 0) ? W0 : (wi == 1) ? W1 : (wi == 2) ? W2
                   : (wi == 3) ? W3 : (wi == 4) ? W4 : W5;
    float sc = (wi == 0) ? SCALE : 1.f;
    int idx = (gi & 1023) * 256 + threadIdx.x;
    int n = idx & 511, kk = idx >> 9;
    float w = W[(size_t)kk * D + n] * sc;
    bf16 h = __float2bfloat16_rn(w);
    bf16 l = __float2bfloat16_rn(w - __bfloat162float(h));
    WH[(size_t)wi * D * D + (size_t)n * D + kk] = h;
    WL[(size_t)wi * D * D + (size_t)n * D + kk] = l;
}

// ---------------------------------------------------------------------------
// Activation split (x, y only): bf16 hi/lo with row-mask zero.
// ---------------------------------------------------------------------------
__global__ void __launch_bounds__(256) asplit_k(
    const float* __restrict__ A, const int* __restrict__ mask,
    bf16* __restrict__ AHg, bf16* __restrict__ ALg)
{
    int i4 = blockIdx.x * 256 + threadIdx.x;   // ROWS*D/4
    int row = i4 >> 7;
    float4 f = ((const float4*)A)[i4];
    if (mask[row]) f = make_float4(0.f, 0.f, 0.f, 0.f);
    u32 h0 = pkbf(f.x, f.y), h1 = pkbf(f.z, f.w);
    float2 a = upbf(h0), b = upbf(h1);
    u32 l0 = pkbf(f.x - a.x, f.y - a.y), l1 = pkbf(f.z - b.x, f.w - b.y);
    uint2 hh = make_uint2(h0, h1), ll = make_uint2(l0, l1);
    *(uint2*)(AHg + (size_t)i4 * 4) = hh;
    *(uint2*)(ALg + (size_t)i4 * 4) = ll;
}

// ---------------------------------------------------------------------------
// bf16 tensor-core GEMM, split precision (Ah.Bh + Ah.Bl + Al.Bh).
// Tile 128x128, k-chunk 16, 8 warps 2x4, warp tile 64x32.
// 3-stage cp.async pipeline (24.6 KB/stage -> 2 CTAs/SM).
// FLAGS: bit0 +bias, bit1 relu, bit3(8) split bf16 out, bit4(16) vT split out.
// ---------------------------------------------------------------------------
#define HG_LD   24                  // smem row stride (elems), k=16 + pad 8
#define HG_ARR  (128 * HG_LD)       // one array (elems)
#define HG_STG  (4 * HG_ARR)        // one stage: AH,AL,BH,BL (elems)
#define HG_SMEM (3 * HG_STG * 2)    // bytes = 73728

__device__ __forceinline__ size_t vtidx(int row, int col) {
    return (((size_t)(row >> 10) * 8 + (col >> 6)) * 64 + (col & 63)) * 1024
           + (row & 1023);
}

template<int FLAGS>
__global__ void __launch_bounds__(256, 2) hgemm_k(
    const bf16* __restrict__ AHg, const bf16* __restrict__ ALg,
    const bf16* __restrict__ BHg, const bf16* __restrict__ BLg,
    const float* __restrict__ bias, float* __restrict__ C,
    bf16* __restrict__ CH, bf16* __restrict__ CL)
{
    extern __shared__ bf16 hs[];
    const u32 sbase = smem_u32(hs);
    const int t = threadIdx.x, lane = t & 31, wid = t >> 5;
    const int wm = wid >> 2, wn = wid & 3;
    const int g = lane >> 2, tg = lane & 3;
    const int row0 = blockIdx.y * 128, col0 = blockIdx.x * 128;
    const int lr = t >> 1, lc = (t & 1) * 8;      // 2 thr/row, 8 elems (16B) each

    const bf16* AHp = AHg + (size_t)(row0 + lr) * D + lc;
    const bf16* ALp = ALg + (size_t)(row0 + lr) * D + lc;
    const bf16* BHp = BHg + (size_t)(col0 + lr) * D + lc;
    const bf16* BLp = BLg + (size_t)(col0 + lr) * D + lc;
    const u32 soff = (u32)(lr * HG_LD + lc) * 2;   // byte offset within array

    auto issue = [&](int c) {
        u32 st = sbase + (u32)(c % 3) * (HG_STG * 2);
        const int ko = c * 16;
        cpa16(st + 0*HG_ARR*2 + soff, AHp + ko);
        cpa16(st + 1*HG_ARR*2 + soff, ALp + ko);
        cpa16(st + 2*HG_ARR*2 + soff, BHp + ko);
        cpa16(st + 3*HG_ARR*2 + soff, BLp + ko);
    };

    issue(0); CPA_COMMIT();
    issue(1); CPA_COMMIT();

    float acc[4][4][4] = {};

    #pragma unroll 1
    for (int c = 0; c < 32; c++) {
        CPA_WAIT1();
        __syncthreads();
        const bf16* AH = hs + (c % 3) * HG_STG;
        const bf16* AL = AH + HG_ARR;
        const bf16* BH = AL + HG_ARR;
        const bf16* BL = BH + HG_ARR;

        u32 bh0[4], bh1[4], bl0[4], bl1[4];
        #pragma unroll
        for (int nt = 0; nt < 4; nt++) {
            int nr = wn * 32 + nt * 8 + g;
            bh0[nt] = *(const u32*)&BH[nr * HG_LD + tg*2];
            bh1[nt] = *(const u32*)&BH[nr * HG_LD + tg*2 + 8];
            bl0[nt] = *(const u32*)&BL[nr * HG_LD + tg*2];
            bl1[nt] = *(const u32*)&BL[nr * HG_LD + tg*2 + 8];
        }
        #pragma unroll
        for (int mt = 0; mt < 4; mt++) {
            int mr = wm * 64 + mt * 16 + g;
            u32 ah0 = *(const u32*)&AH[mr * HG_LD + tg*2];
            u32 ah1 = *(const u32*)&AH[(mr + 8) * HG_LD + tg*2];
            u32 ah2 = *(const u32*)&AH[mr * HG_LD + tg*2 + 8];
            u32 ah3 = *(const u32*)&AH[(mr + 8) * HG_LD + tg*2 + 8];
            u32 al0 = *(const u32*)&AL[mr * HG_LD + tg*2];
            u32 al1 = *(const u32*)&AL[(mr + 8) * HG_LD + tg*2];
            u32 al2 = *(const u32*)&AL[mr * HG_LD + tg*2 + 8];
            u32 al3 = *(const u32*)&AL[(mr + 8) * HG_LD + tg*2 + 8];
            // interleaved: dependent MMAs 4 apart
            #pragma unroll
            for (int nt = 0; nt < 4; nt++)
                MMA(acc[mt][nt], ah0, ah1, ah2, ah3, bh0[nt], bh1[nt]);
            #pragma unroll
            for (int nt = 0; nt < 4; nt++)
                MMA(acc[mt][nt], ah0, ah1, ah2, ah3, bl0[nt], bl1[nt]);
            #pragma unroll
            for (int nt = 0; nt < 4; nt++)
                MMA(acc[mt][nt], al0, al1, al2, al3, bh0[nt], bh1[nt]);
        }
        if (c + 2 < 32) issue(c + 2);
        CPA_COMMIT();
    }

    #pragma unroll
    for (int mt = 0; mt < 4; mt++) {
        int row = row0 + wm * 64 + mt * 16 + g;
        #pragma unroll
        for (int nt = 0; nt < 4; nt++) {
            int col = col0 + wn * 32 + nt * 8 + tg * 2;
            float2 v0 = make_float2(acc[mt][nt][0], acc[mt][nt][1]);
            float2 v1 = make_float2(acc[mt][nt][2], acc[mt][nt][3]);
            if (FLAGS & 1) {
                float bb0 = bias[col], bb1 = bias[col + 1];
                v0.x += bb0; v0.y += bb1; v1.x += bb0; v1.y += bb1;
            }
            if (FLAGS & 2) {
                v0.x = fmaxf(v0.x, 0.f); v0.y = fmaxf(v0.y, 0.f);
                v1.x = fmaxf(v1.x, 0.f); v1.y = fmaxf(v1.y, 0.f);
            }
            if (FLAGS & 16) {
                bf16 h00 = __float2bfloat16_rn(v0.x);
                bf16 h01 = __float2bfloat16_rn(v0.y);
                bf16 h10 = __float2bfloat16_rn(v1.x);
                bf16 h11 = __float2bfloat16_rn(v1.y);
                CH[vtidx(row, col)]       = h00;
                CH[vtidx(row, col + 1)]   = h01;
                CH[vtidx(row + 8, col)]   = h10;
                CH[vtidx(row + 8, col+1)] = h11;
                CL[vtidx(row, col)]       = __float2bfloat16_rn(v0.x - __bfloat162float(h00));
                CL[vtidx(row, col + 1)]   = __float2bfloat16_rn(v0.y - __bfloat162float(h01));
                CL[vtidx(row + 8, col)]   = __float2bfloat16_rn(v1.x - __bfloat162float(h10));
                CL[vtidx(row + 8, col+1)] = __float2bfloat16_rn(v1.y - __bfloat162float(h11));
            } else if (FLAGS & 8) {
                u32 h0 = pkbf(v0.x, v0.y);
                float2 f0 = upbf(h0);
                u32 l0 = pkbf(v0.x - f0.x, v0.y - f0.y);
                u32 h1 = pkbf(v1.x, v1.y);
                float2 f1 = upbf(h1);
                u32 l1 = pkbf(v1.x - f1.x, v1.y - f1.y);
                *(u32*)&CH[(size_t)row * D + col] = h0;
                *(u32*)&CL[(size_t)row * D + col] = l0;
                *(u32*)&CH[(size_t)(row + 8) * D + col] = h1;
                *(u32*)&CL[(size_t)(row + 8) * D + col] = l1;
            } else {
                *(float2*)&C[(size_t)row * D + col] = v0;
                *(float2*)&C[(size_t)(row + 8) * D + col] = v1;
            }
        }
    }
}

// ---------------------------------------------------------------------------
// Tensor-core flash attention. CTA = (b,h,128q), 8 warps x 16q, key chunks 128.
// S and PV via m16n8k16 with split operands; P repacked in registers.
// ---------------------------------------------------------------------------
#define AQS 72
#define AVS 136
__global__ void __launch_bounds__(256) attn_mma(
    const bf16* __restrict__ qh, const bf16* __restrict__ ql,
    const bf16* __restrict__ kh, const bf16* __restrict__ kl,
    const bf16* __restrict__ vth, const bf16* __restrict__ vtl,
    const int* __restrict__ xmask, const int* __restrict__ ymask,
    bf16* __restrict__ atth, bf16* __restrict__ attl)
{
    extern __shared__ char smraw[];
    bf16* Qh = (bf16*)smraw;              // [128][72]
    bf16* Ql = Qh + 128 * AQS;
    bf16* Kh = Ql + 128 * AQS;            // [128][72]
    bf16* Kl = Kh + 128 * AQS;
    bf16* Vh = Kl + 128 * AQS;            // [64][136]  (Vt: [d][key])
    bf16* Vl = Vh + 64 * AVS;
    float* sbias = (float*)(Vl + 64 * AVS);  // [128]

    const int bh = blockIdx.y, b = bh >> 3, h = bh & 7;
    const int n0 = blockIdx.x * 128;
    const int t = threadIdx.x, lane = t & 31, w = t >> 5;
    const int g = lane >> 2, tg = lane & 3;

    {
        int r = t >> 1, c0 = (t & 1) * 32;
        const bf16* sh = qh + (size_t)(b * NN + n0 + r) * D + h * DS + c0;
        const bf16* sl = ql + (size_t)(b * NN + n0 + r) * D + h * DS + c0;
        #pragma unroll
        for (int j = 0; j < 4; j++) {
            *(uint4*)&Qh[r * AQS + c0 + j * 8] = *(const uint4*)(sh + j * 8);
            *(uint4*)&Ql[r * AQS + c0 + j * 8] = *(const uint4*)(sl + j * 8);
        }
    }
    const int* ymb = ymask + b * MM;

    float mi0 = -3.0e38f, mi1 = -3.0e38f, li0 = 0.f, li1 = 0.f;
    float acco[8][4] = {};

    #pragma unroll 1
    for (int m0 = 0; m0 < MM; m0 += 128) {
        __syncthreads();
        {
            int r = t >> 1, c0 = (t & 1) * 32;
            const bf16* skh = kh + (size_t)(b * MM + m0 + r) * D + h * DS + c0;
            const bf16* skl = kl + (size_t)(b * MM + m0 + r) * D + h * DS + c0;
            #pragma unroll
            for (int j = 0; j < 4; j++) {
                *(uint4*)&Kh[r * AQS + c0 + j * 8] = *(const uint4*)(skh + j * 8);
                *(uint4*)&Kl[r * AQS + c0 + j * 8] = *(const uint4*)(skl + j * 8);
            }
            int d = t >> 2, vc = (t & 3) * 32;
            const bf16* svh = vth + ((size_t)bh * 64 + d) * MM + m0 + vc;
            const bf16* svl = vtl + ((size_t)bh * 64 + d) * MM + m0 + vc;
            #pragma unroll
            for (int j = 0; j < 4; j++) {
                *(uint4*)&Vh[d * AVS + vc + j * 8] = *(const uint4*)(svh + j * 8);
                *(uint4*)&Vl[d * AVS + vc + j * 8] = *(const uint4*)(svl + j * 8);
            }
            if (t < 128) sbias[t] = ymb[m0 + t] ? NEGV : 0.f;
        }
        __syncthreads();

        float accs[16][4];
        #pragma unroll
        for (int nt = 0; nt < 16; nt++)
            { accs[nt][0]=0.f; accs[nt][1]=0.f; accs[nt][2]=0.f; accs[nt][3]=0.f; }

        const int qr = w * 16 + g;
        #pragma unroll
        for (int ks = 0; ks < 4; ks++) {
            int kc = ks * 16 + tg * 2;
            u32 ah0 = *(const u32*)&Qh[qr * AQS + kc];
            u32 ah1 = *(const u32*)&Qh[(qr + 8) * AQS + kc];
            u32 ah2 = *(const u32*)&Qh[qr * AQS + kc + 8];
            u32 ah3 = *(const u32*)&Qh[(qr + 8) * AQS + kc + 8];
            u32 al0 = *(const u32*)&Ql[qr * AQS + kc];
            u32 al1 = *(const u32*)&Ql[(qr + 8) * AQS + kc];
            u32 al2 = *(const u32*)&Ql[qr * AQS + kc + 8];
            u32 al3 = *(const u32*)&Ql[(qr + 8) * AQS + kc + 8];
            #pragma unroll
            for (int nt = 0; nt < 16; nt++) {
                int kr = nt * 8 + g;
                u32 b0 = *(const u32*)&Kh[kr * AQS + kc];
                u32 b1 = *(const u32*)&Kh[kr * AQS + kc + 8];
                u32 c0 = *(const u32*)&Kl[kr * AQS + kc];
                u32 c1 = *(const u32*)&Kl[kr * AQS + kc + 8];
                MMA(accs[nt], ah0, ah1, ah2, ah3, b0, b1);
                MMA(accs[nt], ah0, ah1, ah2, ah3, c0, c1);
                MMA(accs[nt], al0, al1, al2, al3, b0, b1);
            }
        }

        float mx0 = -3.0e38f, mx1 = -3.0e38f;
        #pragma unroll
        for (int nt = 0; nt < 16; nt++) {
            float2 sb = *(float2*)&sbias[nt * 8 + tg * 2];
            accs[nt][0] += sb.x; accs[nt][1] += sb.y;
            accs[nt][2] += sb.x; accs[nt][3] += sb.y;
            mx0 = fmaxf(mx0, fmaxf(accs[nt][0], accs[nt][1]));
            mx1 = fmaxf(mx1, fmaxf(accs[nt][2], accs[nt][3]));
        }
        mx0 = fmaxf(mx0, __shfl_xor_sync(0xffffffffu, mx0, 1));
        mx0 = fmaxf(mx0, __shfl_xor_sync(0xffffffffu, mx0, 2));
        mx1 = fmaxf(mx1, __shfl_xor_sync(0xffffffffu, mx1, 1));
        mx1 = fmaxf(mx1, __shfl_xor_sync(0xffffffffu, mx1, 2));
        float mn0 = fmaxf(mi0, mx0), mn1 = fmaxf(mi1, mx1);
        float cr0 = __expf(mi0 - mn0), cr1 = __expf(mi1 - mn1);
        float sum0 = 0.f, sum1 = 0.f;
        #pragma unroll
        for (int nt = 0; nt < 16; nt++) {
            accs[nt][0] = __expf(accs[nt][0] - mn0); sum0 += accs[nt][0];
            accs[nt][1] = __expf(accs[nt][1] - mn0); sum0 += accs[nt][1];
            accs[nt][2] = __expf(accs[nt][2] - mn1); sum1 += accs[nt][2];
            accs[nt][3] = __expf(accs[nt][3] - mn1); sum1 += accs[nt][3];
        }
        sum0 += __shfl_xor_sync(0xffffffffu, sum0, 1);
        sum0 += __shfl_xor_sync(0xffffffffu, sum0, 2);
        sum1 += __shfl_xor_sync(0xffffffffu, sum1, 1);
        sum1 += __shfl_xor_sync(0xffffffffu, sum1, 2);
        li0 = li0 * cr0 + sum0; mi0 = mn0;
        li1 = li1 * cr1 + sum1; mi1 = mn1;
        #pragma unroll
        for (int nt = 0; nt < 8; nt++) {
            acco[nt][0] *= cr0; acco[nt][1] *= cr0;
            acco[nt][2] *= cr1; acco[nt][3] *= cr1;
        }

        #pragma unroll
        for (int ks = 0; ks < 8; ks++) {
            int n0t = ks * 2, n1t = ks * 2 + 1;
            u32 ph0 = pkbf(accs[n0t][0], accs[n0t][1]);
            u32 ph1 = pkbf(accs[n0t][2], accs[n0t][3]);
            u32 ph2 = pkbf(accs[n1t][0], accs[n1t][1]);
            u32 ph3 = pkbf(accs[n1t][2], accs[n1t][3]);
            float2 f0 = upbf(ph0), f1 = upbf(ph1), f2 = upbf(ph2), f3 = upbf(ph3);
            u32 pl0 = pkbf(accs[n0t][0] - f0.x, accs[n0t][1] - f0.y);
            u32 pl1 = pkbf(accs[n0t][2] - f1.x, accs[n0t][3] - f1.y);
            u32 pl2 = pkbf(accs[n1t][0] - f2.x, accs[n1t][1] - f2.y);
            u32 pl3 = pkbf(accs[n1t][2] - f3.x, accs[n1t][3] - f3.y);
            int kc = ks * 16 + tg * 2;
            #pragma unroll
            for (int nt = 0; nt < 8; nt++) {
                int dr = nt * 8 + g;
                u32 b0 = *(const u32*)&Vh[dr * AVS + kc];
                u32 b1 = *(const u32*)&Vh[dr * AVS + kc + 8];
                u32 c0 = *(const u32*)&Vl[dr * AVS + kc];
                u32 c1 = *(const u32*)&Vl[dr * AVS + kc + 8];
                MMA(acco[nt], ph0, ph1, ph2, ph3, b0, b1);
                MMA(acco[nt], ph0, ph1, ph2, ph3, c0, c1);
                MMA(acco[nt], pl0, pl1, pl2, pl3, b0, b1);
            }
        }
    }

    const int* xmb = xmask + b * NN;
    int qr0 = n0 + w * 16 + g, qr1 = qr0 + 8;
    bool qm0 = xmb[qr0] != 0, qm1 = xmb[qr1] != 0;
    float inv0 = qm0 ? 0.f : 1.f / li0;
    float inv1 = qm1 ? 0.f : 1.f / li1;
    #pragma unroll
    for (int nt = 0; nt < 8; nt++) {
        int col = h * DS + nt * 8 + tg * 2;
        float o00 = acco[nt][0] * inv0, o01 = acco[nt][1] * inv0;
        float o10 = acco[nt][2] * inv1, o11 = acco[nt][3] * inv1;
        u32 h0 = pkbf(o00, o01);
        float2 f0 = upbf(h0);
        u32 l0 = pkbf(o00 - f0.x, o01 - f0.y);
        u32 h1 = pkbf(o10, o11);
        float2 f1 = upbf(h1);
        u32 l1 = pkbf(o10 - f1.x, o11 - f1.y);
        *(u32*)&atth[((size_t)b * NN + qr0) * D + col] = h0;
        *(u32*)&attl[((size_t)b * NN + qr0) * D + col] = l0;
        *(u32*)&atth[((size_t)b * NN + qr1) * D + col] = h1;
        *(u32*)&attl[((size_t)b * NN + qr1) * D + col] = l1;
    }
}
#define ATTN_SMEM (4*128*AQS*2 + 2*64*AVS*2 + 128*4)   // 109056

// ---------------------------------------------------------------------------
// out = LN(a' + b) * g + be; mode bit0: mask output rows; bit1: mask `a` rows;
// bit2: also write split bf16 (OH/OL).
// ---------------------------------------------------------------------------
__global__ void __launch_bounds__(128) add_ln_k(
    const float* __restrict__ a, const float* __restrict__ bsrc,
    const float* __restrict__ g, const float* __restrict__ be,
    const int* __restrict__ xmask, int mode,
    float* __restrict__ out, bf16* __restrict__ OH, bf16* __restrict__ OL)
{
    int row = blockIdx.x;
    int t = threadIdx.x;
    const float* ar = a + (size_t)row * D;
    const float* br = bsrc + (size_t)row * D;
    bool rowmask = xmask[row] != 0;
    bool maska = (mode & 2) && rowmask;

    float vals[4];
    float s = 0.f;
    #pragma unroll
    for (int i = 0; i < 4; i++) {
        float av = maska ? 0.f : ar[t + i * 128];
        vals[i] = av + br[t + i * 128];
        s += vals[i];
    }
    __shared__ float red[4];
    #pragma unroll
    for (int o = 16; o; o >>= 1) s += __shfl_xor_sync(0xffffffffu, s, o);
    if ((t & 31) == 0) red[t >> 5] = s;
    __syncthreads();
    float mu = (red[0] + red[1] + red[2] + red[3]) * (1.f / 512.f);

    float s2 = 0.f;
    #pragma unroll
    for (int i = 0; i < 4; i++) { float d = vals[i] - mu; s2 += d * d; }
    __syncthreads();
    #pragma unroll
    for (int o = 16; o; o >>= 1) s2 += __shfl_xor_sync(0xffffffffu, s2, o);
    if ((t & 31) == 0) red[t >> 5] = s2;
    __syncthreads();
    float inv = rsqrtf((red[0] + red[1] + red[2] + red[3]) * (1.f / 512.f) + 1e-5f);

    bool maskout = (mode & 1) && rowmask;
    #pragma unroll
    for (int i = 0; i < 4; i++) {
        int c = t + i * 128;
        float v = maskout ? 0.f : (vals[i] - mu) * inv * g[c] + be[c];
        out[(size_t)row * D + c] = v;
        if (mode & 4) {
            bf16 hb = __float2bfloat16_rn(v);
            OH[(size_t)row * D + c] = hb;
            OL[(size_t)row * D + c] = __float2bfloat16_rn(v - __bfloat162float(hb));
        }
    }
}

// ---------------------------------------------------------------------------
extern "C" void kernel_launch(void* const* d_in, const int* in_sizes, int n_in,
                              void* d_out, int out_size)
{
    const float* x  = (const float*)d_in[0];
    const float* y  = (const float*)d_in[1];
    const int* xm = (const int*)d_in[2];
    const int* ym = (const int*)d_in[3];
    const float* Wq = (const float*)d_in[4];
    const float* Wk = (const float*)d_in[5];
    const float* Wv = (const float*)d_in[6];
    const float* Wo = (const float*)d_in[7];
    const float* W1 = (const float*)d_in[8];
    const float* b1 = (const float*)d_in[9];
    const float* W2 = (const float*)d_in[10];
    const float* b2 = (const float*)d_in[11];
    const float* g1 = (const float*)d_in[12];
    const float* be1= (const float*)d_in[13];
    const float* g2 = (const float*)d_in[14];
    const float* be2= (const float*)d_in[15];
    float* out = (float*)d_out;

    float *t1, *t2, *ff;
    cudaGetSymbolAddress((void**)&t1, S_t1);
    cudaGetSymbolAddress((void**)&t2, S_t2);
    cudaGetSymbolAddress((void**)&ff, S_ff);
    bf16 *wh, *wl, *xh, *xl, *yh, *yl, *qh, *ql, *kh, *kl, *vth, *vtl;
    bf16 *ath, *atl, *t2h, *t2l, *rh, *rl;
    cudaGetSymbolAddress((void**)&wh,  S_WH);
    cudaGetSymbolAddress((void**)&wl,  S_WL);
    cudaGetSymbolAddress((void**)&xh,  S_XH);
    cudaGetSymbolAddress((void**)&xl,  S_XL);
    cudaGetSymbolAddress((void**)&yh,  S_YH);
    cudaGetSymbolAddress((void**)&yl,  S_YL);
    cudaGetSymbolAddress((void**)&qh,  S_QH);
    cudaGetSymbolAddress((void**)&ql,  S_QL);
    cudaGetSymbolAddress((void**)&kh,  S_KH);
    cudaGetSymbolAddress((void**)&kl,  S_KL);
    cudaGetSymbolAddress((void**)&vth, S_VTH);
    cudaGetSymbolAddress((void**)&vtl, S_VTL);
    cudaGetSymbolAddress((void**)&ath, S_ATH);
    cudaGetSymbolAddress((void**)&atl, S_ATL);
    cudaGetSymbolAddress((void**)&t2h, S_T2H);
    cudaGetSymbolAddress((void**)&t2l, S_T2L);
    cudaGetSymbolAddress((void**)&rh,  S_RH);
    cudaGetSymbolAddress((void**)&rl,  S_RL);

    cudaFuncSetAttribute(attn_mma, cudaFuncAttributeMaxDynamicSharedMemorySize,
                         ATTN_SMEM);
    cudaFuncSetAttribute(hgemm_k<0>,  cudaFuncAttributeMaxDynamicSharedMemorySize, HG_SMEM);
    cudaFuncSetAttribute(hgemm_k<1>,  cudaFuncAttributeMaxDynamicSharedMemorySize, HG_SMEM);
    cudaFuncSetAttribute(hgemm_k<8>,  cudaFuncAttributeMaxDynamicSharedMemorySize, HG_SMEM);
    cudaFuncSetAttribute(hgemm_k<11>, cudaFuncAttributeMaxDynamicSharedMemorySize, HG_SMEM);
    cudaFuncSetAttribute(hgemm_k<16>, cudaFuncAttributeMaxDynamicSharedMemorySize, HG_SMEM);

    wsplit_all<<<6144, 256>>>(Wq, Wk, Wv, Wo, W1, W2, wh, wl);
    asplit_k<<<4096, 256>>>(x, xm, xh, xl);
    asplit_k<<<4096, 256>>>(y, ym, yh, yl);

    dim3 gg(4, 64);
    hgemm_k<8> <<<gg, 256, HG_SMEM>>>(xh, xl, wh + 0*(size_t)D*D, wl + 0*(size_t)D*D, nullptr, nullptr, qh, ql);
    hgemm_k<8> <<<gg, 256, HG_SMEM>>>(yh, yl, wh + 1*(size_t)D*D, wl + 1*(size_t)D*D, nullptr, nullptr, kh, kl);
    hgemm_k<16><<<gg, 256, HG_SMEM>>>(yh, yl, wh + 2*(size_t)D*D, wl + 2*(size_t)D*D, nullptr, nullptr, vth, vtl);

    dim3 ga(8, 64);
    attn_mma<<<ga, 256, ATTN_SMEM>>>(qh, ql, kh, kl, vth, vtl, xm, ym, ath, atl);

    hgemm_k<0><<<gg, 256, HG_SMEM>>>(ath, atl, wh + 3*(size_t)D*D, wl + 3*(size_t)D*D, nullptr, t1, nullptr, nullptr);
    add_ln_k<<<ROWS, 128>>>(x, t1, g1, be1, xm, 2 | 4, t2, t2h, t2l);
    hgemm_k<11><<<gg, 256, HG_SMEM>>>(t2h, t2l, wh + 4*(size_t)D*D, wl + 4*(size_t)D*D, b1, nullptr, rh, rl);
    hgemm_k<1><<<gg, 256, HG_SMEM>>>(rh, rl, wh + 5*(size_t)D*D, wl + 5*(size_t)D*D, b2, ff, nullptr, nullptr);
    add_ln_k<<<ROWS, 128>>>(t2, ff, g2, be2, xm, 1, out, nullptr, nullptr);
}

// round 16
// speedup vs baseline: 2.3657x; 1.0805x over previous
#include <cuda_runtime.h>
#include <cuda_bf16.h>
#include <math.h>
#include <stdint.h>

#define BB 8
#define NN 1024
#define MM 1024
#define D  512
#define HH 8
#define DS 64
#define ROWS (BB*NN)          // 8192
#define NEGV (-1e38f)
#define SCALE 0.04419417382415922f   // 1/sqrt(512)

typedef unsigned int u32;
typedef __nv_bfloat16 bf16;

// pack two f32 -> bf16x2 {lo, hi}
__device__ __forceinline__ u32 pkbf(float lo, float hi) {
    u32 r;
    asm("cvt.rn.bf16x2.f32 %0, %1, %2;" : "=r"(r) : "f"(hi), "f"(lo));
    return r;
}
__device__ __forceinline__ float2 upbf(u32 p) {
    __nv_bfloat162 b2 = *reinterpret_cast<__nv_bfloat162*>(&p);
    return __bfloat1622float2(b2);
}
__device__ __forceinline__ u32 smem_u32(const void* p) {
    u32 a;
    asm("{ .reg .u64 t; cvta.to.shared.u64 t, %1; cvt.u32.u64 %0, t; }" : "=r"(a) : "l"(p));
    return a;
}
__device__ __forceinline__ void cpa16(u32 s, const void* g) {
    asm volatile("cp.async.cg.shared.global [%0], [%1], 16;" :: "r"(s), "l"(g));
}
#define CPA_COMMIT() asm volatile("cp.async.commit_group;")
#define CPA_WAIT1()  asm volatile("cp.async.wait_group 1;")

// bf16x2 MMA: D(16x8 f32) += A(16x16) * B(16x8), row.col
#define MMA(d, a0,a1,a2,a3, b0,b1) \
    asm volatile("mma.sync.aligned.m16n8k16.row.col.f32.bf16.bf16.f32 " \
        "{%0,%1,%2,%3}, {%4,%5,%6,%7}, {%8,%9}, {%0,%1,%2,%3};" \
        : "+f"(d[0]),"+f"(d[1]),"+f"(d[2]),"+f"(d[3]) \
        : "r"(a0),"r"(a1),"r"(a2),"r"(a3),"r"(b0),"r"(b1))

// ---------------- scratch (device globals) ----------------
__device__ float S_t1 [ROWS*D];
__device__ float S_t2 [ROWS*D];
__device__ float S_ff [ROWS*D];
__device__ bf16 S_WH[6*D*D], S_WL[6*D*D];         // weights [n][k] split
__device__ bf16 S_XH[ROWS*D], S_XL[ROWS*D];
__device__ bf16 S_YH[ROWS*D], S_YL[ROWS*D];
__device__ bf16 S_QH[ROWS*D], S_QL[ROWS*D];
__device__ bf16 S_KH[ROWS*D], S_KL[ROWS*D];
__device__ bf16 S_VTH[ROWS*D], S_VTL[ROWS*D];     // [b*h][d][key]
__device__ bf16 S_ATH[ROWS*D], S_ATL[ROWS*D];
__device__ bf16 S_T2H[ROWS*D], S_T2L[ROWS*D];
__device__ bf16 S_RH[ROWS*D],  S_RL[ROWS*D];

// ---------------------------------------------------------------------------
// Fused weight prep: all 6 weights, transpose + bf16 split; Wq gets SCALE.
// ---------------------------------------------------------------------------
__global__ void __launch_bounds__(256) wsplit_all(
    const float* __restrict__ W0, const float* __restrict__ W1,
    const float* __restrict__ W2, const float* __restrict__ W3,
    const float* __restrict__ W4, const float* __restrict__ W5,
    bf16* __restrict__ WH, bf16* __restrict__ WL)
{
    int gi = blockIdx.x;
    int wi = gi >> 10;
    const float* W = (wi == 0) ? W0 : (wi == 1) ? W1 : (wi == 2) ? W2
                   : (wi == 3) ? W3 : (wi == 4) ? W4 : W5;
    float sc = (wi == 0) ? SCALE : 1.f;
    int idx = (gi & 1023) * 256 + threadIdx.x;
    int n = idx & 511, kk = idx >> 9;
    float w = W[(size_t)kk * D + n] * sc;
    bf16 h = __float2bfloat16_rn(w);
    bf16 l = __float2bfloat16_rn(w - __bfloat162float(h));
    WH[(size_t)wi * D * D + (size_t)n * D + kk] = h;
    WL[(size_t)wi * D * D + (size_t)n * D + kk] = l;
}

// ---------------------------------------------------------------------------
// Activation split (x, y only): bf16 hi/lo with row-mask zero.
// ---------------------------------------------------------------------------
__global__ void __launch_bounds__(256) asplit_k(
    const float* __restrict__ A, const int* __restrict__ mask,
    bf16* __restrict__ AHg, bf16* __restrict__ ALg)
{
    int i4 = blockIdx.x * 256 + threadIdx.x;   // ROWS*D/4
    int row = i4 >> 7;
    float4 f = ((const float4*)A)[i4];
    if (mask[row]) f = make_float4(0.f, 0.f, 0.f, 0.f);
    u32 h0 = pkbf(f.x, f.y), h1 = pkbf(f.z, f.w);
    float2 a = upbf(h0), b = upbf(h1);
    u32 l0 = pkbf(f.x - a.x, f.y - a.y), l1 = pkbf(f.z - b.x, f.w - b.y);
    uint2 hh = make_uint2(h0, h1), ll = make_uint2(l0, l1);
    *(uint2*)(AHg + (size_t)i4 * 4) = hh;
    *(uint2*)(ALg + (size_t)i4 * 4) = ll;
}

// ---------------------------------------------------------------------------
// bf16 tensor-core GEMM, split precision (Ah.Bh + Ah.Bl + Al.Bh).
// Tile 128x128, k-chunk 32, 8 warps 2x4, warp tile 64x32.
// 3-stage cp.async pipeline, 32 KB/stage -> 2 CTAs/SM, 16 barriers total.
// Smem rows are 64 B with 16B-chunk XOR swizzle (chunk ^= (row>>1)&3):
// cp.async dsts stay 16B-aligned, fragment LDS conflict-free.
// FLAGS: bit0 +bias, bit1 relu, bit3(8) split bf16 out, bit4(16) vT split out.
// ---------------------------------------------------------------------------
#define HG_ARRB  8192                 // one array: 128 rows * 64 B
#define HG_STGB  (4 * HG_ARRB)        // one stage: AH,AL,BH,BL = 32768 B
#define HG_SMEM  (3 * HG_STGB)        // 98304 B

// swizzled byte offset of element e (0..31) in row r of a [128][32] bf16 array
__device__ __forceinline__ u32 sws(int r, int e) {
    int ch = e >> 3;
    return (u32)(r * 64 + (((ch ^ ((r >> 1) & 3)) << 4) | ((e & 7) << 1)));
}

__device__ __forceinline__ size_t vtidx(int row, int col) {
    return (((size_t)(row >> 10) * 8 + (col >> 6)) * 64 + (col & 63)) * 1024
           + (row & 1023);
}

template<int FLAGS>
__global__ void __launch_bounds__(256, 2) hgemm_k(
    const bf16* __restrict__ AHg, const bf16* __restrict__ ALg,
    const bf16* __restrict__ BHg, const bf16* __restrict__ BLg,
    const float* __restrict__ bias, float* __restrict__ C,
    bf16* __restrict__ CH, bf16* __restrict__ CL)
{
    extern __shared__ char hs[];
    const u32 sbase = smem_u32(hs);
    const int t = threadIdx.x, lane = t & 31, wid = t >> 5;
    const int wm = wid >> 2, wn = wid & 3;
    const int g = lane >> 2, tg = lane & 3;
    const int row0 = blockIdx.y * 128, col0 = blockIdx.x * 128;
    const int lr = t >> 1, lc = (t & 1) * 16;     // 2 thr/row, 16 elems each

    const bf16* AHp = AHg + (size_t)(row0 + lr) * D + lc;
    const bf16* ALp = ALg + (size_t)(row0 + lr) * D + lc;
    const bf16* BHp = BHg + (size_t)(col0 + lr) * D + lc;
    const bf16* BLp = BLg + (size_t)(col0 + lr) * D + lc;
    // swizzled dst offsets for this thread's two 16B chunks (loop-invariant)
    const int ci0 = 2 * (t & 1), ci1 = ci0 + 1;
    const u32 sw0 = (u32)(lr * 64) + (u32)(((ci0 ^ ((lr >> 1) & 3)) << 4));
    const u32 sw1 = (u32)(lr * 64) + (u32)(((ci1 ^ ((lr >> 1) & 3)) << 4));

    auto issue = [&](int c) {
        u32 st = sbase + (u32)(c % 3) * HG_STGB;
        const int ko = c * 32;
        cpa16(st + 0*HG_ARRB + sw0, AHp + ko);
        cpa16(st + 0*HG_ARRB + sw1, AHp + ko + 8);
        cpa16(st + 1*HG_ARRB + sw0, ALp + ko);
        cpa16(st + 1*HG_ARRB + sw1, ALp + ko + 8);
        cpa16(st + 2*HG_ARRB + sw0, BHp + ko);
        cpa16(st + 2*HG_ARRB + sw1, BHp + ko + 8);
        cpa16(st + 3*HG_ARRB + sw0, BLp + ko);
        cpa16(st + 3*HG_ARRB + sw1, BLp + ko + 8);
    };

    issue(0); CPA_COMMIT();
    issue(1); CPA_COMMIT();

    float acc[4][4][4] = {};

    #pragma unroll 1
    for (int c = 0; c < 16; c++) {
        CPA_WAIT1();
        __syncthreads();
        const char* AH = hs + (c % 3) * HG_STGB;
        const char* AL = AH + HG_ARRB;
        const char* BH = AL + HG_ARRB;
        const char* BL = BH + HG_ARRB;

        #pragma unroll
        for (int ks = 0; ks < 32; ks += 16) {
            const int e0 = ks + tg * 2, e1 = e0 + 8;
            u32 bh0[4], bh1[4], bl0[4], bl1[4];
            #pragma unroll
            for (int nt = 0; nt < 4; nt++) {
                int nr = wn * 32 + nt * 8 + g;
                bh0[nt] = *(const u32*)(BH + sws(nr, e0));
                bh1[nt] = *(const u32*)(BH + sws(nr, e1));
                bl0[nt] = *(const u32*)(BL + sws(nr, e0));
                bl1[nt] = *(const u32*)(BL + sws(nr, e1));
            }
            #pragma unroll
            for (int mt = 0; mt < 4; mt++) {
                int mr = wm * 64 + mt * 16 + g;
                u32 ah0 = *(const u32*)(AH + sws(mr, e0));
                u32 ah1 = *(const u32*)(AH + sws(mr + 8, e0));
                u32 ah2 = *(const u32*)(AH + sws(mr, e1));
                u32 ah3 = *(const u32*)(AH + sws(mr + 8, e1));
                u32 al0 = *(const u32*)(AL + sws(mr, e0));
                u32 al1 = *(const u32*)(AL + sws(mr + 8, e0));
                u32 al2 = *(const u32*)(AL + sws(mr, e1));
                u32 al3 = *(const u32*)(AL + sws(mr + 8, e1));
                // interleaved: dependent MMAs 4 apart
                #pragma unroll
                for (int nt = 0; nt < 4; nt++)
                    MMA(acc[mt][nt], ah0, ah1, ah2, ah3, bh0[nt], bh1[nt]);
                #pragma unroll
                for (int nt = 0; nt < 4; nt++)
                    MMA(acc[mt][nt], ah0, ah1, ah2, ah3, bl0[nt], bl1[nt]);
                #pragma unroll
                for (int nt = 0; nt < 4; nt++)
                    MMA(acc[mt][nt], al0, al1, al2, al3, bh0[nt], bh1[nt]);
            }
        }
        if (c + 2 < 16) issue(c + 2);
        CPA_COMMIT();
    }

    #pragma unroll
    for (int mt = 0; mt < 4; mt++) {
        int row = row0 + wm * 64 + mt * 16 + g;
        #pragma unroll
        for (int nt = 0; nt < 4; nt++) {
            int col = col0 + wn * 32 + nt * 8 + tg * 2;
            float2 v0 = make_float2(acc[mt][nt][0], acc[mt][nt][1]);
            float2 v1 = make_float2(acc[mt][nt][2], acc[mt][nt][3]);
            if (FLAGS & 1) {
                float bb0 = bias[col], bb1 = bias[col + 1];
                v0.x += bb0; v0.y += bb1; v1.x += bb0; v1.y += bb1;
            }
            if (FLAGS & 2) {
                v0.x = fmaxf(v0.x, 0.f); v0.y = fmaxf(v0.y, 0.f);
                v1.x = fmaxf(v1.x, 0.f); v1.y = fmaxf(v1.y, 0.f);
            }
            if (FLAGS & 16) {
                bf16 h00 = __float2bfloat16_rn(v0.x);
                bf16 h01 = __float2bfloat16_rn(v0.y);
                bf16 h10 = __float2bfloat16_rn(v1.x);
                bf16 h11 = __float2bfloat16_rn(v1.y);
                CH[vtidx(row, col)]       = h00;
                CH[vtidx(row, col + 1)]   = h01;
                CH[vtidx(row + 8, col)]   = h10;
                CH[vtidx(row + 8, col+1)] = h11;
                CL[vtidx(row, col)]       = __float2bfloat16_rn(v0.x - __bfloat162float(h00));
                CL[vtidx(row, col + 1)]   = __float2bfloat16_rn(v0.y - __bfloat162float(h01));
                CL[vtidx(row + 8, col)]   = __float2bfloat16_rn(v1.x - __bfloat162float(h10));
                CL[vtidx(row + 8, col+1)] = __float2bfloat16_rn(v1.y - __bfloat162float(h11));
            } else if (FLAGS & 8) {
                u32 h0 = pkbf(v0.x, v0.y);
                float2 f0 = upbf(h0);
                u32 l0 = pkbf(v0.x - f0.x, v0.y - f0.y);
                u32 h1 = pkbf(v1.x, v1.y);
                float2 f1 = upbf(h1);
                u32 l1 = pkbf(v1.x - f1.x, v1.y - f1.y);
                *(u32*)&CH[(size_t)row * D + col] = h0;
                *(u32*)&CL[(size_t)row * D + col] = l0;
                *(u32*)&CH[(size_t)(row + 8) * D + col] = h1;
                *(u32*)&CL[(size_t)(row + 8) * D + col] = l1;
            } else {
                *(float2*)&C[(size_t)row * D + col] = v0;
                *(float2*)&C[(size_t)(row + 8) * D + col] = v1;
            }
        }
    }
}

// ---------------------------------------------------------------------------
// Tensor-core flash attention. CTA = (b,h,128q), 8 warps x 16q, key chunks 128.
// S and PV via m16n8k16 with split operands; P repacked in registers.
// ---------------------------------------------------------------------------
#define AQS 72
#define AVS 136
__global__ void __launch_bounds__(256) attn_mma(
    const bf16* __restrict__ qh, const bf16* __restrict__ ql,
    const bf16* __restrict__ kh, const bf16* __restrict__ kl,
    const bf16* __restrict__ vth, const bf16* __restrict__ vtl,
    const int* __restrict__ xmask, const int* __restrict__ ymask,
    bf16* __restrict__ atth, bf16* __restrict__ attl)
{
    extern __shared__ char smraw[];
    bf16* Qh = (bf16*)smraw;              // [128][72]
    bf16* Ql = Qh + 128 * AQS;
    bf16* Kh = Ql + 128 * AQS;            // [128][72]
    bf16* Kl = Kh + 128 * AQS;
    bf16* Vh = Kl + 128 * AQS;            // [64][136]  (Vt: [d][key])
    bf16* Vl = Vh + 64 * AVS;
    float* sbias = (float*)(Vl + 64 * AVS);  // [128]

    const int bh = blockIdx.y, b = bh >> 3, h = bh & 7;
    const int n0 = blockIdx.x * 128;
    const int t = threadIdx.x, lane = t & 31, w = t >> 5;
    const int g = lane >> 2, tg = lane & 3;

    {
        int r = t >> 1, c0 = (t & 1) * 32;
        const bf16* sh = qh + (size_t)(b * NN + n0 + r) * D + h * DS + c0;
        const bf16* sl = ql + (size_t)(b * NN + n0 + r) * D + h * DS + c0;
        #pragma unroll
        for (int j = 0; j < 4; j++) {
            *(uint4*)&Qh[r * AQS + c0 + j * 8] = *(const uint4*)(sh + j * 8);
            *(uint4*)&Ql[r * AQS + c0 + j * 8] = *(const uint4*)(sl + j * 8);
        }
    }
    const int* ymb = ymask + b * MM;

    float mi0 = -3.0e38f, mi1 = -3.0e38f, li0 = 0.f, li1 = 0.f;
    float acco[8][4] = {};

    #pragma unroll 1
    for (int m0 = 0; m0 < MM; m0 += 128) {
        __syncthreads();
        {
            int r = t >> 1, c0 = (t & 1) * 32;
            const bf16* skh = kh + (size_t)(b * MM + m0 + r) * D + h * DS + c0;
            const bf16* skl = kl + (size_t)(b * MM + m0 + r) * D + h * DS + c0;
            #pragma unroll
            for (int j = 0; j < 4; j++) {
                *(uint4*)&Kh[r * AQS + c0 + j * 8] = *(const uint4*)(skh + j * 8);
                *(uint4*)&Kl[r * AQS + c0 + j * 8] = *(const uint4*)(skl + j * 8);
            }
            int d = t >> 2, vc = (t & 3) * 32;
            const bf16* svh = vth + ((size_t)bh * 64 + d) * MM + m0 + vc;
            const bf16* svl = vtl + ((size_t)bh * 64 + d) * MM + m0 + vc;
            #pragma unroll
            for (int j = 0; j < 4; j++) {
                *(uint4*)&Vh[d * AVS + vc + j * 8] = *(const uint4*)(svh + j * 8);
                *(uint4*)&Vl[d * AVS + vc + j * 8] = *(const uint4*)(svl + j * 8);
            }
            if (t < 128) sbias[t] = ymb[m0 + t] ? NEGV : 0.f;
        }
        __syncthreads();

        float accs[16][4];
        #pragma unroll
        for (int nt = 0; nt < 16; nt++)
            { accs[nt][0]=0.f; accs[nt][1]=0.f; accs[nt][2]=0.f; accs[nt][3]=0.f; }

        const int qr = w * 16 + g;
        #pragma unroll
        for (int ks = 0; ks < 4; ks++) {
            int kc = ks * 16 + tg * 2;
            u32 ah0 = *(const u32*)&Qh[qr * AQS + kc];
            u32 ah1 = *(const u32*)&Qh[(qr + 8) * AQS + kc];
            u32 ah2 = *(const u32*)&Qh[qr * AQS + kc + 8];
            u32 ah3 = *(const u32*)&Qh[(qr + 8) * AQS + kc + 8];
            u32 al0 = *(const u32*)&Ql[qr * AQS + kc];
            u32 al1 = *(const u32*)&Ql[(qr + 8) * AQS + kc];
            u32 al2 = *(const u32*)&Ql[qr * AQS + kc + 8];
            u32 al3 = *(const u32*)&Ql[(qr + 8) * AQS + kc + 8];
            #pragma unroll
            for (int nt = 0; nt < 16; nt++) {
                int kr = nt * 8 + g;
                u32 b0 = *(const u32*)&Kh[kr * AQS + kc];
                u32 b1 = *(const u32*)&Kh[kr * AQS + kc + 8];
                u32 c0 = *(const u32*)&Kl[kr * AQS + kc];
                u32 c1 = *(const u32*)&Kl[kr * AQS + kc + 8];
                MMA(accs[nt], ah0, ah1, ah2, ah3, b0, b1);
                MMA(accs[nt], ah0, ah1, ah2, ah3, c0, c1);
                MMA(accs[nt], al0, al1, al2, al3, b0, b1);
            }
        }

        float mx0 = -3.0e38f, mx1 = -3.0e38f;
        #pragma unroll
        for (int nt = 0; nt < 16; nt++) {
            float2 sb = *(float2*)&sbias[nt * 8 + tg * 2];
            accs[nt][0] += sb.x; accs[nt][1] += sb.y;
            accs[nt][2] += sb.x; accs[nt][3] += sb.y;
            mx0 = fmaxf(mx0, fmaxf(accs[nt][0], accs[nt][1]));
            mx1 = fmaxf(mx1, fmaxf(accs[nt][2], accs[nt][3]));
        }
        mx0 = fmaxf(mx0, __shfl_xor_sync(0xffffffffu, mx0, 1));
        mx0 = fmaxf(mx0, __shfl_xor_sync(0xffffffffu, mx0, 2));
        mx1 = fmaxf(mx1, __shfl_xor_sync(0xffffffffu, mx1, 1));
        mx1 = fmaxf(mx1, __shfl_xor_sync(0xffffffffu, mx1, 2));
        float mn0 = fmaxf(mi0, mx0), mn1 = fmaxf(mi1, mx1);
        float cr0 = __expf(mi0 - mn0), cr1 = __expf(mi1 - mn1);
        float sum0 = 0.f, sum1 = 0.f;
        #pragma unroll
        for (int nt = 0; nt < 16; nt++) {
            accs[nt][0] = __expf(accs[nt][0] - mn0); sum0 += accs[nt][0];
            accs[nt][1] = __expf(accs[nt][1] - mn0); sum0 += accs[nt][1];
            accs[nt][2] = __expf(accs[nt][2] - mn1); sum1 += accs[nt][2];
            accs[nt][3] = __expf(accs[nt][3] - mn1); sum1 += accs[nt][3];
        }
        sum0 += __shfl_xor_sync(0xffffffffu, sum0, 1);
        sum0 += __shfl_xor_sync(0xffffffffu, sum0, 2);
        sum1 += __shfl_xor_sync(0xffffffffu, sum1, 1);
        sum1 += __shfl_xor_sync(0xffffffffu, sum1, 2);
        li0 = li0 * cr0 + sum0; mi0 = mn0;
        li1 = li1 * cr1 + sum1; mi1 = mn1;
        #pragma unroll
        for (int nt = 0; nt < 8; nt++) {
            acco[nt][0] *= cr0; acco[nt][1] *= cr0;
            acco[nt][2] *= cr1; acco[nt][3] *= cr1;
        }

        #pragma unroll
        for (int ks = 0; ks < 8; ks++) {
            int n0t = ks * 2, n1t = ks * 2 + 1;
            u32 ph0 = pkbf(accs[n0t][0], accs[n0t][1]);
            u32 ph1 = pkbf(accs[n0t][2], accs[n0t][3]);
            u32 ph2 = pkbf(accs[n1t][0], accs[n1t][1]);
            u32 ph3 = pkbf(accs[n1t][2], accs[n1t][3]);
            float2 f0 = upbf(ph0), f1 = upbf(ph1), f2 = upbf(ph2), f3 = upbf(ph3);
            u32 pl0 = pkbf(accs[n0t][0] - f0.x, accs[n0t][1] - f0.y);
            u32 pl1 = pkbf(accs[n0t][2] - f1.x, accs[n0t][3] - f1.y);
            u32 pl2 = pkbf(accs[n1t][0] - f2.x, accs[n1t][1] - f2.y);
            u32 pl3 = pkbf(accs[n1t][2] - f3.x, accs[n1t][3] - f3.y);
            int kc = ks * 16 + tg * 2;
            #pragma unroll
            for (int nt = 0; nt < 8; nt++) {
                int dr = nt * 8 + g;
                u32 b0 = *(const u32*)&Vh[dr * AVS + kc];
                u32 b1 = *(const u32*)&Vh[dr * AVS + kc + 8];
                u32 c0 = *(const u32*)&Vl[dr * AVS + kc];
                u32 c1 = *(const u32*)&Vl[dr * AVS + kc + 8];
                MMA(acco[nt], ph0, ph1, ph2, ph3, b0, b1);
                MMA(acco[nt], ph0, ph1, ph2, ph3, c0, c1);
                MMA(acco[nt], pl0, pl1, pl2, pl3, b0, b1);
            }
        }
    }

    const int* xmb = xmask + b * NN;
    int qr0 = n0 + w * 16 + g, qr1 = qr0 + 8;
    bool qm0 = xmb[qr0] != 0, qm1 = xmb[qr1] != 0;
    float inv0 = qm0 ? 0.f : 1.f / li0;
    float inv1 = qm1 ? 0.f : 1.f / li1;
    #pragma unroll
    for (int nt = 0; nt < 8; nt++) {
        int col = h * DS + nt * 8 + tg * 2;
        float o00 = acco[nt][0] * inv0, o01 = acco[nt][1] * inv0;
        float o10 = acco[nt][2] * inv1, o11 = acco[nt][3] * inv1;
        u32 h0 = pkbf(o00, o01);
        float2 f0 = upbf(h0);
        u32 l0 = pkbf(o00 - f0.x, o01 - f0.y);
        u32 h1 = pkbf(o10, o11);
        float2 f1 = upbf(h1);
        u32 l1 = pkbf(o10 - f1.x, o11 - f1.y);
        *(u32*)&atth[((size_t)b * NN + qr0) * D + col] = h0;
        *(u32*)&attl[((size_t)b * NN + qr0) * D + col] = l0;
        *(u32*)&atth[((size_t)b * NN + qr1) * D + col] = h1;
        *(u32*)&attl[((size_t)b * NN + qr1) * D + col] = l1;
    }
}
#define ATTN_SMEM (4*128*AQS*2 + 2*64*AVS*2 + 128*4)   // 109056

// ---------------------------------------------------------------------------
// out = LN(a' + b) * g + be; mode bit0: mask output rows; bit1: mask `a` rows;
// bit2: also write split bf16 (OH/OL).
// ---------------------------------------------------------------------------
__global__ void __launch_bounds__(128) add_ln_k(
    const float* __restrict__ a, const float* __restrict__ bsrc,
    const float* __restrict__ g, const float* __restrict__ be,
    const int* __restrict__ xmask, int mode,
    float* __restrict__ out, bf16* __restrict__ OH, bf16* __restrict__ OL)
{
    int row = blockIdx.x;
    int t = threadIdx.x;
    const float* ar = a + (size_t)row * D;
    const float* br = bsrc + (size_t)row * D;
    bool rowmask = xmask[row] != 0;
    bool maska = (mode & 2) && rowmask;

    float vals[4];
    float s = 0.f;
    #pragma unroll
    for (int i = 0; i < 4; i++) {
        float av = maska ? 0.f : ar[t + i * 128];
        vals[i] = av + br[t + i * 128];
        s += vals[i];
    }
    __shared__ float red[4];
    #pragma unroll
    for (int o = 16; o; o >>= 1) s += __shfl_xor_sync(0xffffffffu, s, o);
    if ((t & 31) == 0) red[t >> 5] = s;
    __syncthreads();
    float mu = (red[0] + red[1] + red[2] + red[3]) * (1.f / 512.f);

    float s2 = 0.f;
    #pragma unroll
    for (int i = 0; i < 4; i++) { float d = vals[i] - mu; s2 += d * d; }
    __syncthreads();
    #pragma unroll
    for (int o = 16; o; o >>= 1) s2 += __shfl_xor_sync(0xffffffffu, s2, o);
    if ((t & 31) == 0) red[t >> 5] = s2;
    __syncthreads();
    float inv = rsqrtf((red[0] + red[1] + red[2] + red[3]) * (1.f / 512.f) + 1e-5f);

    bool maskout = (mode & 1) && rowmask;
    #pragma unroll
    for (int i = 0; i < 4; i++) {
        int c = t + i * 128;
        float v = maskout ? 0.f : (vals[i] - mu) * inv * g[c] + be[c];
        out[(size_t)row * D + c] = v;
        if (mode & 4) {
            bf16 hb = __float2bfloat16_rn(v);
            OH[(size_t)row * D + c] = hb;
            OL[(size_t)row * D + c] = __float2bfloat16_rn(v - __bfloat162float(hb));
        }
    }
}

// ---------------------------------------------------------------------------
extern "C" void kernel_launch(void* const* d_in, const int* in_sizes, int n_in,
                              void* d_out, int out_size)
{
    const float* x  = (const float*)d_in[0];
    const float* y  = (const float*)d_in[1];
    const int* xm = (const int*)d_in[2];
    const int* ym = (const int*)d_in[3];
    const float* Wq = (const float*)d_in[4];
    const float* Wk = (const float*)d_in[5];
    const float* Wv = (const float*)d_in[6];
    const float* Wo = (const float*)d_in[7];
    const float* W1 = (const float*)d_in[8];
    const float* b1 = (const float*)d_in[9];
    const float* W2 = (const float*)d_in[10];
    const float* b2 = (const float*)d_in[11];
    const float* g1 = (const float*)d_in[12];
    const float* be1= (const float*)d_in[13];
    const float* g2 = (const float*)d_in[14];
    const float* be2= (const float*)d_in[15];
    float* out = (float*)d_out;

    float *t1, *t2, *ff;
    cudaGetSymbolAddress((void**)&t1, S_t1);
    cudaGetSymbolAddress((void**)&t2, S_t2);
    cudaGetSymbolAddress((void**)&ff, S_ff);
    bf16 *wh, *wl, *xh, *xl, *yh, *yl, *qh, *ql, *kh, *kl, *vth, *vtl;
    bf16 *ath, *atl, *t2h, *t2l, *rh, *rl;
    cudaGetSymbolAddress((void**)&wh,  S_WH);
    cudaGetSymbolAddress((void**)&wl,  S_WL);
    cudaGetSymbolAddress((void**)&xh,  S_XH);
    cudaGetSymbolAddress((void**)&xl,  S_XL);
    cudaGetSymbolAddress((void**)&yh,  S_YH);
    cudaGetSymbolAddress((void**)&yl,  S_YL);
    cudaGetSymbolAddress((void**)&qh,  S_QH);
    cudaGetSymbolAddress((void**)&ql,  S_QL);
    cudaGetSymbolAddress((void**)&kh,  S_KH);
    cudaGetSymbolAddress((void**)&kl,  S_KL);
    cudaGetSymbolAddress((void**)&vth, S_VTH);
    cudaGetSymbolAddress((void**)&vtl, S_VTL);
    cudaGetSymbolAddress((void**)&ath, S_ATH);
    cudaGetSymbolAddress((void**)&atl, S_ATL);
    cudaGetSymbolAddress((void**)&t2h, S_T2H);
    cudaGetSymbolAddress((void**)&t2l, S_T2L);
    cudaGetSymbolAddress((void**)&rh,  S_RH);
    cudaGetSymbolAddress((void**)&rl,  S_RL);

    cudaFuncSetAttribute(attn_mma, cudaFuncAttributeMaxDynamicSharedMemorySize,
                         ATTN_SMEM);
    cudaFuncSetAttribute(hgemm_k<0>,  cudaFuncAttributeMaxDynamicSharedMemorySize, HG_SMEM);
    cudaFuncSetAttribute(hgemm_k<1>,  cudaFuncAttributeMaxDynamicSharedMemorySize, HG_SMEM);
    cudaFuncSetAttribute(hgemm_k<8>,  cudaFuncAttributeMaxDynamicSharedMemorySize, HG_SMEM);
    cudaFuncSetAttribute(hgemm_k<11>, cudaFuncAttributeMaxDynamicSharedMemorySize, HG_SMEM);
    cudaFuncSetAttribute(hgemm_k<16>, cudaFuncAttributeMaxDynamicSharedMemorySize, HG_SMEM);

    wsplit_all<<<6144, 256>>>(Wq, Wk, Wv, Wo, W1, W2, wh, wl);
    asplit_k<<<4096, 256>>>(x, xm, xh, xl);
    asplit_k<<<4096, 256>>>(y, ym, yh, yl);

    dim3 gg(4, 64);
    hgemm_k<8> <<<gg, 256, HG_SMEM>>>(xh, xl, wh + 0*(size_t)D*D, wl + 0*(size_t)D*D, nullptr, nullptr, qh, ql);
    hgemm_k<8> <<<gg, 256, HG_SMEM>>>(yh, yl, wh + 1*(size_t)D*D, wl + 1*(size_t)D*D, nullptr, nullptr, kh, kl);
    hgemm_k<16><<<gg, 256, HG_SMEM>>>(yh, yl, wh + 2*(size_t)D*D, wl + 2*(size_t)D*D, nullptr, nullptr, vth, vtl);

    dim3 ga(8, 64);
    attn_mma<<<ga, 256, ATTN_SMEM>>>(qh, ql, kh, kl, vth, vtl, xm, ym, ath, atl);

    hgemm_k<0><<<gg, 256, HG_SMEM>>>(ath, atl, wh + 3*(size_t)D*D, wl + 3*(size_t)D*D, nullptr, t1, nullptr, nullptr);
    add_ln_k<<<ROWS, 128>>>(x, t1, g1, be1, xm, 2 | 4, t2, t2h, t2l);
    hgemm_k<11><<<gg, 256, HG_SMEM>>>(t2h, t2l, wh + 4*(size_t)D*D, wl + 4*(size_t)D*D, b1, nullptr, rh, rl);
    hgemm_k<1><<<gg, 256, HG_SMEM>>>(rh, rl, wh + 5*(size_t)D*D, wl + 5*(size_t)D*D, b2, ff, nullptr, nullptr);
    add_ln_k<<<ROWS, 128>>>(t2, ff, g2, be2, xm, 1, out, nullptr, nullptr);
}

// round 17
// speedup vs baseline: 2.5789x; 1.0901x over previous
#include <cuda_runtime.h>
#include <cuda_bf16.h>
#include <math.h>
#include <stdint.h>

#define BB 8
#define NN 1024
#define MM 1024
#define D  512
#define HH 8
#define DS 64
#define ROWS (BB*NN)          // 8192
#define NEGV (-1e38f)
#define SCALE 0.04419417382415922f   // 1/sqrt(512)

typedef unsigned int u32;
typedef __nv_bfloat16 bf16;

// pack two f32 -> bf16x2 {lo, hi}
__device__ __forceinline__ u32 pkbf(float lo, float hi) {
    u32 r;
    asm("cvt.rn.bf16x2.f32 %0, %1, %2;" : "=r"(r) : "f"(hi), "f"(lo));
    return r;
}
__device__ __forceinline__ float2 upbf(u32 p) {
    __nv_bfloat162 b2 = *reinterpret_cast<__nv_bfloat162*>(&p);
    return __bfloat1622float2(b2);
}
__device__ __forceinline__ u32 smem_u32(const void* p) {
    u32 a;
    asm("{ .reg .u64 t; cvta.to.shared.u64 t, %1; cvt.u32.u64 %0, t; }" : "=r"(a) : "l"(p));
    return a;
}
__device__ __forceinline__ void cpa16(u32 s, const void* g) {
    asm volatile("cp.async.cg.shared.global [%0], [%1], 16;" :: "r"(s), "l"(g));
}
#define CPA_COMMIT() asm volatile("cp.async.commit_group;")
#define CPA_WAIT1()  asm volatile("cp.async.wait_group 1;")

// bf16x2 MMA: D(16x8 f32) += A(16x16) * B(16x8), row.col
#define MMA(d, a0,a1,a2,a3, b0,b1) \
    asm volatile("mma.sync.aligned.m16n8k16.row.col.f32.bf16.bf16.f32 " \
        "{%0,%1,%2,%3}, {%4,%5,%6,%7}, {%8,%9}, {%0,%1,%2,%3};" \
        : "+f"(d[0]),"+f"(d[1]),"+f"(d[2]),"+f"(d[3]) \
        : "r"(a0),"r"(a1),"r"(a2),"r"(a3),"r"(b0),"r"(b1))

__device__ __forceinline__ void ldsm4(u32& r0, u32& r1, u32& r2, u32& r3, u32 a) {
    asm volatile("ldmatrix.sync.aligned.m8n8.x4.shared.b16 {%0,%1,%2,%3}, [%4];"
                 : "=r"(r0), "=r"(r1), "=r"(r2), "=r"(r3) : "r"(a));
}

// ---------------- scratch (device globals) ----------------
__device__ float S_t1 [ROWS*D];
__device__ float S_t2 [ROWS*D];
__device__ float S_ff [ROWS*D];
__device__ bf16 S_WH[6*D*D], S_WL[6*D*D];         // weights [n][k] split
__device__ bf16 S_XH[ROWS*D], S_XL[ROWS*D];
__device__ bf16 S_YH[ROWS*D], S_YL[ROWS*D];
__device__ bf16 S_QH[ROWS*D], S_QL[ROWS*D];
__device__ bf16 S_KH[ROWS*D], S_KL[ROWS*D];
__device__ bf16 S_VTH[ROWS*D], S_VTL[ROWS*D];     // [b*h][d][key]
__device__ bf16 S_ATH[ROWS*D], S_ATL[ROWS*D];
__device__ bf16 S_T2H[ROWS*D], S_T2L[ROWS*D];
__device__ bf16 S_RH[ROWS*D],  S_RL[ROWS*D];

// ---------------------------------------------------------------------------
// Fused weight prep: all 6 weights, transpose + bf16 split; Wq gets SCALE.
// ---------------------------------------------------------------------------
__global__ void __launch_bounds__(256) wsplit_all(
    const float* __restrict__ W0, const float* __restrict__ W1,
    const float* __restrict__ W2, const float* __restrict__ W3,
    const float* __restrict__ W4, const float* __restrict__ W5,
    bf16* __restrict__ WH, bf16* __restrict__ WL)
{
    int gi = blockIdx.x;
    int wi = gi >> 10;
    const float* W = (wi == 0) ? W0 : (wi == 1) ? W1 : (wi == 2) ? W2
                   : (wi == 3) ? W3 : (wi == 4) ? W4 : W5;
    float sc = (wi == 0) ? SCALE : 1.f;
    int idx = (gi & 1023) * 256 + threadIdx.x;
    int n = idx & 511, kk = idx >> 9;
    float w = W[(size_t)kk * D + n] * sc;
    bf16 h = __float2bfloat16_rn(w);
    bf16 l = __float2bfloat16_rn(w - __bfloat162float(h));
    WH[(size_t)wi * D * D + (size_t)n * D + kk] = h;
    WL[(size_t)wi * D * D + (size_t)n * D + kk] = l;
}

// ---------------------------------------------------------------------------
// Activation split for BOTH x and y in one launch (grid.y: 0=x, 1=y).
// ---------------------------------------------------------------------------
__global__ void __launch_bounds__(256) asplit2_k(
    const float* __restrict__ X, const float* __restrict__ Y,
    const int* __restrict__ xmask, const int* __restrict__ ymask,
    bf16* __restrict__ XHg, bf16* __restrict__ XLg,
    bf16* __restrict__ YHg, bf16* __restrict__ YLg)
{
    const float* A = blockIdx.y ? Y : X;
    const int* mask = blockIdx.y ? ymask : xmask;
    bf16* AHg = blockIdx.y ? YHg : XHg;
    bf16* ALg = blockIdx.y ? YLg : XLg;

    int i4 = blockIdx.x * 256 + threadIdx.x;   // ROWS*D/4
    int row = i4 >> 7;
    float4 f = ((const float4*)A)[i4];
    if (mask[row]) f = make_float4(0.f, 0.f, 0.f, 0.f);
    u32 h0 = pkbf(f.x, f.y), h1 = pkbf(f.z, f.w);
    float2 a = upbf(h0), b = upbf(h1);
    u32 l0 = pkbf(f.x - a.x, f.y - a.y), l1 = pkbf(f.z - b.x, f.w - b.y);
    uint2 hh = make_uint2(h0, h1), ll = make_uint2(l0, l1);
    *(uint2*)(AHg + (size_t)i4 * 4) = hh;
    *(uint2*)(ALg + (size_t)i4 * 4) = ll;
}

// ---------------------------------------------------------------------------
// bf16 tensor-core GEMM, split precision (Ah.Bh + Ah.Bl + Al.Bh).
// Tile 128x128, k-chunk 32, 8 warps 2x4, warp tile 64x32.
// 3-stage cp.async pipeline, 32 KB/stage -> 2 CTAs/SM.
// Fragment loads via ldmatrix.x4 (24 instr/warp/chunk vs 96 LDS.32).
// Smem rows 64 B with 16B-chunk XOR swizzle (chunk ^= (row>>1)&3).
// FLAGS: bit0 +bias, bit1 relu, bit3(8) split bf16 out, bit4(16) vT split out.
// ---------------------------------------------------------------------------
#define HG_ARRB  8192                 // one array: 128 rows * 64 B
#define HG_STGB  (4 * HG_ARRB)        // one stage: AH,AL,BH,BL = 32768 B
#define HG_SMEM  (3 * HG_STGB)        // 98304 B

// swizzled byte offset of element e (0..31) in row r (e multiple of 8 -> 16B aligned)
__device__ __forceinline__ u32 sws8(int r, int e) {
    return (u32)(r * 64 + ((((e >> 3) ^ ((r >> 1) & 3)) << 4)));
}

__device__ __forceinline__ size_t vtidx(int row, int col) {
    return (((size_t)(row >> 10) * 8 + (col >> 6)) * 64 + (col & 63)) * 1024
           + (row & 1023);
}

template<int FLAGS>
__global__ void __launch_bounds__(256, 2) hgemm_k(
    const bf16* __restrict__ AHg, const bf16* __restrict__ ALg,
    const bf16* __restrict__ BHg, const bf16* __restrict__ BLg,
    const float* __restrict__ bias, float* __restrict__ C,
    bf16* __restrict__ CH, bf16* __restrict__ CL)
{
    extern __shared__ char hs[];
    const u32 sbase = smem_u32(hs);
    const int t = threadIdx.x, lane = t & 31, wid = t >> 5;
    const int wm = wid >> 2, wn = wid & 3;
    const int g = lane >> 2, tg = lane & 3;
    const int row0 = blockIdx.y * 128, col0 = blockIdx.x * 128;
    const int lr = t >> 1, lc = (t & 1) * 16;     // 2 thr/row, 16 elems each

    const bf16* AHp = AHg + (size_t)(row0 + lr) * D + lc;
    const bf16* ALp = ALg + (size_t)(row0 + lr) * D + lc;
    const bf16* BHp = BHg + (size_t)(col0 + lr) * D + lc;
    const bf16* BLp = BLg + (size_t)(col0 + lr) * D + lc;
    const int ci0 = 2 * (t & 1), ci1 = ci0 + 1;
    const u32 sw0 = (u32)(lr * 64) + (u32)(((ci0 ^ ((lr >> 1) & 3)) << 4));
    const u32 sw1 = (u32)(lr * 64) + (u32)(((ci1 ^ ((lr >> 1) & 3)) << 4));

    auto issue = [&](int c) {
        u32 st = sbase + (u32)(c % 3) * HG_STGB;
        const int ko = c * 32;
        cpa16(st + 0*HG_ARRB + sw0, AHp + ko);
        cpa16(st + 0*HG_ARRB + sw1, AHp + ko + 8);
        cpa16(st + 1*HG_ARRB + sw0, ALp + ko);
        cpa16(st + 1*HG_ARRB + sw1, ALp + ko + 8);
        cpa16(st + 2*HG_ARRB + sw0, BHp + ko);
        cpa16(st + 2*HG_ARRB + sw1, BHp + ko + 8);
        cpa16(st + 3*HG_ARRB + sw0, BLp + ko);
        cpa16(st + 3*HG_ARRB + sw1, BLp + ko + 8);
    };

    issue(0); CPA_COMMIT();
    issue(1); CPA_COMMIT();

    // ldmatrix lane-address components (loop-invariant)
    const int lAr = lane & 15;                 // + mr
    const int lAe = (lane >> 4) * 8;           // + ks
    const int lBr = wn * 32 + ((lane >> 4) << 3) + (lane & 7);  // + ntp*16
    const int lBe = ((lane >> 3) & 1) * 8;     // + ks

    float acc[4][4][4] = {};

    #pragma unroll 1
    for (int c = 0; c < 16; c++) {
        CPA_WAIT1();
        __syncthreads();
        const u32 AH = sbase + (u32)(c % 3) * HG_STGB;
        const u32 AL = AH + HG_ARRB;
        const u32 BH = AL + HG_ARRB;
        const u32 BL = BH + HG_ARRB;

        #pragma unroll
        for (int ks = 0; ks < 32; ks += 16) {
            // B fragments: 2 ldmatrix.x4 per array cover all 4 n8 tiles
            u32 bh[8], bl[8];
            #pragma unroll
            for (int ntp = 0; ntp < 2; ntp++) {
                u32 ba = sws8(lBr + ntp * 16, ks + lBe);
                ldsm4(bh[ntp*4+0], bh[ntp*4+1], bh[ntp*4+2], bh[ntp*4+3], BH + ba);
                ldsm4(bl[ntp*4+0], bl[ntp*4+1], bl[ntp*4+2], bl[ntp*4+3], BL + ba);
            }
            #pragma unroll
            for (int mt = 0; mt < 4; mt++) {
                u32 aa = sws8(wm * 64 + mt * 16 + lAr, ks + lAe);
                u32 ah0, ah1, ah2, ah3, al0, al1, al2, al3;
                ldsm4(ah0, ah1, ah2, ah3, AH + aa);
                ldsm4(al0, al1, al2, al3, AL + aa);
                #pragma unroll
                for (int nt = 0; nt < 4; nt++)
                    MMA(acc[mt][nt], ah0, ah1, ah2, ah3, bh[nt*2], bh[nt*2+1]);
                #pragma unroll
                for (int nt = 0; nt < 4; nt++)
                    MMA(acc[mt][nt], ah0, ah1, ah2, ah3, bl[nt*2], bl[nt*2+1]);
                #pragma unroll
                for (int nt = 0; nt < 4; nt++)
                    MMA(acc[mt][nt], al0, al1, al2, al3, bh[nt*2], bh[nt*2+1]);
            }
        }
        if (c + 2 < 16) issue(c + 2);
        CPA_COMMIT();
    }

    #pragma unroll
    for (int mt = 0; mt < 4; mt++) {
        int row = row0 + wm * 64 + mt * 16 + g;
        #pragma unroll
        for (int nt = 0; nt < 4; nt++) {
            int col = col0 + wn * 32 + nt * 8 + tg * 2;
            float2 v0 = make_float2(acc[mt][nt][0], acc[mt][nt][1]);
            float2 v1 = make_float2(acc[mt][nt][2], acc[mt][nt][3]);
            if (FLAGS & 1) {
                float bb0 = bias[col], bb1 = bias[col + 1];
                v0.x += bb0; v0.y += bb1; v1.x += bb0; v1.y += bb1;
            }
            if (FLAGS & 2) {
                v0.x = fmaxf(v0.x, 0.f); v0.y = fmaxf(v0.y, 0.f);
                v1.x = fmaxf(v1.x, 0.f); v1.y = fmaxf(v1.y, 0.f);
            }
            if (FLAGS & 16) {
                bf16 h00 = __float2bfloat16_rn(v0.x);
                bf16 h01 = __float2bfloat16_rn(v0.y);
                bf16 h10 = __float2bfloat16_rn(v1.x);
                bf16 h11 = __float2bfloat16_rn(v1.y);
                CH[vtidx(row, col)]       = h00;
                CH[vtidx(row, col + 1)]   = h01;
                CH[vtidx(row + 8, col)]   = h10;
                CH[vtidx(row + 8, col+1)] = h11;
                CL[vtidx(row, col)]       = __float2bfloat16_rn(v0.x - __bfloat162float(h00));
                CL[vtidx(row, col + 1)]   = __float2bfloat16_rn(v0.y - __bfloat162float(h01));
                CL[vtidx(row + 8, col)]   = __float2bfloat16_rn(v1.x - __bfloat162float(h10));
                CL[vtidx(row + 8, col+1)] = __float2bfloat16_rn(v1.y - __bfloat162float(h11));
            } else if (FLAGS & 8) {
                u32 h0 = pkbf(v0.x, v0.y);
                float2 f0 = upbf(h0);
                u32 l0 = pkbf(v0.x - f0.x, v0.y - f0.y);
                u32 h1 = pkbf(v1.x, v1.y);
                float2 f1 = upbf(h1);
                u32 l1 = pkbf(v1.x - f1.x, v1.y - f1.y);
                *(u32*)&CH[(size_t)row * D + col] = h0;
                *(u32*)&CL[(size_t)row * D + col] = l0;
                *(u32*)&CH[(size_t)(row + 8) * D + col] = h1;
                *(u32*)&CL[(size_t)(row + 8) * D + col] = l1;
            } else {
                *(float2*)&C[(size_t)row * D + col] = v0;
                *(float2*)&C[(size_t)(row + 8) * D + col] = v1;
            }
        }
    }
}

// ---------------------------------------------------------------------------
// Tensor-core flash attention. CTA = (b,h,128q), 8 warps x 16q, key chunks 128.
// S and PV via m16n8k16 with split operands; P repacked in registers.
// ---------------------------------------------------------------------------
#define AQS 72
#define AVS 136
__global__ void __launch_bounds__(256) attn_mma(
    const bf16* __restrict__ qh, const bf16* __restrict__ ql,
    const bf16* __restrict__ kh, const bf16* __restrict__ kl,
    const bf16* __restrict__ vth, const bf16* __restrict__ vtl,
    const int* __restrict__ xmask, const int* __restrict__ ymask,
    bf16* __restrict__ atth, bf16* __restrict__ attl)
{
    extern __shared__ char smraw[];
    bf16* Qh = (bf16*)smraw;              // [128][72]
    bf16* Ql = Qh + 128 * AQS;
    bf16* Kh = Ql + 128 * AQS;            // [128][72]
    bf16* Kl = Kh + 128 * AQS;
    bf16* Vh = Kl + 128 * AQS;            // [64][136]  (Vt: [d][key])
    bf16* Vl = Vh + 64 * AVS;
    float* sbias = (float*)(Vl + 64 * AVS);  // [128]

    const int bh = blockIdx.y, b = bh >> 3, h = bh & 7;
    const int n0 = blockIdx.x * 128;
    const int t = threadIdx.x, lane = t & 31, w = t >> 5;
    const int g = lane >> 2, tg = lane & 3;

    {
        int r = t >> 1, c0 = (t & 1) * 32;
        const bf16* sh = qh + (size_t)(b * NN + n0 + r) * D + h * DS + c0;
        const bf16* sl = ql + (size_t)(b * NN + n0 + r) * D + h * DS + c0;
        #pragma unroll
        for (int j = 0; j < 4; j++) {
            *(uint4*)&Qh[r * AQS + c0 + j * 8] = *(const uint4*)(sh + j * 8);
            *(uint4*)&Ql[r * AQS + c0 + j * 8] = *(const uint4*)(sl + j * 8);
        }
    }
    const int* ymb = ymask + b * MM;

    float mi0 = -3.0e38f, mi1 = -3.0e38f, li0 = 0.f, li1 = 0.f;
    float acco[8][4] = {};

    #pragma unroll 1
    for (int m0 = 0; m0 < MM; m0 += 128) {
        __syncthreads();
        {
            int r = t >> 1, c0 = (t & 1) * 32;
            const bf16* skh = kh + (size_t)(b * MM + m0 + r) * D + h * DS + c0;
            const bf16* skl = kl + (size_t)(b * MM + m0 + r) * D + h * DS + c0;
            #pragma unroll
            for (int j = 0; j < 4; j++) {
                *(uint4*)&Kh[r * AQS + c0 + j * 8] = *(const uint4*)(skh + j * 8);
                *(uint4*)&Kl[r * AQS + c0 + j * 8] = *(const uint4*)(skl + j * 8);
            }
            int d = t >> 2, vc = (t & 3) * 32;
            const bf16* svh = vth + ((size_t)bh * 64 + d) * MM + m0 + vc;
            const bf16* svl = vtl + ((size_t)bh * 64 + d) * MM + m0 + vc;
            #pragma unroll
            for (int j = 0; j < 4; j++) {
                *(uint4*)&Vh[d * AVS + vc + j * 8] = *(const uint4*)(svh + j * 8);
                *(uint4*)&Vl[d * AVS + vc + j * 8] = *(const uint4*)(svl + j * 8);
            }
            if (t < 128) sbias[t] = ymb[m0 + t] ? NEGV : 0.f;
        }
        __syncthreads();

        float accs[16][4];
        #pragma unroll
        for (int nt = 0; nt < 16; nt++)
            { accs[nt][0]=0.f; accs[nt][1]=0.f; accs[nt][2]=0.f; accs[nt][3]=0.f; }

        const int qr = w * 16 + g;
        #pragma unroll
        for (int ks = 0; ks < 4; ks++) {
            int kc = ks * 16 + tg * 2;
            u32 ah0 = *(const u32*)&Qh[qr * AQS + kc];
            u32 ah1 = *(const u32*)&Qh[(qr + 8) * AQS + kc];
            u32 ah2 = *(const u32*)&Qh[qr * AQS + kc + 8];
            u32 ah3 = *(const u32*)&Qh[(qr + 8) * AQS + kc + 8];
            u32 al0 = *(const u32*)&Ql[qr * AQS + kc];
            u32 al1 = *(const u32*)&Ql[(qr + 8) * AQS + kc];
            u32 al2 = *(const u32*)&Ql[qr * AQS + kc + 8];
            u32 al3 = *(const u32*)&Ql[(qr + 8) * AQS + kc + 8];
            #pragma unroll
            for (int nt = 0; nt < 16; nt++) {
                int kr = nt * 8 + g;
                u32 b0 = *(const u32*)&Kh[kr * AQS + kc];
                u32 b1 = *(const u32*)&Kh[kr * AQS + kc + 8];
                u32 c0 = *(const u32*)&Kl[kr * AQS + kc];
                u32 c1 = *(const u32*)&Kl[kr * AQS + kc + 8];
                MMA(accs[nt], ah0, ah1, ah2, ah3, b0, b1);
                MMA(accs[nt], ah0, ah1, ah2, ah3, c0, c1);
                MMA(accs[nt], al0, al1, al2, al3, b0, b1);
            }
        }

        float mx0 = -3.0e38f, mx1 = -3.0e38f;
        #pragma unroll
        for (int nt = 0; nt < 16; nt++) {
            float2 sb = *(float2*)&sbias[nt * 8 + tg * 2];
            accs[nt][0] += sb.x; accs[nt][1] += sb.y;
            accs[nt][2] += sb.x; accs[nt][3] += sb.y;
            mx0 = fmaxf(mx0, fmaxf(accs[nt][0], accs[nt][1]));
            mx1 = fmaxf(mx1, fmaxf(accs[nt][2], accs[nt][3]));
        }
        mx0 = fmaxf(mx0, __shfl_xor_sync(0xffffffffu, mx0, 1));
        mx0 = fmaxf(mx0, __shfl_xor_sync(0xffffffffu, mx0, 2));
        mx1 = fmaxf(mx1, __shfl_xor_sync(0xffffffffu, mx1, 1));
        mx1 = fmaxf(mx1, __shfl_xor_sync(0xffffffffu, mx1, 2));
        float mn0 = fmaxf(mi0, mx0), mn1 = fmaxf(mi1, mx1);
        float cr0 = __expf(mi0 - mn0), cr1 = __expf(mi1 - mn1);
        float sum0 = 0.f, sum1 = 0.f;
        #pragma unroll
        for (int nt = 0; nt < 16; nt++) {
            accs[nt][0] = __expf(accs[nt][0] - mn0); sum0 += accs[nt][0];
            accs[nt][1] = __expf(accs[nt][1] - mn0); sum0 += accs[nt][1];
            accs[nt][2] = __expf(accs[nt][2] - mn1); sum1 += accs[nt][2];
            accs[nt][3] = __expf(accs[nt][3] - mn1); sum1 += accs[nt][3];
        }
        sum0 += __shfl_xor_sync(0xffffffffu, sum0, 1);
        sum0 += __shfl_xor_sync(0xffffffffu, sum0, 2);
        sum1 += __shfl_xor_sync(0xffffffffu, sum1, 1);
        sum1 += __shfl_xor_sync(0xffffffffu, sum1, 2);
        li0 = li0 * cr0 + sum0; mi0 = mn0;
        li1 = li1 * cr1 + sum1; mi1 = mn1;
        #pragma unroll
        for (int nt = 0; nt < 8; nt++) {
            acco[nt][0] *= cr0; acco[nt][1] *= cr0;
            acco[nt][2] *= cr1; acco[nt][3] *= cr1;
        }

        #pragma unroll
        for (int ks = 0; ks < 8; ks++) {
            int n0t = ks * 2, n1t = ks * 2 + 1;
            u32 ph0 = pkbf(accs[n0t][0], accs[n0t][1]);
            u32 ph1 = pkbf(accs[n0t][2], accs[n0t][3]);
            u32 ph2 = pkbf(accs[n1t][0], accs[n1t][1]);
            u32 ph3 = pkbf(accs[n1t][2], accs[n1t][3]);
            float2 f0 = upbf(ph0), f1 = upbf(ph1), f2 = upbf(ph2), f3 = upbf(ph3);
            u32 pl0 = pkbf(accs[n0t][0] - f0.x, accs[n0t][1] - f0.y);
            u32 pl1 = pkbf(accs[n0t][2] - f1.x, accs[n0t][3] - f1.y);
            u32 pl2 = pkbf(accs[n1t][0] - f2.x, accs[n1t][1] - f2.y);
            u32 pl3 = pkbf(accs[n1t][2] - f3.x, accs[n1t][3] - f3.y);
            int kc = ks * 16 + tg * 2;
            #pragma unroll
            for (int nt = 0; nt < 8; nt++) {
                int dr = nt * 8 + g;
                u32 b0 = *(const u32*)&Vh[dr * AVS + kc];
                u32 b1 = *(const u32*)&Vh[dr * AVS + kc + 8];
                u32 c0 = *(const u32*)&Vl[dr * AVS + kc];
                u32 c1 = *(const u32*)&Vl[dr * AVS + kc + 8];
                MMA(acco[nt], ph0, ph1, ph2, ph3, b0, b1);
                MMA(acco[nt], ph0, ph1, ph2, ph3, c0, c1);
                MMA(acco[nt], pl0, pl1, pl2, pl3, b0, b1);
            }
        }
    }

    const int* xmb = xmask + b * NN;
    int qr0 = n0 + w * 16 + g, qr1 = qr0 + 8;
    bool qm0 = xmb[qr0] != 0, qm1 = xmb[qr1] != 0;
    float inv0 = qm0 ? 0.f : 1.f / li0;
    float inv1 = qm1 ? 0.f : 1.f / li1;
    #pragma unroll
    for (int nt = 0; nt < 8; nt++) {
        int col = h * DS + nt * 8 + tg * 2;
        float o00 = acco[nt][0] * inv0, o01 = acco[nt][1] * inv0;
        float o10 = acco[nt][2] * inv1, o11 = acco[nt][3] * inv1;
        u32 h0 = pkbf(o00, o01);
        float2 f0 = upbf(h0);
        u32 l0 = pkbf(o00 - f0.x, o01 - f0.y);
        u32 h1 = pkbf(o10, o11);
        float2 f1 = upbf(h1);
        u32 l1 = pkbf(o10 - f1.x, o11 - f1.y);
        *(u32*)&atth[((size_t)b * NN + qr0) * D + col] = h0;
        *(u32*)&attl[((size_t)b * NN + qr0) * D + col] = l0;
        *(u32*)&atth[((size_t)b * NN + qr1) * D + col] = h1;
        *(u32*)&attl[((size_t)b * NN + qr1) * D + col] = l1;
    }
}
#define ATTN_SMEM (4*128*AQS*2 + 2*64*AVS*2 + 128*4)   // 109056

// ---------------------------------------------------------------------------
// out = LN(a' + b) * g + be; mode bit0: mask output rows; bit1: mask `a` rows;
// bit2: also write split bf16 (OH/OL).
// ---------------------------------------------------------------------------
__global__ void __launch_bounds__(128) add_ln_k(
    const float* __restrict__ a, const float* __restrict__ bsrc,
    const float* __restrict__ g, const float* __restrict__ be,
    const int* __restrict__ xmask, int mode,
    float* __restrict__ out, bf16* __restrict__ OH, bf16* __restrict__ OL)
{
    int row = blockIdx.x;
    int t = threadIdx.x;
    const float* ar = a + (size_t)row * D;
    const float* br = bsrc + (size_t)row * D;
    bool rowmask = xmask[row] != 0;
    bool maska = (mode & 2) && rowmask;

    float vals[4];
    float s = 0.f;
    #pragma unroll
    for (int i = 0; i < 4; i++) {
        float av = maska ? 0.f : ar[t + i * 128];
        vals[i] = av + br[t + i * 128];
        s += vals[i];
    }
    __shared__ float red[4];
    #pragma unroll
    for (int o = 16; o; o >>= 1) s += __shfl_xor_sync(0xffffffffu, s, o);
    if ((t & 31) == 0) red[t >> 5] = s;
    __syncthreads();
    float mu = (red[0] + red[1] + red[2] + red[3]) * (1.f / 512.f);

    float s2 = 0.f;
    #pragma unroll
    for (int i = 0; i < 4; i++) { float d = vals[i] - mu; s2 += d * d; }
    __syncthreads();
    #pragma unroll
    for (int o = 16; o; o >>= 1) s2 += __shfl_xor_sync(0xffffffffu, s2, o);
    if ((t & 31) == 0) red[t >> 5] = s2;
    __syncthreads();
    float inv = rsqrtf((red[0] + red[1] + red[2] + red[3]) * (1.f / 512.f) + 1e-5f);

    bool maskout = (mode & 1) && rowmask;
    #pragma unroll
    for (int i = 0; i < 4; i++) {
        int c = t + i * 128;
        float v = maskout ? 0.f : (vals[i] - mu) * inv * g[c] + be[c];
        out[(size_t)row * D + c] = v;
        if (mode & 4) {
            bf16 hb = __float2bfloat16_rn(v);
            OH[(size_t)row * D + c] = hb;
            OL[(size_t)row * D + c] = __float2bfloat16_rn(v - __bfloat162float(hb));
        }
    }
}

// ---------------------------------------------------------------------------
extern "C" void kernel_launch(void* const* d_in, const int* in_sizes, int n_in,
                              void* d_out, int out_size)
{
    const float* x  = (const float*)d_in[0];
    const float* y  = (const float*)d_in[1];
    const int* xm = (const int*)d_in[2];
    const int* ym = (const int*)d_in[3];
    const float* Wq = (const float*)d_in[4];
    const float* Wk = (const float*)d_in[5];
    const float* Wv = (const float*)d_in[6];
    const float* Wo = (const float*)d_in[7];
    const float* W1 = (const float*)d_in[8];
    const float* b1 = (const float*)d_in[9];
    const float* W2 = (const float*)d_in[10];
    const float* b2 = (const float*)d_in[11];
    const float* g1 = (const float*)d_in[12];
    const float* be1= (const float*)d_in[13];
    const float* g2 = (const float*)d_in[14];
    const float* be2= (const float*)d_in[15];
    float* out = (float*)d_out;

    float *t1, *t2, *ff;
    cudaGetSymbolAddress((void**)&t1, S_t1);
    cudaGetSymbolAddress((void**)&t2, S_t2);
    cudaGetSymbolAddress((void**)&ff, S_ff);
    bf16 *wh, *wl, *xh, *xl, *yh, *yl, *qh, *ql, *kh, *kl, *vth, *vtl;
    bf16 *ath, *atl, *t2h, *t2l, *rh, *rl;
    cudaGetSymbolAddress((void**)&wh,  S_WH);
    cudaGetSymbolAddress((void**)&wl,  S_WL);
    cudaGetSymbolAddress((void**)&xh,  S_XH);
    cudaGetSymbolAddress((void**)&xl,  S_XL);
    cudaGetSymbolAddress((void**)&yh,  S_YH);
    cudaGetSymbolAddress((void**)&yl,  S_YL);
    cudaGetSymbolAddress((void**)&qh,  S_QH);
    cudaGetSymbolAddress((void**)&ql,  S_QL);
    cudaGetSymbolAddress((void**)&kh,  S_KH);
    cudaGetSymbolAddress((void**)&kl,  S_KL);
    cudaGetSymbolAddress((void**)&vth, S_VTH);
    cudaGetSymbolAddress((void**)&vtl, S_VTL);
    cudaGetSymbolAddress((void**)&ath, S_ATH);
    cudaGetSymbolAddress((void**)&atl, S_ATL);
    cudaGetSymbolAddress((void**)&t2h, S_T2H);
    cudaGetSymbolAddress((void**)&t2l, S_T2L);
    cudaGetSymbolAddress((void**)&rh,  S_RH);
    cudaGetSymbolAddress((void**)&rl,  S_RL);

    cudaFuncSetAttribute(attn_mma, cudaFuncAttributeMaxDynamicSharedMemorySize,
                         ATTN_SMEM);
    cudaFuncSetAttribute(hgemm_k<0>,  cudaFuncAttributeMaxDynamicSharedMemorySize, HG_SMEM);
    cudaFuncSetAttribute(hgemm_k<1>,  cudaFuncAttributeMaxDynamicSharedMemorySize, HG_SMEM);
    cudaFuncSetAttribute(hgemm_k<8>,  cudaFuncAttributeMaxDynamicSharedMemorySize, HG_SMEM);
    cudaFuncSetAttribute(hgemm_k<11>, cudaFuncAttributeMaxDynamicSharedMemorySize, HG_SMEM);
    cudaFuncSetAttribute(hgemm_k<16>, cudaFuncAttributeMaxDynamicSharedMemorySize, HG_SMEM);

    wsplit_all<<<6144, 256>>>(Wq, Wk, Wv, Wo, W1, W2, wh, wl);
    {
        dim3 gs(4096, 2);
        asplit2_k<<<gs, 256>>>(x, y, xm, ym, xh, xl, yh, yl);
    }

    dim3 gg(4, 64);
    hgemm_k<8> <<<gg, 256, HG_SMEM>>>(xh, xl, wh + 0*(size_t)D*D, wl + 0*(size_t)D*D, nullptr, nullptr, qh, ql);
    hgemm_k<8> <<<gg, 256, HG_SMEM>>>(yh, yl, wh + 1*(size_t)D*D, wl + 1*(size_t)D*D, nullptr, nullptr, kh, kl);
    hgemm_k<16><<<gg, 256, HG_SMEM>>>(yh, yl, wh + 2*(size_t)D*D, wl + 2*(size_t)D*D, nullptr, nullptr, vth, vtl);

    dim3 ga(8, 64);
    attn_mma<<<ga, 256, ATTN_SMEM>>>(qh, ql, kh, kl, vth, vtl, xm, ym, ath, atl);

    hgemm_k<0><<<gg, 256, HG_SMEM>>>(ath, atl, wh + 3*(size_t)D*D, wl + 3*(size_t)D*D, nullptr, t1, nullptr, nullptr);
    add_ln_k<<<ROWS, 128>>>(x, t1, g1, be1, xm, 2 | 4, t2, t2h, t2l);
    hgemm_k<11><<<gg, 256, HG_SMEM>>>(t2h, t2l, wh + 4*(size_t)D*D, wl + 4*(size_t)D*D, b1, nullptr, rh, rl);
    hgemm_k<1><<<gg, 256, HG_SMEM>>>(rh, rl, wh + 5*(size_t)D*D, wl + 5*(size_t)D*D, b2, ff, nullptr, nullptr);
    add_ln_k<<<ROWS, 128>>>(t2, ff, g2, be2, xm, 1, out, nullptr, nullptr);
}